// round 7
// baseline (speedup 1.0000x reference)
#include <cuda_runtime.h>
#include <cuda_bf16.h>
#include <cstdint>

// Problem dims (fixed by the reference)
constexpr int B_  = 32;
constexpr int D_  = 256;   // idf
constexpr int Q_  = 1024;  // ih*iw
constexpr int C_  = 512;   // cdf
constexpr int L_  = 128;
constexpr int N_  = 10;    // contexts
constexpr int K2_ = N_ * L_;  // 1280

// Scratch (static device globals — no allocation in kernel_launch)
__device__ float g_tgt[(size_t)B_ * Q_ * D_];          //  [b][q][d] fp32
__device__ float g_src[(size_t)N_ * B_ * L_ * D_];     //  [n][b][l][d] fp32
__device__ float g_w  [(size_t)B_ * Q_ * N_ * L_];     //  [b][q][n][l] fp32
__device__ float g_s2 [(size_t)B_ * D_ * N_ * L_];     //  [b][e][n][l] fp32
// bf16 split copies for tensor-core path
__device__ __align__(16) __nv_bfloat16 g_tgtH[(size_t)B_ * Q_ * D_];
__device__ __align__(16) __nv_bfloat16 g_tgtL[(size_t)B_ * Q_ * D_];
__device__ __align__(16) __nv_bfloat16 g_srcH[(size_t)N_ * B_ * L_ * D_];
__device__ __align__(16) __nv_bfloat16 g_srcL[(size_t)N_ * B_ * L_ * D_];

typedef unsigned long long u64;

// ---- packed f32x2 helpers ----
__device__ __forceinline__ u64 packbc(float x) {
    u64 r; asm("mov.b64 %0, {%1, %1};" : "=l"(r) : "f"(x)); return r;
}
__device__ __forceinline__ void ffma2(u64& d, u64 a, u64 b) {
    asm("fma.rn.f32x2 %0, %1, %2, %0;" : "+l"(d) : "l"(a), "l"(b));
}
__device__ __forceinline__ float2 unpk(u64 v) {
    float lo, hi; asm("mov.b64 {%0, %1}, %2;" : "=f"(lo), "=f"(hi) : "l"(v));
    return make_float2(lo, hi);
}
__device__ __forceinline__ void fma8x8p(u64 (&acc)[8][4], float4 a0, float4 a1,
                                        const u64 (&bv)[4]) {
    float av[8] = {a0.x, a0.y, a0.z, a0.w, a1.x, a1.y, a1.z, a1.w};
    #pragma unroll
    for (int i = 0; i < 8; i++) {
        u64 ap = packbc(av[i]);
        #pragma unroll
        for (int j = 0; j < 4; j++) ffma2(acc[i][j], ap, bv[j]);
    }
}
__device__ __forceinline__ float warpSum32(float v) {
    #pragma unroll
    for (int o = 16; o; o >>= 1) v += __shfl_xor_sync(0xffffffffu, v, o);
    return v;
}

// ---- bf16 split helpers ----
__device__ __forceinline__ void split1(float x, __nv_bfloat16& h, __nv_bfloat16& l) {
    h = __float2bfloat16(x);
    l = __float2bfloat16(x - __bfloat162float(h));
}
__device__ __forceinline__ void split4(const float* v, u64& h4, u64& l4) {
    unsigned short hs[4], ls[4];
    #pragma unroll
    for (int i = 0; i < 4; i++) {
        __nv_bfloat16 h, l; split1(v[i], h, l);
        hs[i] = __bfloat16_as_ushort(h); ls[i] = __bfloat16_as_ushort(l);
    }
    h4 = (u64)hs[0] | ((u64)hs[1] << 16) | ((u64)hs[2] << 32) | ((u64)hs[3] << 48);
    l4 = (u64)ls[0] | ((u64)ls[1] << 16) | ((u64)ls[2] << 32) | ((u64)ls[3] << 48);
}

// ---- warp-level tensor core helpers (sm_80 baseline; no 'a' features) ----
__device__ __forceinline__ uint32_t smem_u32(const void* p) {
    uint32_t a;
    asm("{ .reg .u64 t; cvta.to.shared.u64 t, %1; cvt.u32.u64 %0, t; }" : "=r"(a) : "l"(p));
    return a;
}
__device__ __forceinline__ void ldsm_x4(uint32_t& r0, uint32_t& r1, uint32_t& r2,
                                        uint32_t& r3, uint32_t a) {
    asm volatile("ldmatrix.sync.aligned.m8n8.x4.shared.b16 {%0,%1,%2,%3}, [%4];"
                 : "=r"(r0), "=r"(r1), "=r"(r2), "=r"(r3) : "r"(a));
}
__device__ __forceinline__ void mma_bf16(float* d, const uint32_t* a, const uint32_t* b) {
    asm volatile("mma.sync.aligned.m16n8k16.row.col.f32.bf16.bf16.f32 "
        "{%0,%1,%2,%3}, {%4,%5,%6,%7}, {%8,%9}, {%0,%1,%2,%3};"
        : "+f"(d[0]), "+f"(d[1]), "+f"(d[2]), "+f"(d[3])
        : "r"(a[0]), "r"(a[1]), "r"(a[2]), "r"(a[3]), "r"(b[0]), "r"(b[1]));
}

// ---------------------------------------------------------------------------
// K1: transpose input [B][D][Q] -> g_tgt fp32 + g_tgtH/L bf16 split, [B][Q][D]
// ---------------------------------------------------------------------------
__global__ void __launch_bounds__(256) k_transpose(const float* __restrict__ in) {
    __shared__ float tile[32][33];
    const int b  = blockIdx.z;
    const int q0 = blockIdx.x * 32;
    const int d0 = blockIdx.y * 32;
    const int tx = threadIdx.x, ty = threadIdx.y;  // 32 x 8
    #pragma unroll
    for (int j = 0; j < 4; j++)
        tile[ty + j * 8][tx] = in[((size_t)b * D_ + d0 + ty + j * 8) * Q_ + q0 + tx];
    __syncthreads();
    #pragma unroll
    for (int j = 0; j < 4; j++) {
        float x = tile[tx][ty + j * 8];
        size_t idx = ((size_t)b * Q_ + q0 + ty + j * 8) * D_ + d0 + tx;
        g_tgt[idx] = x;
        __nv_bfloat16 h, l; split1(x, h, l);
        g_tgtH[idx] = h; g_tgtL[idx] = l;
    }
}

// ---------------------------------------------------------------------------
// K2: per (n,b): src[l,d] = sum_c ctx[c,l] * Wc[d,c]   (fp32 + bf16 split out)
// ---------------------------------------------------------------------------
__global__ void __launch_bounds__(256, 2) k_source(const float* __restrict__ ctx,
                                                   const float* __restrict__ Wc) {
    const int nb = blockIdx.y;
    const int d0 = blockIdx.x * 128;
    const float* ctxp = ctx + (size_t)nb * C_ * L_;  // [C][L]
    __shared__ __align__(16) float a_s[32][132];   // [c][l]
    __shared__ __align__(16) float b_s[32][132];   // [c][d]
    const int t  = threadIdx.x;
    const int ty = t >> 4, tx = t & 15;
    u64 acc[8][4] = {};
    for (int kc = 0; kc < C_; kc += 32) {
        __syncthreads();
        #pragma unroll
        for (int i = 0; i < 4; i++) {
            int idx = t + i * 256;
            int c = idx >> 5, l4 = idx & 31;
            *(float4*)&a_s[c][l4 * 4] = *(const float4*)&ctxp[(size_t)(kc + c) * L_ + l4 * 4];
        }
        #pragma unroll
        for (int i = 0; i < 4; i++) {
            int idx = t + i * 256;
            int d = idx >> 3, c4 = (idx & 7) * 4;
            float4 v = *(const float4*)&Wc[(size_t)(d0 + d) * C_ + kc + c4];
            b_s[c4 + 0][d] = v.x; b_s[c4 + 1][d] = v.y;
            b_s[c4 + 2][d] = v.z; b_s[c4 + 3][d] = v.w;
        }
        __syncthreads();
        #pragma unroll
        for (int c = 0; c < 32; c++) {
            float4 a0 = *(const float4*)&a_s[c][ty * 4];
            float4 a1 = *(const float4*)&a_s[c][ty * 4 + 64];
            const u64* p0 = (const u64*)&b_s[c][tx * 4];
            const u64* p1 = (const u64*)&b_s[c][tx * 4 + 64];
            u64 bv[4] = {p0[0], p0[1], p1[0], p1[1]};
            fma8x8p(acc, a0, a1, bv);
        }
    }
    float* outp = g_src + (size_t)nb * L_ * D_;
    __nv_bfloat16* oH = g_srcH + (size_t)nb * L_ * D_;
    __nv_bfloat16* oL = g_srcL + (size_t)nb * L_ * D_;
    #pragma unroll
    for (int h = 0; h < 2; h++)
        #pragma unroll
        for (int i = 0; i < 4; i++) {
            int l = h * 64 + ty * 4 + i;
            u64* a = acc[h * 4 + i];
            float2 r0 = unpk(a[0]), r1 = unpk(a[1]);
            float2 r2 = unpk(a[2]), r3 = unpk(a[3]);
            float v0[4] = {r0.x, r0.y, r1.x, r1.y};
            float v1[4] = {r2.x, r2.y, r3.x, r3.y};
            *(float4*)&outp[(size_t)l * D_ + d0 + tx * 4]      = make_float4(v0[0], v0[1], v0[2], v0[3]);
            *(float4*)&outp[(size_t)l * D_ + d0 + 64 + tx * 4] = make_float4(v1[0], v1[1], v1[2], v1[3]);
            u64 h4, l4;
            split4(v0, h4, l4);
            *(u64*)&oH[(size_t)l * D_ + d0 + tx * 4] = h4;
            *(u64*)&oL[(size_t)l * D_ + d0 + tx * 4] = l4;
            split4(v1, h4, l4);
            *(u64*)&oH[(size_t)l * D_ + d0 + 64 + tx * 4] = h4;
            *(u64*)&oL[(size_t)l * D_ + d0 + 64 + tx * 4] = l4;
        }
}

// ---------------------------------------------------------------------------
// K3 (mma.sync): per (n,b,q0): logits[128q,128l] = tgt·src^T via bf16 3-term
// split (fp32 accumulate in registers), softmax in smem, write fp32 w.
// 8 warps: 4 along q (32 rows each), 2 along l (64 cols each).
// smem tiles: 4 planes (Ah, Al, Bh, Bl), 128 rows x 80B (64B data + 16B pad).
// logits union: 128 x 129 floats (66048 B dynamic smem).
// ---------------------------------------------------------------------------
constexpr int ROWB    = 80;      // smem tile row stride (bytes)
constexpr int PLANE   = 128 * ROWB;  // 10240
constexpr int LSTRIDE = 129;     // logits row stride (floats)
constexpr int ATTN_SMEM = 128 * LSTRIDE * 4;  // 66048

__global__ void __launch_bounds__(256) k_attn_mma() {
    extern __shared__ __align__(16) char smem[];
    float* logits = (float*)smem;
    const uint32_t sb = smem_u32(smem);
    const int t = threadIdx.x;
    const int lane = t & 31, wid = t >> 5;
    const int qw = (wid & 3) * 32;   // warp q offset in tile
    const int lw = (wid >> 2) * 64;  // warp l offset in tile
    const int nb = blockIdx.y;
    const int n = nb >> 5, b = nb & 31;
    const int q0 = blockIdx.x * 128;

    const __nv_bfloat16* aH = g_tgtH + ((size_t)b * Q_ + q0) * D_;
    const __nv_bfloat16* aL = g_tgtL + ((size_t)b * Q_ + q0) * D_;
    const __nv_bfloat16* bH = g_srcH + (size_t)nb * L_ * D_;
    const __nv_bfloat16* bL = g_srcL + (size_t)nb * L_ * D_;

    float acc[2][8][4] = {};   // [m16 block][n8 block][frag]

    for (int c = 0; c < 8; c++) {
        const int kd = c * 32;
        __syncthreads();
        // copy chunk: 4 planes x 128 rows x 64B = 2048 uint4, 8 per thread
        #pragma unroll
        for (int i = 0; i < 8; i++) {
            int idx = t + i * 256;
            int pl = idx >> 9;           // 0=Ah 1=Al 2=Bh 3=Bl
            int p2 = idx & 511;
            int row = p2 >> 2, c4 = p2 & 3;
            const __nv_bfloat16* sp =
                (pl == 0) ? aH : (pl == 1) ? aL : (pl == 2) ? bH : bL;
            uint4 v = *reinterpret_cast<const uint4*>(sp + (size_t)row * D_ + kd + c4 * 8);
            *reinterpret_cast<uint4*>(smem + pl * PLANE + row * ROWB + c4 * 16) = v;
        }
        __syncthreads();
        #pragma unroll
        for (int kh = 0; kh < 2; kh++) {
            uint32_t ah[2][4], al[2][4];
            #pragma unroll
            for (int m = 0; m < 2; m++) {
                uint32_t addr = sb + (qw + m * 16 + (lane & 15)) * ROWB
                              + (lane >> 4) * 16 + kh * 32;
                ldsm_x4(ah[m][0], ah[m][1], ah[m][2], ah[m][3], addr);
                ldsm_x4(al[m][0], al[m][1], al[m][2], al[m][3], addr + PLANE);
            }
            uint32_t bhf[8][2], blf[8][2];
            {
                int nrow = (lane & 7) + ((lane >> 4) << 3);
                int koff = ((lane >> 3) & 1) * 16;
                #pragma unroll
                for (int j = 0; j < 4; j++) {
                    uint32_t addr = sb + 2 * PLANE + (lw + j * 16 + nrow) * ROWB
                                  + kh * 32 + koff;
                    uint32_t r0, r1, r2, r3;
                    ldsm_x4(r0, r1, r2, r3, addr);
                    bhf[2 * j][0] = r0; bhf[2 * j][1] = r1;
                    bhf[2 * j + 1][0] = r2; bhf[2 * j + 1][1] = r3;
                    ldsm_x4(r0, r1, r2, r3, addr + PLANE);
                    blf[2 * j][0] = r0; blf[2 * j][1] = r1;
                    blf[2 * j + 1][0] = r2; blf[2 * j + 1][1] = r3;
                }
            }
            #pragma unroll
            for (int m = 0; m < 2; m++)
                #pragma unroll
                for (int j = 0; j < 8; j++) {
                    mma_bf16(acc[m][j], ah[m], bhf[j]);   // hi*hi
                    mma_bf16(acc[m][j], ah[m], blf[j]);   // hi*lo
                    mma_bf16(acc[m][j], al[m], bhf[j]);   // lo*hi
                }
        }
    }
    __syncthreads();   // all ldmatrix done before logits overwrite tiles
    #pragma unroll
    for (int m = 0; m < 2; m++)
        #pragma unroll
        for (int j = 0; j < 8; j++) {
            int qr  = qw + m * 16 + (lane >> 2);
            int col = lw + j * 8 + (lane & 3) * 2;
            logits[qr * LSTRIDE + col]           = acc[m][j][0];
            logits[qr * LSTRIDE + col + 1]       = acc[m][j][1];
            logits[(qr + 8) * LSTRIDE + col]     = acc[m][j][2];
            logits[(qr + 8) * LSTRIDE + col + 1] = acc[m][j][3];
        }
    __syncthreads();
    if (t < 128) {
        float* row = logits + t * LSTRIDE;
        float m = row[0];
        #pragma unroll 8
        for (int j = 1; j < 128; j++) m = fmaxf(m, row[j]);
        float s = 0.f;
        #pragma unroll 8
        for (int j = 0; j < 128; j++) {
            float ev = __expf(row[j] - m);
            row[j] = ev;
            s += ev;
        }
        float inv = 1.0f / s;
        float* wrow = g_w + (((size_t)b * Q_ + q0 + t) * N_ + n) * L_;
        #pragma unroll
        for (int j = 0; j < 128; j += 4) {
            float4 o = make_float4(row[j] * inv, row[j + 1] * inv,
                                   row[j + 2] * inv, row[j + 3] * inv);
            *(float4*)&wrow[j] = o;
        }
    }
}

// ---------------------------------------------------------------------------
// K4: per (n,b): S2[e,l] = sum_d Wcat[e, n*D+d] * src[l,d] -> g_s2[b][e][n][l]
// ---------------------------------------------------------------------------
__global__ void __launch_bounds__(256, 2) k_s2(const float* __restrict__ Wcat) {
    const int nb = blockIdx.y;
    const int n = nb >> 5, b = nb & 31;
    const int e0 = blockIdx.x * 128;
    const float* src = g_src + (size_t)nb * L_ * D_;
    __shared__ __align__(16) float a_s[32][132];   // [d][e]
    __shared__ __align__(16) float b_s[32][132];   // [d][l]
    const int t  = threadIdx.x;
    const int ty = t >> 4, tx = t & 15;
    u64 acc[8][4] = {};
    for (int kd = 0; kd < D_; kd += 32) {
        __syncthreads();
        #pragma unroll
        for (int i = 0; i < 4; i++) {
            int idx = t + i * 256;
            int e = idx >> 3, d4 = (idx & 7) * 4;
            float4 v = *(const float4*)&Wcat[(size_t)(e0 + e) * (N_ * D_) + n * D_ + kd + d4];
            a_s[d4 + 0][e] = v.x; a_s[d4 + 1][e] = v.y;
            a_s[d4 + 2][e] = v.z; a_s[d4 + 3][e] = v.w;
        }
        #pragma unroll
        for (int i = 0; i < 4; i++) {
            int idx = t + i * 256;
            int l = idx >> 3, d4 = (idx & 7) * 4;
            float4 v = *(const float4*)&src[(size_t)l * D_ + kd + d4];
            b_s[d4 + 0][l] = v.x; b_s[d4 + 1][l] = v.y;
            b_s[d4 + 2][l] = v.z; b_s[d4 + 3][l] = v.w;
        }
        __syncthreads();
        #pragma unroll
        for (int d = 0; d < 32; d++) {
            float4 a0 = *(const float4*)&a_s[d][ty * 4];
            float4 a1 = *(const float4*)&a_s[d][ty * 4 + 64];
            const u64* p0 = (const u64*)&b_s[d][tx * 4];
            const u64* p1 = (const u64*)&b_s[d][tx * 4 + 64];
            u64 bv[4] = {p0[0], p0[1], p1[0], p1[1]};
            fma8x8p(acc, a0, a1, bv);
        }
    }
    #pragma unroll
    for (int h = 0; h < 2; h++)
        #pragma unroll
        for (int i = 0; i < 4; i++) {
            int e = e0 + h * 64 + ty * 4 + i;
            float* srow = g_s2 + (((size_t)b * D_ + e) * N_ + n) * L_;
            u64* a = acc[h * 4 + i];
            float2 r0 = unpk(a[0]), r1 = unpk(a[1]), r2 = unpk(a[2]), r3 = unpk(a[3]);
            *(float4*)&srow[tx * 4]      = make_float4(r0.x, r0.y, r1.x, r1.y);
            *(float4*)&srow[64 + tx * 4] = make_float4(r2.x, r2.y, r3.x, r3.y);
        }
}

// ---------------------------------------------------------------------------
// K5: per b: x[q,e] = sum_k w[b,q,k] * s2[b,e,k]  (K = 1280)
//     epilogue: + Wb, relu, + tgt, LayerNorm(eps=0) * gamma + beta -> out
// ---------------------------------------------------------------------------
__global__ void __launch_bounds__(256, 2) k_out(const float* __restrict__ Wb,
                                                const float* __restrict__ gamma,
                                                const float* __restrict__ beta,
                                                float* __restrict__ out) {
    const int b  = blockIdx.y;
    const int q0 = blockIdx.x * 64;
    const float* wp = g_w  + (size_t)b * Q_ * K2_;
    const float* sp = g_s2 + (size_t)b * D_ * K2_;
    __shared__ __align__(16) float a_s[16][68];    // [k][q]  (64 q)
    __shared__ __align__(16) float b_s[16][260];   // [k][e]  (256 e)
    const int t  = threadIdx.x;
    const int ty = t >> 5, tx = t & 31;
    u64 acc[8][4] = {};
    for (int k0 = 0; k0 < K2_; k0 += 16) {
        __syncthreads();
        {
            int q = t >> 2, k4 = (t & 3) * 4;
            float4 v = *(const float4*)&wp[(size_t)(q0 + q) * K2_ + k0 + k4];
            a_s[k4 + 0][q] = v.x; a_s[k4 + 1][q] = v.y;
            a_s[k4 + 2][q] = v.z; a_s[k4 + 3][q] = v.w;
        }
        #pragma unroll
        for (int i = 0; i < 4; i++) {
            int idx = t + i * 256;
            int e = idx >> 2, k4 = (idx & 3) * 4;
            float4 v = *(const float4*)&sp[(size_t)e * K2_ + k0 + k4];
            b_s[k4 + 0][e] = v.x; b_s[k4 + 1][e] = v.y;
            b_s[k4 + 2][e] = v.z; b_s[k4 + 3][e] = v.w;
        }
        __syncthreads();
        #pragma unroll
        for (int k = 0; k < 16; k++) {
            float4 a0 = *(const float4*)&a_s[k][ty * 8];
            float4 a1 = *(const float4*)&a_s[k][ty * 8 + 4];
            const u64* p0 = (const u64*)&b_s[k][tx * 4];
            const u64* p1 = (const u64*)&b_s[k][tx * 4 + 128];
            u64 bv[4] = {p0[0], p0[1], p1[0], p1[1]};
            fma8x8p(acc, a0, a1, bv);
        }
    }
    float wb[8], gm[8], be[8];
    {
        float4 w0 = *(const float4*)&Wb[tx * 4];
        float4 w1 = *(const float4*)&Wb[tx * 4 + 128];
        float4 g0 = *(const float4*)&gamma[tx * 4];
        float4 g1 = *(const float4*)&gamma[tx * 4 + 128];
        float4 e0 = *(const float4*)&beta[tx * 4];
        float4 e1 = *(const float4*)&beta[tx * 4 + 128];
        wb[0]=w0.x; wb[1]=w0.y; wb[2]=w0.z; wb[3]=w0.w; wb[4]=w1.x; wb[5]=w1.y; wb[6]=w1.z; wb[7]=w1.w;
        gm[0]=g0.x; gm[1]=g0.y; gm[2]=g0.z; gm[3]=g0.w; gm[4]=g1.x; gm[5]=g1.y; gm[6]=g1.z; gm[7]=g1.w;
        be[0]=e0.x; be[1]=e0.y; be[2]=e0.z; be[3]=e0.w; be[4]=e1.x; be[5]=e1.y; be[6]=e1.z; be[7]=e1.w;
    }
    const float* tgt = g_tgt + (size_t)b * Q_ * D_;
    #pragma unroll
    for (int i = 0; i < 8; i++) {
        const int q = q0 + ty * 8 + i;
        u64* a = acc[i];
        float2 r0 = unpk(a[0]), r1 = unpk(a[1]), r2 = unpk(a[2]), r3 = unpk(a[3]);
        float av[8] = {r0.x, r0.y, r1.x, r1.y, r2.x, r2.y, r3.x, r3.y};
        float4 t0 = *(const float4*)&tgt[(size_t)q * D_ + tx * 4];
        float4 t1 = *(const float4*)&tgt[(size_t)q * D_ + tx * 4 + 128];
        float tv[8] = {t0.x, t0.y, t0.z, t0.w, t1.x, t1.y, t1.z, t1.w};
        float v[8], s = 0.f;
        #pragma unroll
        for (int j = 0; j < 8; j++) {
            v[j] = fmaxf(av[j] + wb[j], 0.f) + tv[j];
            s += v[j];
        }
        s = warpSum32(s);
        const float mu = s * (1.0f / 256.0f);
        float d2 = 0.f;
        #pragma unroll
        for (int j = 0; j < 8; j++) { float dd = v[j] - mu; d2 += dd * dd; }
        d2 = warpSum32(d2);
        const float rs = rsqrtf(d2 * (1.0f / 256.0f));
        float o[8];
        #pragma unroll
        for (int j = 0; j < 8; j++) o[j] = (v[j] - mu) * rs * gm[j] + be[j];
        float* orow = out + (size_t)(b * Q_ + q) * D_;
        *(float4*)&orow[tx * 4]       = make_float4(o[0], o[1], o[2], o[3]);
        *(float4*)&orow[tx * 4 + 128] = make_float4(o[4], o[5], o[6], o[7]);
    }
}

// ---------------------------------------------------------------------------
extern "C" void kernel_launch(void* const* d_in, const int* in_sizes, int n_in,
                              void* d_out, int out_size) {
    const float* input    = (const float*)d_in[0];  // [B, D, 32, 32]
    const float* contexts = (const float*)d_in[1];  // [N, B, C, L]
    const float* Wc       = (const float*)d_in[2];  // [D, C]
    const float* Wcat     = (const float*)d_in[3];  // [D, N*D]
    const float* Wb       = (const float*)d_in[4];  // [D]
    const float* gamma    = (const float*)d_in[5];  // [D]
    const float* beta     = (const float*)d_in[6];  // [D]
    float* out = (float*)d_out;                     // [B, Q, D]

    cudaFuncSetAttribute(k_attn_mma, cudaFuncAttributeMaxDynamicSharedMemorySize,
                         ATTN_SMEM);

    k_transpose<<<dim3(Q_ / 32, D_ / 32, B_), dim3(32, 8)>>>(input);
    k_source   <<<dim3(2,        N_ * B_),    256>>>(contexts, Wc);
    k_attn_mma <<<dim3(Q_ / 128, N_ * B_),    256, ATTN_SMEM>>>();
    k_s2       <<<dim3(2,        N_ * B_),    256>>>(Wcat);
    k_out      <<<dim3(Q_ / 64,  B_),         256>>>(Wb, gamma, beta, out);
}

// round 8
// speedup vs baseline: 1.7664x; 1.7664x over previous
#include <cuda_runtime.h>
#include <cuda_bf16.h>
#include <cstdint>

// Problem dims (fixed by the reference)
constexpr int B_  = 32;
constexpr int D_  = 256;   // idf
constexpr int Q_  = 1024;  // ih*iw
constexpr int C_  = 512;   // cdf
constexpr int L_  = 128;
constexpr int N_  = 10;    // contexts
constexpr int K2_ = N_ * L_;  // 1280

// Scratch (static device globals — no allocation in kernel_launch)
__device__ float g_tgt[(size_t)B_ * Q_ * D_];          //  [b][q][d] fp32
__device__ float g_src[(size_t)N_ * B_ * L_ * D_];     //  [n][b][l][d] fp32
__device__ float g_w  [(size_t)B_ * Q_ * N_ * L_];     //  [b][q][n][l] fp32
__device__ float g_s2 [(size_t)B_ * D_ * N_ * L_];     //  [b][e][n][l] fp32
// bf16 split copies for tensor-core path
__device__ __align__(16) __nv_bfloat16 g_tgtH[(size_t)B_ * Q_ * D_];
__device__ __align__(16) __nv_bfloat16 g_tgtL[(size_t)B_ * Q_ * D_];
__device__ __align__(16) __nv_bfloat16 g_srcH[(size_t)N_ * B_ * L_ * D_];
__device__ __align__(16) __nv_bfloat16 g_srcL[(size_t)N_ * B_ * L_ * D_];

typedef unsigned long long u64;

// ---- packed f32x2 helpers ----
__device__ __forceinline__ u64 packbc(float x) {
    u64 r; asm("mov.b64 %0, {%1, %1};" : "=l"(r) : "f"(x)); return r;
}
__device__ __forceinline__ void ffma2(u64& d, u64 a, u64 b) {
    asm("fma.rn.f32x2 %0, %1, %2, %0;" : "+l"(d) : "l"(a), "l"(b));
}
__device__ __forceinline__ float2 unpk(u64 v) {
    float lo, hi; asm("mov.b64 {%0, %1}, %2;" : "=f"(lo), "=f"(hi) : "l"(v));
    return make_float2(lo, hi);
}
__device__ __forceinline__ void fma8x8p(u64 (&acc)[8][4], float4 a0, float4 a1,
                                        const u64 (&bv)[4]) {
    float av[8] = {a0.x, a0.y, a0.z, a0.w, a1.x, a1.y, a1.z, a1.w};
    #pragma unroll
    for (int i = 0; i < 8; i++) {
        u64 ap = packbc(av[i]);
        #pragma unroll
        for (int j = 0; j < 4; j++) ffma2(acc[i][j], ap, bv[j]);
    }
}
__device__ __forceinline__ float warpSum32(float v) {
    #pragma unroll
    for (int o = 16; o; o >>= 1) v += __shfl_xor_sync(0xffffffffu, v, o);
    return v;
}

// ---- bf16 split helpers ----
__device__ __forceinline__ void split1(float x, __nv_bfloat16& h, __nv_bfloat16& l) {
    h = __float2bfloat16(x);
    l = __float2bfloat16(x - __bfloat162float(h));
}
__device__ __forceinline__ void split4(const float* v, u64& h4, u64& l4) {
    unsigned short hs[4], ls[4];
    #pragma unroll
    for (int i = 0; i < 4; i++) {
        __nv_bfloat16 h, l; split1(v[i], h, l);
        hs[i] = __bfloat16_as_ushort(h); ls[i] = __bfloat16_as_ushort(l);
    }
    h4 = (u64)hs[0] | ((u64)hs[1] << 16) | ((u64)hs[2] << 32) | ((u64)hs[3] << 48);
    l4 = (u64)ls[0] | ((u64)ls[1] << 16) | ((u64)ls[2] << 32) | ((u64)ls[3] << 48);
}

// ---- warp-level tensor core helpers (sm_80 baseline; no 'a' features) ----
__device__ __forceinline__ uint32_t smem_u32(const void* p) {
    uint32_t a;
    asm("{ .reg .u64 t; cvta.to.shared.u64 t, %1; cvt.u32.u64 %0, t; }" : "=r"(a) : "l"(p));
    return a;
}
__device__ __forceinline__ void ldsm_x4(uint32_t& r0, uint32_t& r1, uint32_t& r2,
                                        uint32_t& r3, uint32_t a) {
    asm volatile("ldmatrix.sync.aligned.m8n8.x4.shared.b16 {%0,%1,%2,%3}, [%4];"
                 : "=r"(r0), "=r"(r1), "=r"(r2), "=r"(r3) : "r"(a));
}
__device__ __forceinline__ void mma_bf16(float* d, const uint32_t* a, const uint32_t* b) {
    asm volatile("mma.sync.aligned.m16n8k16.row.col.f32.bf16.bf16.f32 "
        "{%0,%1,%2,%3}, {%4,%5,%6,%7}, {%8,%9}, {%0,%1,%2,%3};"
        : "+f"(d[0]), "+f"(d[1]), "+f"(d[2]), "+f"(d[3])
        : "r"(a[0]), "r"(a[1]), "r"(a[2]), "r"(a[3]), "r"(b[0]), "r"(b[1]));
}
__device__ __forceinline__ void cp16(uint32_t saddr, const void* gaddr) {
    asm volatile("cp.async.cg.shared.global [%0], [%1], 16;"
                 :: "r"(saddr), "l"(gaddr) : "memory");
}
#define CP_COMMIT() asm volatile("cp.async.commit_group;" ::: "memory")
#define CP_WAIT(n)  asm volatile("cp.async.wait_group %0;" :: "n"(n) : "memory")

// ---------------------------------------------------------------------------
// K1: transpose input [B][D][Q] -> g_tgt fp32 + g_tgtH/L bf16 split, [B][Q][D]
// ---------------------------------------------------------------------------
__global__ void __launch_bounds__(256) k_transpose(const float* __restrict__ in) {
    __shared__ float tile[32][33];
    const int b  = blockIdx.z;
    const int q0 = blockIdx.x * 32;
    const int d0 = blockIdx.y * 32;
    const int tx = threadIdx.x, ty = threadIdx.y;  // 32 x 8
    #pragma unroll
    for (int j = 0; j < 4; j++)
        tile[ty + j * 8][tx] = in[((size_t)b * D_ + d0 + ty + j * 8) * Q_ + q0 + tx];
    __syncthreads();
    #pragma unroll
    for (int j = 0; j < 4; j++) {
        float x = tile[tx][ty + j * 8];
        size_t idx = ((size_t)b * Q_ + q0 + ty + j * 8) * D_ + d0 + tx;
        g_tgt[idx] = x;
        __nv_bfloat16 h, l; split1(x, h, l);
        g_tgtH[idx] = h; g_tgtL[idx] = l;
    }
}

// ---------------------------------------------------------------------------
// K2: per (n,b): src[l,d] = sum_c ctx[c,l] * Wc[d,c]   (fp32 + bf16 split out)
// ---------------------------------------------------------------------------
__global__ void __launch_bounds__(256, 2) k_source(const float* __restrict__ ctx,
                                                   const float* __restrict__ Wc) {
    const int nb = blockIdx.y;
    const int d0 = blockIdx.x * 128;
    const float* ctxp = ctx + (size_t)nb * C_ * L_;  // [C][L]
    __shared__ __align__(16) float a_s[32][132];   // [c][l]
    __shared__ __align__(16) float b_s[32][132];   // [c][d]
    const int t  = threadIdx.x;
    const int ty = t >> 4, tx = t & 15;
    u64 acc[8][4] = {};
    for (int kc = 0; kc < C_; kc += 32) {
        __syncthreads();
        #pragma unroll
        for (int i = 0; i < 4; i++) {
            int idx = t + i * 256;
            int c = idx >> 5, l4 = idx & 31;
            *(float4*)&a_s[c][l4 * 4] = *(const float4*)&ctxp[(size_t)(kc + c) * L_ + l4 * 4];
        }
        #pragma unroll
        for (int i = 0; i < 4; i++) {
            int idx = t + i * 256;
            int d = idx >> 3, c4 = (idx & 7) * 4;
            float4 v = *(const float4*)&Wc[(size_t)(d0 + d) * C_ + kc + c4];
            b_s[c4 + 0][d] = v.x; b_s[c4 + 1][d] = v.y;
            b_s[c4 + 2][d] = v.z; b_s[c4 + 3][d] = v.w;
        }
        __syncthreads();
        #pragma unroll
        for (int c = 0; c < 32; c++) {
            float4 a0 = *(const float4*)&a_s[c][ty * 4];
            float4 a1 = *(const float4*)&a_s[c][ty * 4 + 64];
            const u64* p0 = (const u64*)&b_s[c][tx * 4];
            const u64* p1 = (const u64*)&b_s[c][tx * 4 + 64];
            u64 bv[4] = {p0[0], p0[1], p1[0], p1[1]};
            fma8x8p(acc, a0, a1, bv);
        }
    }
    float* outp = g_src + (size_t)nb * L_ * D_;
    __nv_bfloat16* oH = g_srcH + (size_t)nb * L_ * D_;
    __nv_bfloat16* oL = g_srcL + (size_t)nb * L_ * D_;
    #pragma unroll
    for (int h = 0; h < 2; h++)
        #pragma unroll
        for (int i = 0; i < 4; i++) {
            int l = h * 64 + ty * 4 + i;
            u64* a = acc[h * 4 + i];
            float2 r0 = unpk(a[0]), r1 = unpk(a[1]);
            float2 r2 = unpk(a[2]), r3 = unpk(a[3]);
            float v0[4] = {r0.x, r0.y, r1.x, r1.y};
            float v1[4] = {r2.x, r2.y, r3.x, r3.y};
            *(float4*)&outp[(size_t)l * D_ + d0 + tx * 4]      = make_float4(v0[0], v0[1], v0[2], v0[3]);
            *(float4*)&outp[(size_t)l * D_ + d0 + 64 + tx * 4] = make_float4(v1[0], v1[1], v1[2], v1[3]);
            u64 h4, l4;
            split4(v0, h4, l4);
            *(u64*)&oH[(size_t)l * D_ + d0 + tx * 4] = h4;
            *(u64*)&oL[(size_t)l * D_ + d0 + tx * 4] = l4;
            split4(v1, h4, l4);
            *(u64*)&oH[(size_t)l * D_ + d0 + 64 + tx * 4] = h4;
            *(u64*)&oL[(size_t)l * D_ + d0 + 64 + tx * 4] = l4;
        }
}

// ---------------------------------------------------------------------------
// K3 (mma.sync, low-pressure + cp.async double buffer):
// logits[128q,128l] = tgt·src^T via bf16 3-term split, softmax, fp32 w out.
// 8 warps: 4 along q (32 rows), 2 along l (64 cols).
// Tiles: 2 buffers x 4 planes (Ah, Al, Bh, Bl) x 128 rows x 80B.
// ---------------------------------------------------------------------------
constexpr int ROWB    = 80;
constexpr int PLANE   = 128 * ROWB;      // 10240
constexpr int BUFSZ   = 4 * PLANE;       // 40960
constexpr int LSTRIDE = 129;
constexpr int ATTN_SMEM = 2 * BUFSZ;     // 81920 (logits 66048 reuses buffer 0)
constexpr int NCH = 8;                   // K chunks of 32

__global__ void __launch_bounds__(256, 2) k_attn_mma() {
    extern __shared__ __align__(16) char smem[];
    float* logits = (float*)smem;
    const uint32_t sb = smem_u32(smem);
    const int t = threadIdx.x;
    const int lane = t & 31, wid = t >> 5;
    const int qw = (wid & 3) * 32;   // warp q offset
    const int lw = (wid >> 2) * 64;  // warp l offset
    const int nb = blockIdx.y;
    const int n = nb >> 5, b = nb & 31;
    const int q0 = blockIdx.x * 128;

    const __nv_bfloat16* aH = g_tgtH + ((size_t)b * Q_ + q0) * D_;
    const __nv_bfloat16* aL = g_tgtL + ((size_t)b * Q_ + q0) * D_;
    const __nv_bfloat16* bH = g_srcH + (size_t)nb * L_ * D_;
    const __nv_bfloat16* bL = g_srcL + (size_t)nb * L_ * D_;

    // per-thread cp.async mapping (constant across chunks, recomputed cheaply)
    auto prefetch = [&](int c, int buf) {
        const int kd = c * 32;
        const uint32_t sbase = sb + buf * BUFSZ;
        #pragma unroll
        for (int i = 0; i < 8; i++) {
            int idx = t + i * 256;
            int pl = idx >> 9;
            int p2 = idx & 511;
            int row = p2 >> 2, c4 = p2 & 3;
            const __nv_bfloat16* sp =
                (pl == 0) ? aH : (pl == 1) ? aL : (pl == 2) ? bH : bL;
            cp16(sbase + pl * PLANE + row * ROWB + c4 * 16,
                 sp + (size_t)row * D_ + kd + c4 * 8);
        }
        CP_COMMIT();
    };

    float acc[2][8][4] = {};   // [m16 block][n8 block][frag]

    prefetch(0, 0);
    for (int c = 0; c < NCH; c++) {
        const int buf = c & 1;
        __syncthreads();                 // prior compute on buf^1 done
        if (c + 1 < NCH) { prefetch(c + 1, buf ^ 1); CP_WAIT(1); }
        else             { CP_WAIT(0); }
        __syncthreads();                 // buf data visible to all
        const uint32_t sbase = sb + buf * BUFSZ;
        #pragma unroll
        for (int kh = 0; kh < 2; kh++) {
            uint32_t ah[2][4], al[2][4];
            #pragma unroll
            for (int m = 0; m < 2; m++) {
                uint32_t addr = sbase + (qw + m * 16 + (lane & 15)) * ROWB
                              + (lane >> 4) * 16 + kh * 32;
                ldsm_x4(ah[m][0], ah[m][1], ah[m][2], ah[m][3], addr);
                ldsm_x4(al[m][0], al[m][1], al[m][2], al[m][3], addr + PLANE);
            }
            const int nrow = (lane & 7) + ((lane >> 4) << 3);
            const int koff = ((lane >> 3) & 1) * 16;
            #pragma unroll
            for (int jj = 0; jj < 4; jj++) {   // B loaded just-in-time: 8 live regs
                uint32_t addr = sbase + 2 * PLANE + (lw + jj * 16 + nrow) * ROWB
                              + kh * 32 + koff;
                uint32_t bh[4], bl[4];
                ldsm_x4(bh[0], bh[1], bh[2], bh[3], addr);
                ldsm_x4(bl[0], bl[1], bl[2], bl[3], addr + PLANE);
                #pragma unroll
                for (int m = 0; m < 2; m++)
                    #pragma unroll
                    for (int jb = 0; jb < 2; jb++) {
                        float* d = acc[m][jj * 2 + jb];
                        mma_bf16(d, ah[m], bh + jb * 2);   // hi*hi
                        mma_bf16(d, ah[m], bl + jb * 2);   // hi*lo
                        mma_bf16(d, al[m], bh + jb * 2);   // lo*hi
                    }
            }
        }
    }
    __syncthreads();   // all ldmatrix done before logits overwrite tiles
    #pragma unroll
    for (int m = 0; m < 2; m++)
        #pragma unroll
        for (int j = 0; j < 8; j++) {
            int qr  = qw + m * 16 + (lane >> 2);
            int col = lw + j * 8 + (lane & 3) * 2;
            logits[qr * LSTRIDE + col]           = acc[m][j][0];
            logits[qr * LSTRIDE + col + 1]       = acc[m][j][1];
            logits[(qr + 8) * LSTRIDE + col]     = acc[m][j][2];
            logits[(qr + 8) * LSTRIDE + col + 1] = acc[m][j][3];
        }
    __syncthreads();
    if (t < 128) {
        float* row = logits + t * LSTRIDE;
        float m = row[0];
        #pragma unroll 8
        for (int j = 1; j < 128; j++) m = fmaxf(m, row[j]);
        float s = 0.f;
        #pragma unroll 8
        for (int j = 0; j < 128; j++) {
            float ev = __expf(row[j] - m);
            row[j] = ev;
            s += ev;
        }
        float inv = 1.0f / s;
        float* wrow = g_w + (((size_t)b * Q_ + q0 + t) * N_ + n) * L_;
        #pragma unroll
        for (int j = 0; j < 128; j += 4)
            *(float4*)&wrow[j] = make_float4(row[j] * inv, row[j + 1] * inv,
                                             row[j + 2] * inv, row[j + 3] * inv);
    }
}

// ---------------------------------------------------------------------------
// K4: per (n,b): S2[e,l] = sum_d Wcat[e, n*D+d] * src[l,d] -> g_s2[b][e][n][l]
// ---------------------------------------------------------------------------
__global__ void __launch_bounds__(256, 2) k_s2(const float* __restrict__ Wcat) {
    const int nb = blockIdx.y;
    const int n = nb >> 5, b = nb & 31;
    const int e0 = blockIdx.x * 128;
    const float* src = g_src + (size_t)nb * L_ * D_;
    __shared__ __align__(16) float a_s[32][132];   // [d][e]
    __shared__ __align__(16) float b_s[32][132];   // [d][l]
    const int t  = threadIdx.x;
    const int ty = t >> 4, tx = t & 15;
    u64 acc[8][4] = {};
    for (int kd = 0; kd < D_; kd += 32) {
        __syncthreads();
        #pragma unroll
        for (int i = 0; i < 4; i++) {
            int idx = t + i * 256;
            int e = idx >> 3, d4 = (idx & 7) * 4;
            float4 v = *(const float4*)&Wcat[(size_t)(e0 + e) * (N_ * D_) + n * D_ + kd + d4];
            a_s[d4 + 0][e] = v.x; a_s[d4 + 1][e] = v.y;
            a_s[d4 + 2][e] = v.z; a_s[d4 + 3][e] = v.w;
        }
        #pragma unroll
        for (int i = 0; i < 4; i++) {
            int idx = t + i * 256;
            int l = idx >> 3, d4 = (idx & 7) * 4;
            float4 v = *(const float4*)&src[(size_t)l * D_ + kd + d4];
            b_s[d4 + 0][l] = v.x; b_s[d4 + 1][l] = v.y;
            b_s[d4 + 2][l] = v.z; b_s[d4 + 3][l] = v.w;
        }
        __syncthreads();
        #pragma unroll
        for (int d = 0; d < 32; d++) {
            float4 a0 = *(const float4*)&a_s[d][ty * 4];
            float4 a1 = *(const float4*)&a_s[d][ty * 4 + 64];
            const u64* p0 = (const u64*)&b_s[d][tx * 4];
            const u64* p1 = (const u64*)&b_s[d][tx * 4 + 64];
            u64 bv[4] = {p0[0], p0[1], p1[0], p1[1]};
            fma8x8p(acc, a0, a1, bv);
        }
    }
    #pragma unroll
    for (int h = 0; h < 2; h++)
        #pragma unroll
        for (int i = 0; i < 4; i++) {
            int e = e0 + h * 64 + ty * 4 + i;
            float* srow = g_s2 + (((size_t)b * D_ + e) * N_ + n) * L_;
            u64* a = acc[h * 4 + i];
            float2 r0 = unpk(a[0]), r1 = unpk(a[1]), r2 = unpk(a[2]), r3 = unpk(a[3]);
            *(float4*)&srow[tx * 4]      = make_float4(r0.x, r0.y, r1.x, r1.y);
            *(float4*)&srow[64 + tx * 4] = make_float4(r2.x, r2.y, r3.x, r3.y);
        }
}

// ---------------------------------------------------------------------------
// K5: per b: x[q,e] = sum_k w[b,q,k] * s2[b,e,k]  (K = 1280)
//     epilogue: + Wb, relu, + tgt, LayerNorm(eps=0) * gamma + beta -> out
// ---------------------------------------------------------------------------
__global__ void __launch_bounds__(256, 2) k_out(const float* __restrict__ Wb,
                                                const float* __restrict__ gamma,
                                                const float* __restrict__ beta,
                                                float* __restrict__ out) {
    const int b  = blockIdx.y;
    const int q0 = blockIdx.x * 64;
    const float* wp = g_w  + (size_t)b * Q_ * K2_;
    const float* sp = g_s2 + (size_t)b * D_ * K2_;
    __shared__ __align__(16) float a_s[16][68];    // [k][q]  (64 q)
    __shared__ __align__(16) float b_s[16][260];   // [k][e]  (256 e)
    const int t  = threadIdx.x;
    const int ty = t >> 5, tx = t & 31;
    u64 acc[8][4] = {};
    for (int k0 = 0; k0 < K2_; k0 += 16) {
        __syncthreads();
        {
            int q = t >> 2, k4 = (t & 3) * 4;
            float4 v = *(const float4*)&wp[(size_t)(q0 + q) * K2_ + k0 + k4];
            a_s[k4 + 0][q] = v.x; a_s[k4 + 1][q] = v.y;
            a_s[k4 + 2][q] = v.z; a_s[k4 + 3][q] = v.w;
        }
        #pragma unroll
        for (int i = 0; i < 4; i++) {
            int idx = t + i * 256;
            int e = idx >> 2, k4 = (idx & 3) * 4;
            float4 v = *(const float4*)&sp[(size_t)e * K2_ + k0 + k4];
            b_s[k4 + 0][e] = v.x; b_s[k4 + 1][e] = v.y;
            b_s[k4 + 2][e] = v.z; b_s[k4 + 3][e] = v.w;
        }
        __syncthreads();
        #pragma unroll
        for (int k = 0; k < 16; k++) {
            float4 a0 = *(const float4*)&a_s[k][ty * 8];
            float4 a1 = *(const float4*)&a_s[k][ty * 8 + 4];
            const u64* p0 = (const u64*)&b_s[k][tx * 4];
            const u64* p1 = (const u64*)&b_s[k][tx * 4 + 128];
            u64 bv[4] = {p0[0], p0[1], p1[0], p1[1]};
            fma8x8p(acc, a0, a1, bv);
        }
    }
    float wb[8], gm[8], be[8];
    {
        float4 w0 = *(const float4*)&Wb[tx * 4];
        float4 w1 = *(const float4*)&Wb[tx * 4 + 128];
        float4 g0 = *(const float4*)&gamma[tx * 4];
        float4 g1 = *(const float4*)&gamma[tx * 4 + 128];
        float4 e0 = *(const float4*)&beta[tx * 4];
        float4 e1 = *(const float4*)&beta[tx * 4 + 128];
        wb[0]=w0.x; wb[1]=w0.y; wb[2]=w0.z; wb[3]=w0.w; wb[4]=w1.x; wb[5]=w1.y; wb[6]=w1.z; wb[7]=w1.w;
        gm[0]=g0.x; gm[1]=g0.y; gm[2]=g0.z; gm[3]=g0.w; gm[4]=g1.x; gm[5]=g1.y; gm[6]=g1.z; gm[7]=g1.w;
        be[0]=e0.x; be[1]=e0.y; be[2]=e0.z; be[3]=e0.w; be[4]=e1.x; be[5]=e1.y; be[6]=e1.z; be[7]=e1.w;
    }
    const float* tgt = g_tgt + (size_t)b * Q_ * D_;
    #pragma unroll
    for (int i = 0; i < 8; i++) {
        const int q = q0 + ty * 8 + i;
        u64* a = acc[i];
        float2 r0 = unpk(a[0]), r1 = unpk(a[1]), r2 = unpk(a[2]), r3 = unpk(a[3]);
        float av[8] = {r0.x, r0.y, r1.x, r1.y, r2.x, r2.y, r3.x, r3.y};
        float4 t0 = *(const float4*)&tgt[(size_t)q * D_ + tx * 4];
        float4 t1 = *(const float4*)&tgt[(size_t)q * D_ + tx * 4 + 128];
        float tv[8] = {t0.x, t0.y, t0.z, t0.w, t1.x, t1.y, t1.z, t1.w};
        float v[8], s = 0.f;
        #pragma unroll
        for (int j = 0; j < 8; j++) {
            v[j] = fmaxf(av[j] + wb[j], 0.f) + tv[j];
            s += v[j];
        }
        s = warpSum32(s);
        const float mu = s * (1.0f / 256.0f);
        float d2 = 0.f;
        #pragma unroll
        for (int j = 0; j < 8; j++) { float dd = v[j] - mu; d2 += dd * dd; }
        d2 = warpSum32(d2);
        const float rs = rsqrtf(d2 * (1.0f / 256.0f));
        float o[8];
        #pragma unroll
        for (int j = 0; j < 8; j++) o[j] = (v[j] - mu) * rs * gm[j] + be[j];
        float* orow = out + (size_t)(b * Q_ + q) * D_;
        *(float4*)&orow[tx * 4]       = make_float4(o[0], o[1], o[2], o[3]);
        *(float4*)&orow[tx * 4 + 128] = make_float4(o[4], o[5], o[6], o[7]);
    }
}

// ---------------------------------------------------------------------------
extern "C" void kernel_launch(void* const* d_in, const int* in_sizes, int n_in,
                              void* d_out, int out_size) {
    const float* input    = (const float*)d_in[0];  // [B, D, 32, 32]
    const float* contexts = (const float*)d_in[1];  // [N, B, C, L]
    const float* Wc       = (const float*)d_in[2];  // [D, C]
    const float* Wcat     = (const float*)d_in[3];  // [D, N*D]
    const float* Wb       = (const float*)d_in[4];  // [D]
    const float* gamma    = (const float*)d_in[5];  // [D]
    const float* beta     = (const float*)d_in[6];  // [D]
    float* out = (float*)d_out;                     // [B, Q, D]

    cudaFuncSetAttribute(k_attn_mma, cudaFuncAttributeMaxDynamicSharedMemorySize,
                         ATTN_SMEM);

    k_transpose<<<dim3(Q_ / 32, D_ / 32, B_), dim3(32, 8)>>>(input);
    k_source   <<<dim3(2,        N_ * B_),    256>>>(contexts, Wc);
    k_attn_mma <<<dim3(Q_ / 128, N_ * B_),    256, ATTN_SMEM>>>();
    k_s2       <<<dim3(2,        N_ * B_),    256>>>(Wcat);
    k_out      <<<dim3(Q_ / 64,  B_),         256>>>(Wb, gamma, beta, out);
}

// round 9
// speedup vs baseline: 2.5410x; 1.4385x over previous
#include <cuda_runtime.h>
#include <cuda_bf16.h>
#include <cstdint>

// Problem dims (fixed by the reference)
constexpr int B_  = 32;
constexpr int D_  = 256;   // idf
constexpr int Q_  = 1024;  // ih*iw
constexpr int C_  = 512;   // cdf
constexpr int L_  = 128;
constexpr int N_  = 10;    // contexts
constexpr int K2_ = N_ * L_;  // 1280
constexpr int ND_ = N_ * D_;  // 2560

// Scratch (static device globals — no allocation in kernel_launch)
__device__ float g_tgt[(size_t)B_ * Q_ * D_];          //  [b][q][d] fp32 (residual)
// bf16 split pairs (tensor-core operands)
__device__ __align__(16) __nv_bfloat16 g_tgtH[(size_t)B_ * Q_ * D_];
__device__ __align__(16) __nv_bfloat16 g_tgtL[(size_t)B_ * Q_ * D_];
__device__ __align__(16) __nv_bfloat16 g_srcH[(size_t)N_ * B_ * L_ * D_];
__device__ __align__(16) __nv_bfloat16 g_srcL[(size_t)N_ * B_ * L_ * D_];
__device__ __align__(16) __nv_bfloat16 g_wH [(size_t)B_ * Q_ * N_ * L_];
__device__ __align__(16) __nv_bfloat16 g_wL [(size_t)B_ * Q_ * N_ * L_];
__device__ __align__(16) __nv_bfloat16 g_s2H[(size_t)B_ * D_ * N_ * L_];
__device__ __align__(16) __nv_bfloat16 g_s2L[(size_t)B_ * D_ * N_ * L_];
__device__ __align__(16) __nv_bfloat16 g_WcatH[(size_t)D_ * ND_];
__device__ __align__(16) __nv_bfloat16 g_WcatL[(size_t)D_ * ND_];

typedef unsigned long long u64;

// ---- packed f32x2 helpers (scalar path for k_source) ----
__device__ __forceinline__ u64 packbc(float x) {
    u64 r; asm("mov.b64 %0, {%1, %1};" : "=l"(r) : "f"(x)); return r;
}
__device__ __forceinline__ void ffma2(u64& d, u64 a, u64 b) {
    asm("fma.rn.f32x2 %0, %1, %2, %0;" : "+l"(d) : "l"(a), "l"(b));
}
__device__ __forceinline__ float2 unpk(u64 v) {
    float lo, hi; asm("mov.b64 {%0, %1}, %2;" : "=f"(lo), "=f"(hi) : "l"(v));
    return make_float2(lo, hi);
}
__device__ __forceinline__ void fma8x8p(u64 (&acc)[8][4], float4 a0, float4 a1,
                                        const u64 (&bv)[4]) {
    float av[8] = {a0.x, a0.y, a0.z, a0.w, a1.x, a1.y, a1.z, a1.w};
    #pragma unroll
    for (int i = 0; i < 8; i++) {
        u64 ap = packbc(av[i]);
        #pragma unroll
        for (int j = 0; j < 4; j++) ffma2(acc[i][j], ap, bv[j]);
    }
}
__device__ __forceinline__ float warpSum32(float v) {
    #pragma unroll
    for (int o = 16; o; o >>= 1) v += __shfl_xor_sync(0xffffffffu, v, o);
    return v;
}

// ---- bf16 split helpers ----
__device__ __forceinline__ void split1(float x, __nv_bfloat16& h, __nv_bfloat16& l) {
    h = __float2bfloat16(x);
    l = __float2bfloat16(x - __bfloat162float(h));
}
__device__ __forceinline__ void split4(const float* v, u64& h4, u64& l4) {
    unsigned short hs[4], ls[4];
    #pragma unroll
    for (int i = 0; i < 4; i++) {
        __nv_bfloat16 h, l; split1(v[i], h, l);
        hs[i] = __bfloat16_as_ushort(h); ls[i] = __bfloat16_as_ushort(l);
    }
    h4 = (u64)hs[0] | ((u64)hs[1] << 16) | ((u64)hs[2] << 32) | ((u64)hs[3] << 48);
    l4 = (u64)ls[0] | ((u64)ls[1] << 16) | ((u64)ls[2] << 32) | ((u64)ls[3] << 48);
}
// store two consecutive values as packed bf16 hi/lo pairs (4B each array)
__device__ __forceinline__ void st_pair(__nv_bfloat16* H, __nv_bfloat16* L,
                                        size_t off, float x0, float x1) {
    __nv_bfloat16 h0, l0, h1, l1;
    split1(x0, h0, l0); split1(x1, h1, l1);
    uint32_t hu = (uint32_t)__bfloat16_as_ushort(h0) |
                  ((uint32_t)__bfloat16_as_ushort(h1) << 16);
    uint32_t lu = (uint32_t)__bfloat16_as_ushort(l0) |
                  ((uint32_t)__bfloat16_as_ushort(l1) << 16);
    *(uint32_t*)&H[off] = hu;
    *(uint32_t*)&L[off] = lu;
}

// ---- warp-level tensor core helpers (sm_80 baseline; no 'a' features) ----
__device__ __forceinline__ uint32_t smem_u32(const void* p) {
    uint32_t a;
    asm("{ .reg .u64 t; cvta.to.shared.u64 t, %1; cvt.u32.u64 %0, t; }" : "=r"(a) : "l"(p));
    return a;
}
__device__ __forceinline__ void ldsm_x4(uint32_t& r0, uint32_t& r1, uint32_t& r2,
                                        uint32_t& r3, uint32_t a) {
    asm volatile("ldmatrix.sync.aligned.m8n8.x4.shared.b16 {%0,%1,%2,%3}, [%4];"
                 : "=r"(r0), "=r"(r1), "=r"(r2), "=r"(r3) : "r"(a));
}
__device__ __forceinline__ void mma_bf16(float* d, const uint32_t* a, const uint32_t* b) {
    asm volatile("mma.sync.aligned.m16n8k16.row.col.f32.bf16.bf16.f32 "
        "{%0,%1,%2,%3}, {%4,%5,%6,%7}, {%8,%9}, {%0,%1,%2,%3};"
        : "+f"(d[0]), "+f"(d[1]), "+f"(d[2]), "+f"(d[3])
        : "r"(a[0]), "r"(a[1]), "r"(a[2]), "r"(a[3]), "r"(b[0]), "r"(b[1]));
}
__device__ __forceinline__ void cp16(uint32_t saddr, const void* gaddr) {
    asm volatile("cp.async.cg.shared.global [%0], [%1], 16;"
                 :: "r"(saddr), "l"(gaddr) : "memory");
}
#define CP_COMMIT() asm volatile("cp.async.commit_group;" ::: "memory")
#define CP_WAIT(n)  asm volatile("cp.async.wait_group %0;" :: "n"(n) : "memory")

// ---------------------------------------------------------------------------
// K1: transpose input [B][D][Q] -> g_tgt fp32 + g_tgtH/L bf16 split, [B][Q][D]
// ---------------------------------------------------------------------------
__global__ void __launch_bounds__(256) k_transpose(const float* __restrict__ in) {
    __shared__ float tile[32][33];
    const int b  = blockIdx.z;
    const int q0 = blockIdx.x * 32;
    const int d0 = blockIdx.y * 32;
    const int tx = threadIdx.x, ty = threadIdx.y;  // 32 x 8
    #pragma unroll
    for (int j = 0; j < 4; j++)
        tile[ty + j * 8][tx] = in[((size_t)b * D_ + d0 + ty + j * 8) * Q_ + q0 + tx];
    __syncthreads();
    #pragma unroll
    for (int j = 0; j < 4; j++) {
        float x = tile[tx][ty + j * 8];
        size_t idx = ((size_t)b * Q_ + q0 + ty + j * 8) * D_ + d0 + tx;
        g_tgt[idx] = x;
        __nv_bfloat16 h, l; split1(x, h, l);
        g_tgtH[idx] = h; g_tgtL[idx] = l;
    }
}

// ---------------------------------------------------------------------------
// K1b: split Wcat fp32 -> bf16 hi/lo (tiny one-shot)
// ---------------------------------------------------------------------------
__global__ void __launch_bounds__(256) k_splitW(const float* __restrict__ Wcat) {
    int idx = blockIdx.x * 1024 + threadIdx.x * 4;
    #pragma unroll
    for (int i = 0; i < 4; i++) {
        float x = Wcat[idx + i];
        __nv_bfloat16 h, l; split1(x, h, l);
        g_WcatH[idx + i] = h; g_WcatL[idx + i] = l;
    }
}

// ---------------------------------------------------------------------------
// K2 (scalar fp32): per (n,b): src[l,d] = sum_c ctx[c,l] * Wc[d,c]
// emits bf16 hi/lo only.
// ---------------------------------------------------------------------------
__global__ void __launch_bounds__(256, 2) k_source(const float* __restrict__ ctx,
                                                   const float* __restrict__ Wc) {
    const int nb = blockIdx.y;
    const int d0 = blockIdx.x * 128;
    const float* ctxp = ctx + (size_t)nb * C_ * L_;  // [C][L]
    __shared__ __align__(16) float a_s[32][132];   // [c][l]
    __shared__ __align__(16) float b_s[32][132];   // [c][d]
    const int t  = threadIdx.x;
    const int ty = t >> 4, tx = t & 15;
    u64 acc[8][4] = {};
    for (int kc = 0; kc < C_; kc += 32) {
        __syncthreads();
        #pragma unroll
        for (int i = 0; i < 4; i++) {
            int idx = t + i * 256;
            int c = idx >> 5, l4 = idx & 31;
            *(float4*)&a_s[c][l4 * 4] = *(const float4*)&ctxp[(size_t)(kc + c) * L_ + l4 * 4];
        }
        #pragma unroll
        for (int i = 0; i < 4; i++) {
            int idx = t + i * 256;
            int d = idx >> 3, c4 = (idx & 7) * 4;
            float4 v = *(const float4*)&Wc[(size_t)(d0 + d) * C_ + kc + c4];
            b_s[c4 + 0][d] = v.x; b_s[c4 + 1][d] = v.y;
            b_s[c4 + 2][d] = v.z; b_s[c4 + 3][d] = v.w;
        }
        __syncthreads();
        #pragma unroll
        for (int c = 0; c < 32; c++) {
            float4 a0 = *(const float4*)&a_s[c][ty * 4];
            float4 a1 = *(const float4*)&a_s[c][ty * 4 + 64];
            const u64* p0 = (const u64*)&b_s[c][tx * 4];
            const u64* p1 = (const u64*)&b_s[c][tx * 4 + 64];
            u64 bv[4] = {p0[0], p0[1], p1[0], p1[1]};
            fma8x8p(acc, a0, a1, bv);
        }
    }
    __nv_bfloat16* oH = g_srcH + (size_t)nb * L_ * D_;
    __nv_bfloat16* oL = g_srcL + (size_t)nb * L_ * D_;
    #pragma unroll
    for (int h = 0; h < 2; h++)
        #pragma unroll
        for (int i = 0; i < 4; i++) {
            int l = h * 64 + ty * 4 + i;
            u64* a = acc[h * 4 + i];
            float2 r0 = unpk(a[0]), r1 = unpk(a[1]);
            float2 r2 = unpk(a[2]), r3 = unpk(a[3]);
            float v0[4] = {r0.x, r0.y, r1.x, r1.y};
            float v1[4] = {r2.x, r2.y, r3.x, r3.y};
            u64 h4, l4;
            split4(v0, h4, l4);
            *(u64*)&oH[(size_t)l * D_ + d0 + tx * 4] = h4;
            *(u64*)&oL[(size_t)l * D_ + d0 + tx * 4] = l4;
            split4(v1, h4, l4);
            *(u64*)&oH[(size_t)l * D_ + d0 + 64 + tx * 4] = h4;
            *(u64*)&oL[(size_t)l * D_ + d0 + 64 + tx * 4] = l4;
        }
}

// ---------------------------------------------------------------------------
// Shared tile constants for the 128x128 mma kernels (attn, s2)
// ---------------------------------------------------------------------------
constexpr int ROWB    = 80;
constexpr int PLANE   = 128 * ROWB;      // 10240
constexpr int BUFSZ   = 4 * PLANE;       // 40960
constexpr int LSTRIDE = 129;
constexpr int MMA_SMEM = 2 * BUFSZ;      // 81920 (attn logits 66048 reuses it)
constexpr int NCH = 8;                   // K=256 in chunks of 32

// ---------------------------------------------------------------------------
// K3 (mma.sync): logits[128q,128l] = tgt·src^T (3-term bf16 split), softmax,
// write w as bf16 hi/lo. 8 warps: 4 along q, 2 along l.
// ---------------------------------------------------------------------------
__global__ void __launch_bounds__(256, 2) k_attn_mma() {
    extern __shared__ __align__(16) char smem[];
    float* logits = (float*)smem;
    const uint32_t sb = smem_u32(smem);
    const int t = threadIdx.x;
    const int lane = t & 31, wid = t >> 5;
    const int qw = (wid & 3) * 32;
    const int lw = (wid >> 2) * 64;
    const int nb = blockIdx.y;
    const int n = nb >> 5, b = nb & 31;
    const int q0 = blockIdx.x * 128;

    const __nv_bfloat16* aH = g_tgtH + ((size_t)b * Q_ + q0) * D_;
    const __nv_bfloat16* aL = g_tgtL + ((size_t)b * Q_ + q0) * D_;
    const __nv_bfloat16* bH = g_srcH + (size_t)nb * L_ * D_;
    const __nv_bfloat16* bL = g_srcL + (size_t)nb * L_ * D_;

    auto prefetch = [&](int c, int buf) {
        const int kd = c * 32;
        const uint32_t sbase = sb + buf * BUFSZ;
        #pragma unroll
        for (int i = 0; i < 8; i++) {
            int idx = t + i * 256;
            int pl = idx >> 9;
            int p2 = idx & 511;
            int row = p2 >> 2, c4 = p2 & 3;
            const __nv_bfloat16* sp =
                (pl == 0) ? aH : (pl == 1) ? aL : (pl == 2) ? bH : bL;
            cp16(sbase + pl * PLANE + row * ROWB + c4 * 16,
                 sp + (size_t)row * D_ + kd + c4 * 8);
        }
        CP_COMMIT();
    };

    float acc[2][8][4] = {};

    prefetch(0, 0);
    for (int c = 0; c < NCH; c++) {
        const int buf = c & 1;
        __syncthreads();
        if (c + 1 < NCH) { prefetch(c + 1, buf ^ 1); CP_WAIT(1); }
        else             { CP_WAIT(0); }
        __syncthreads();
        const uint32_t sbase = sb + buf * BUFSZ;
        #pragma unroll
        for (int kh = 0; kh < 2; kh++) {
            uint32_t ah[2][4], al[2][4];
            #pragma unroll
            for (int m = 0; m < 2; m++) {
                uint32_t addr = sbase + (qw + m * 16 + (lane & 15)) * ROWB
                              + (lane >> 4) * 16 + kh * 32;
                ldsm_x4(ah[m][0], ah[m][1], ah[m][2], ah[m][3], addr);
                ldsm_x4(al[m][0], al[m][1], al[m][2], al[m][3], addr + PLANE);
            }
            const int nrow = (lane & 7) + ((lane >> 4) << 3);
            const int koff = ((lane >> 3) & 1) * 16;
            #pragma unroll
            for (int jj = 0; jj < 4; jj++) {
                uint32_t addr = sbase + 2 * PLANE + (lw + jj * 16 + nrow) * ROWB
                              + kh * 32 + koff;
                uint32_t bh[4], bl[4];
                ldsm_x4(bh[0], bh[1], bh[2], bh[3], addr);
                ldsm_x4(bl[0], bl[1], bl[2], bl[3], addr + PLANE);
                #pragma unroll
                for (int m = 0; m < 2; m++)
                    #pragma unroll
                    for (int jb = 0; jb < 2; jb++) {
                        float* d = acc[m][jj * 2 + jb];
                        mma_bf16(d, ah[m], bh + jb * 2);
                        mma_bf16(d, ah[m], bl + jb * 2);
                        mma_bf16(d, al[m], bh + jb * 2);
                    }
            }
        }
    }
    __syncthreads();
    #pragma unroll
    for (int m = 0; m < 2; m++)
        #pragma unroll
        for (int j = 0; j < 8; j++) {
            int qr  = qw + m * 16 + (lane >> 2);
            int col = lw + j * 8 + (lane & 3) * 2;
            logits[qr * LSTRIDE + col]           = acc[m][j][0];
            logits[qr * LSTRIDE + col + 1]       = acc[m][j][1];
            logits[(qr + 8) * LSTRIDE + col]     = acc[m][j][2];
            logits[(qr + 8) * LSTRIDE + col + 1] = acc[m][j][3];
        }
    __syncthreads();
    if (t < 128) {
        float* row = logits + t * LSTRIDE;
        float m = row[0];
        #pragma unroll 8
        for (int j = 1; j < 128; j++) m = fmaxf(m, row[j]);
        float s = 0.f;
        #pragma unroll 8
        for (int j = 0; j < 128; j++) {
            float ev = __expf(row[j] - m);
            row[j] = ev;
            s += ev;
        }
        float inv = 1.0f / s;
        size_t base = (((size_t)b * Q_ + q0 + t) * N_ + n) * L_;
        #pragma unroll
        for (int j = 0; j < 128; j += 2)
            st_pair(g_wH, g_wL, base + j, row[j] * inv, row[j + 1] * inv);
    }
}

// ---------------------------------------------------------------------------
// K4 (mma.sync): S2[e,l] = sum_d Wcat[e, n*D+d] * src[l,d] -> bf16 hi/lo
// tile 128e x 128l, K=256; identical machinery to k_attn_mma, no softmax.
// ---------------------------------------------------------------------------
__global__ void __launch_bounds__(256, 2) k_s2_mma() {
    extern __shared__ __align__(16) char smem[];
    const uint32_t sb = smem_u32(smem);
    const int t = threadIdx.x;
    const int lane = t & 31, wid = t >> 5;
    const int qw = (wid & 3) * 32;   // e dir
    const int lw = (wid >> 2) * 64;  // l dir
    const int nb = blockIdx.y;
    const int n = nb >> 5, b = nb & 31;
    const int e0 = blockIdx.x * 128;

    const __nv_bfloat16* aH = g_WcatH + (size_t)e0 * ND_ + n * D_;
    const __nv_bfloat16* aL = g_WcatL + (size_t)e0 * ND_ + n * D_;
    const __nv_bfloat16* bH = g_srcH + (size_t)nb * L_ * D_;
    const __nv_bfloat16* bL = g_srcL + (size_t)nb * L_ * D_;

    auto prefetch = [&](int c, int buf) {
        const int kd = c * 32;
        const uint32_t sbase = sb + buf * BUFSZ;
        #pragma unroll
        for (int i = 0; i < 8; i++) {
            int idx = t + i * 256;
            int pl = idx >> 9;
            int p2 = idx & 511;
            int row = p2 >> 2, c4 = p2 & 3;
            const __nv_bfloat16* sp;
            size_t stride;
            if (pl < 2) { sp = pl ? aL : aH; stride = ND_; }
            else        { sp = (pl == 3) ? bL : bH; stride = D_; }
            cp16(sbase + pl * PLANE + row * ROWB + c4 * 16,
                 sp + (size_t)row * stride + kd + c4 * 8);
        }
        CP_COMMIT();
    };

    float acc[2][8][4] = {};

    prefetch(0, 0);
    for (int c = 0; c < NCH; c++) {
        const int buf = c & 1;
        __syncthreads();
        if (c + 1 < NCH) { prefetch(c + 1, buf ^ 1); CP_WAIT(1); }
        else             { CP_WAIT(0); }
        __syncthreads();
        const uint32_t sbase = sb + buf * BUFSZ;
        #pragma unroll
        for (int kh = 0; kh < 2; kh++) {
            uint32_t ah[2][4], al[2][4];
            #pragma unroll
            for (int m = 0; m < 2; m++) {
                uint32_t addr = sbase + (qw + m * 16 + (lane & 15)) * ROWB
                              + (lane >> 4) * 16 + kh * 32;
                ldsm_x4(ah[m][0], ah[m][1], ah[m][2], ah[m][3], addr);
                ldsm_x4(al[m][0], al[m][1], al[m][2], al[m][3], addr + PLANE);
            }
            const int nrow = (lane & 7) + ((lane >> 4) << 3);
            const int koff = ((lane >> 3) & 1) * 16;
            #pragma unroll
            for (int jj = 0; jj < 4; jj++) {
                uint32_t addr = sbase + 2 * PLANE + (lw + jj * 16 + nrow) * ROWB
                              + kh * 32 + koff;
                uint32_t bh[4], bl[4];
                ldsm_x4(bh[0], bh[1], bh[2], bh[3], addr);
                ldsm_x4(bl[0], bl[1], bl[2], bl[3], addr + PLANE);
                #pragma unroll
                for (int m = 0; m < 2; m++)
                    #pragma unroll
                    for (int jb = 0; jb < 2; jb++) {
                        float* d = acc[m][jj * 2 + jb];
                        mma_bf16(d, ah[m], bh + jb * 2);
                        mma_bf16(d, ah[m], bl + jb * 2);
                        mma_bf16(d, al[m], bh + jb * 2);
                    }
            }
        }
    }
    // direct bf16-pair stores (no inter-thread reduction needed)
    #pragma unroll
    for (int m = 0; m < 2; m++)
        #pragma unroll
        for (int j = 0; j < 8; j++) {
            int er  = e0 + qw + m * 16 + (lane >> 2);
            int col = lw + j * 8 + (lane & 3) * 2;
            float* d = acc[m][j];
            size_t off0 = (((size_t)b * D_ + er) * N_ + n) * L_ + col;
            size_t off1 = (((size_t)b * D_ + er + 8) * N_ + n) * L_ + col;
            st_pair(g_s2H, g_s2L, off0, d[0], d[1]);
            st_pair(g_s2H, g_s2L, off1, d[2], d[3]);
        }
}

// ---------------------------------------------------------------------------
// K5 (mma.sync): x[q,e] = sum_k w[q,k]*s2[e,k], K=1280, tile 64q x 256e.
// 8 warps: 2 along q (32 rows), 4 along e (64 cols).
// Epilogue: stage x to smem, then bias+relu+residual+LayerNorm -> out.
// ---------------------------------------------------------------------------
constexpr int O_ROWB = 80;
constexpr int O_APL  = 64 * O_ROWB;    // 5120
constexpr int O_BPL  = 256 * O_ROWB;   // 20480
constexpr int O_BUF  = 2 * O_APL + 2 * O_BPL;  // 51200
constexpr int O_SMEM = 2 * O_BUF;      // 102400 (x-staging 66560 reuses it)
constexpr int O_NCH  = K2_ / 32;       // 40
constexpr int XS     = 260;            // x staging row stride (floats)

__global__ void __launch_bounds__(256, 2) k_out_mma(const float* __restrict__ Wb,
                                                    const float* __restrict__ gamma,
                                                    const float* __restrict__ beta,
                                                    float* __restrict__ out) {
    extern __shared__ __align__(16) char smem[];
    const uint32_t sb = smem_u32(smem);
    const int t = threadIdx.x;
    const int lane = t & 31, wid = t >> 5;
    const int qw = (wid & 1) * 32;   // q dir
    const int ew = (wid >> 1) * 64;  // e dir
    const int b  = blockIdx.y;
    const int q0 = blockIdx.x * 64;

    const __nv_bfloat16* wHp = g_wH + ((size_t)b * Q_ + q0) * K2_;
    const __nv_bfloat16* wLp = g_wL + ((size_t)b * Q_ + q0) * K2_;
    const __nv_bfloat16* sHp = g_s2H + (size_t)b * D_ * K2_;
    const __nv_bfloat16* sLp = g_s2L + (size_t)b * D_ * K2_;

    auto prefetch = [&](int c, int buf) {
        const int k0 = c * 32;
        const uint32_t sbase = sb + buf * O_BUF;
        #pragma unroll
        for (int i = 0; i < 10; i++) {
            int idx = t + i * 256;
            if (idx < 512) {       // A planes: 64 rows x 4 c4 x 2
                int pl = idx >> 8, p = idx & 255, row = p >> 2, c4 = p & 3;
                const __nv_bfloat16* sp = pl ? wLp : wHp;
                cp16(sbase + pl * O_APL + row * O_ROWB + c4 * 16,
                     sp + (size_t)row * K2_ + k0 + c4 * 8);
            } else {               // B planes: 256 rows x 4 c4 x 2
                int idx2 = idx - 512;
                int pl = idx2 >> 10, p = idx2 & 1023, row = p >> 2, c4 = p & 3;
                const __nv_bfloat16* sp = pl ? sLp : sHp;
                cp16(sbase + 2 * O_APL + pl * O_BPL + row * O_ROWB + c4 * 16,
                     sp + (size_t)row * K2_ + k0 + c4 * 8);
            }
        }
        CP_COMMIT();
    };

    float acc[2][8][4] = {};

    prefetch(0, 0);
    for (int c = 0; c < O_NCH; c++) {
        const int buf = c & 1;
        __syncthreads();
        if (c + 1 < O_NCH) { prefetch(c + 1, buf ^ 1); CP_WAIT(1); }
        else               { CP_WAIT(0); }
        __syncthreads();
        const uint32_t sbase = sb + buf * O_BUF;
        #pragma unroll
        for (int kh = 0; kh < 2; kh++) {
            uint32_t ah[2][4], al[2][4];
            #pragma unroll
            for (int m = 0; m < 2; m++) {
                uint32_t addr = sbase + (qw + m * 16 + (lane & 15)) * O_ROWB
                              + (lane >> 4) * 16 + kh * 32;
                ldsm_x4(ah[m][0], ah[m][1], ah[m][2], ah[m][3], addr);
                ldsm_x4(al[m][0], al[m][1], al[m][2], al[m][3], addr + O_APL);
            }
            const int nrow = (lane & 7) + ((lane >> 4) << 3);
            const int koff = ((lane >> 3) & 1) * 16;
            #pragma unroll
            for (int jj = 0; jj < 4; jj++) {
                uint32_t addr = sbase + 2 * O_APL + (ew + jj * 16 + nrow) * O_ROWB
                              + kh * 32 + koff;
                uint32_t bh[4], bl[4];
                ldsm_x4(bh[0], bh[1], bh[2], bh[3], addr);
                ldsm_x4(bl[0], bl[1], bl[2], bl[3], addr + O_BPL);
                #pragma unroll
                for (int m = 0; m < 2; m++)
                    #pragma unroll
                    for (int jb = 0; jb < 2; jb++) {
                        float* d = acc[m][jj * 2 + jb];
                        mma_bf16(d, ah[m], bh + jb * 2);
                        mma_bf16(d, ah[m], bl + jb * 2);
                        mma_bf16(d, al[m], bh + jb * 2);
                    }
            }
        }
    }
    __syncthreads();   // all tile reads done; safe to overwrite with staging
    float* sx = (float*)smem;
    #pragma unroll
    for (int m = 0; m < 2; m++)
        #pragma unroll
        for (int j = 0; j < 8; j++) {
            int qr  = qw + m * 16 + (lane >> 2);
            int col = ew + j * 8 + (lane & 3) * 2;
            sx[qr * XS + col]           = acc[m][j][0];
            sx[qr * XS + col + 1]       = acc[m][j][1];
            sx[(qr + 8) * XS + col]     = acc[m][j][2];
            sx[(qr + 8) * XS + col + 1] = acc[m][j][3];
        }
    __syncthreads();
    // LN epilogue: warp wid -> rows wid*8..+7; lane -> e {lane*4, 128+lane*4}
    float wb[8], gm[8], be[8];
    {
        float4 w0 = *(const float4*)&Wb[lane * 4];
        float4 w1 = *(const float4*)&Wb[lane * 4 + 128];
        float4 g0 = *(const float4*)&gamma[lane * 4];
        float4 g1 = *(const float4*)&gamma[lane * 4 + 128];
        float4 e0 = *(const float4*)&beta[lane * 4];
        float4 e1 = *(const float4*)&beta[lane * 4 + 128];
        wb[0]=w0.x; wb[1]=w0.y; wb[2]=w0.z; wb[3]=w0.w; wb[4]=w1.x; wb[5]=w1.y; wb[6]=w1.z; wb[7]=w1.w;
        gm[0]=g0.x; gm[1]=g0.y; gm[2]=g0.z; gm[3]=g0.w; gm[4]=g1.x; gm[5]=g1.y; gm[6]=g1.z; gm[7]=g1.w;
        be[0]=e0.x; be[1]=e0.y; be[2]=e0.z; be[3]=e0.w; be[4]=e1.x; be[5]=e1.y; be[6]=e1.z; be[7]=e1.w;
    }
    const float* tgt = g_tgt + (size_t)b * Q_ * D_;
    #pragma unroll
    for (int i = 0; i < 8; i++) {
        const int r = wid * 8 + i;          // local q row
        const int q = q0 + r;
        float4 a0 = *(const float4*)&sx[r * XS + lane * 4];
        float4 a1 = *(const float4*)&sx[r * XS + lane * 4 + 128];
        float av[8] = {a0.x, a0.y, a0.z, a0.w, a1.x, a1.y, a1.z, a1.w};
        float4 t0 = *(const float4*)&tgt[(size_t)q * D_ + lane * 4];
        float4 t1 = *(const float4*)&tgt[(size_t)q * D_ + lane * 4 + 128];
        float tv[8] = {t0.x, t0.y, t0.z, t0.w, t1.x, t1.y, t1.z, t1.w};
        float v[8], s = 0.f;
        #pragma unroll
        for (int j = 0; j < 8; j++) {
            v[j] = fmaxf(av[j] + wb[j], 0.f) + tv[j];
            s += v[j];
        }
        s = warpSum32(s);
        const float mu = s * (1.0f / 256.0f);
        float d2 = 0.f;
        #pragma unroll
        for (int j = 0; j < 8; j++) { float dd = v[j] - mu; d2 += dd * dd; }
        d2 = warpSum32(d2);
        const float rs = rsqrtf(d2 * (1.0f / 256.0f));
        float o[8];
        #pragma unroll
        for (int j = 0; j < 8; j++) o[j] = (v[j] - mu) * rs * gm[j] + be[j];
        float* orow = out + (size_t)(b * Q_ + q) * D_;
        *(float4*)&orow[lane * 4]       = make_float4(o[0], o[1], o[2], o[3]);
        *(float4*)&orow[lane * 4 + 128] = make_float4(o[4], o[5], o[6], o[7]);
    }
}

// ---------------------------------------------------------------------------
extern "C" void kernel_launch(void* const* d_in, const int* in_sizes, int n_in,
                              void* d_out, int out_size) {
    const float* input    = (const float*)d_in[0];  // [B, D, 32, 32]
    const float* contexts = (const float*)d_in[1];  // [N, B, C, L]
    const float* Wc       = (const float*)d_in[2];  // [D, C]
    const float* Wcat     = (const float*)d_in[3];  // [D, N*D]
    const float* Wb       = (const float*)d_in[4];  // [D]
    const float* gamma    = (const float*)d_in[5];  // [D]
    const float* beta     = (const float*)d_in[6];  // [D]
    float* out = (float*)d_out;                     // [B, Q, D]

    cudaFuncSetAttribute(k_attn_mma, cudaFuncAttributeMaxDynamicSharedMemorySize, MMA_SMEM);
    cudaFuncSetAttribute(k_s2_mma,   cudaFuncAttributeMaxDynamicSharedMemorySize, MMA_SMEM);
    cudaFuncSetAttribute(k_out_mma,  cudaFuncAttributeMaxDynamicSharedMemorySize, O_SMEM);

    k_transpose<<<dim3(Q_ / 32, D_ / 32, B_), dim3(32, 8)>>>(input);
    k_splitW   <<<D_ * ND_ / 1024, 256>>>(Wcat);
    k_source   <<<dim3(2,        N_ * B_),    256>>>(contexts, Wc);
    k_attn_mma <<<dim3(Q_ / 128, N_ * B_),    256, MMA_SMEM>>>();
    k_s2_mma   <<<dim3(2,        N_ * B_),    256, MMA_SMEM>>>();
    k_out_mma  <<<dim3(Q_ / 64,  B_),         256, O_SMEM>>>(Wb, gamma, beta, out);
}

// round 10
// speedup vs baseline: 2.8764x; 1.1320x over previous
#include <cuda_runtime.h>
#include <cuda_bf16.h>
#include <cstdint>

// Problem dims (fixed by the reference)
constexpr int B_  = 32;
constexpr int D_  = 256;   // idf
constexpr int Q_  = 1024;  // ih*iw
constexpr int C_  = 512;   // cdf
constexpr int L_  = 128;
constexpr int N_  = 10;    // contexts
constexpr int K2_ = N_ * L_;  // 1280
constexpr int ND_ = N_ * D_;  // 2560

// Scratch (static device globals — no allocation in kernel_launch)
__device__ float g_tgt[(size_t)B_ * Q_ * D_];          //  [b][q][d] fp32 (residual)
// bf16 split pairs (tensor-core operands)
__device__ __align__(16) __nv_bfloat16 g_tgtH[(size_t)B_ * Q_ * D_];
__device__ __align__(16) __nv_bfloat16 g_tgtL[(size_t)B_ * Q_ * D_];
__device__ __align__(16) __nv_bfloat16 g_srcH[(size_t)N_ * B_ * L_ * D_];
__device__ __align__(16) __nv_bfloat16 g_srcL[(size_t)N_ * B_ * L_ * D_];
__device__ __align__(16) __nv_bfloat16 g_wH [(size_t)B_ * Q_ * N_ * L_];
__device__ __align__(16) __nv_bfloat16 g_wL [(size_t)B_ * Q_ * N_ * L_];
__device__ __align__(16) __nv_bfloat16 g_s2H[(size_t)B_ * D_ * N_ * L_];
__device__ __align__(16) __nv_bfloat16 g_s2L[(size_t)B_ * D_ * N_ * L_];
__device__ __align__(16) __nv_bfloat16 g_WcatH[(size_t)D_ * ND_];
__device__ __align__(16) __nv_bfloat16 g_WcatL[(size_t)D_ * ND_];
__device__ __align__(16) __nv_bfloat16 g_WcH[(size_t)D_ * C_];
__device__ __align__(16) __nv_bfloat16 g_WcL[(size_t)D_ * C_];
__device__ __align__(16) __nv_bfloat16 g_ctxTH[(size_t)N_ * B_ * L_ * C_];
__device__ __align__(16) __nv_bfloat16 g_ctxTL[(size_t)N_ * B_ * L_ * C_];

typedef unsigned long long u64;

__device__ __forceinline__ float warpSum32(float v) {
    #pragma unroll
    for (int o = 16; o; o >>= 1) v += __shfl_xor_sync(0xffffffffu, v, o);
    return v;
}

// ---- bf16 split helpers ----
__device__ __forceinline__ void split1(float x, __nv_bfloat16& h, __nv_bfloat16& l) {
    h = __float2bfloat16(x);
    l = __float2bfloat16(x - __bfloat162float(h));
}
// store two consecutive values as packed bf16 hi/lo pairs (4B each array)
__device__ __forceinline__ void st_pair(__nv_bfloat16* H, __nv_bfloat16* L,
                                        size_t off, float x0, float x1) {
    __nv_bfloat16 h0, l0, h1, l1;
    split1(x0, h0, l0); split1(x1, h1, l1);
    uint32_t hu = (uint32_t)__bfloat16_as_ushort(h0) |
                  ((uint32_t)__bfloat16_as_ushort(h1) << 16);
    uint32_t lu = (uint32_t)__bfloat16_as_ushort(l0) |
                  ((uint32_t)__bfloat16_as_ushort(l1) << 16);
    *(uint32_t*)&H[off] = hu;
    *(uint32_t*)&L[off] = lu;
}

// ---- warp-level tensor core helpers (sm_80 baseline; no 'a' features) ----
__device__ __forceinline__ uint32_t smem_u32(const void* p) {
    uint32_t a;
    asm("{ .reg .u64 t; cvta.to.shared.u64 t, %1; cvt.u32.u64 %0, t; }" : "=r"(a) : "l"(p));
    return a;
}
__device__ __forceinline__ void ldsm_x4(uint32_t& r0, uint32_t& r1, uint32_t& r2,
                                        uint32_t& r3, uint32_t a) {
    asm volatile("ldmatrix.sync.aligned.m8n8.x4.shared.b16 {%0,%1,%2,%3}, [%4];"
                 : "=r"(r0), "=r"(r1), "=r"(r2), "=r"(r3) : "r"(a));
}
__device__ __forceinline__ void mma_bf16(float* d, const uint32_t* a, const uint32_t* b) {
    asm volatile("mma.sync.aligned.m16n8k16.row.col.f32.bf16.bf16.f32 "
        "{%0,%1,%2,%3}, {%4,%5,%6,%7}, {%8,%9}, {%0,%1,%2,%3};"
        : "+f"(d[0]), "+f"(d[1]), "+f"(d[2]), "+f"(d[3])
        : "r"(a[0]), "r"(a[1]), "r"(a[2]), "r"(a[3]), "r"(b[0]), "r"(b[1]));
}
__device__ __forceinline__ void cp16(uint32_t saddr, const void* gaddr) {
    asm volatile("cp.async.cg.shared.global [%0], [%1], 16;"
                 :: "r"(saddr), "l"(gaddr) : "memory");
}
#define CP_COMMIT() asm volatile("cp.async.commit_group;" ::: "memory")
#define CP_WAIT(n)  asm volatile("cp.async.wait_group %0;" :: "n"(n) : "memory")

// 3-term split MMA for one jj-group, term-outer ordering:
// dependent HMMAs on the same acc are 4 apart (m x jb interleave).
__device__ __forceinline__ void mma_group(float (*acc)[4], int jj,
                                          uint32_t (&ah)[2][4], uint32_t (&al)[2][4],
                                          const uint32_t* bh, const uint32_t* bl) {
    #pragma unroll
    for (int m = 0; m < 2; m++)
        #pragma unroll
        for (int jb = 0; jb < 2; jb++)
            mma_bf16(acc[m * 8 + jj * 2 + jb], ah[m], bh + jb * 2);   // hi*hi
    #pragma unroll
    for (int m = 0; m < 2; m++)
        #pragma unroll
        for (int jb = 0; jb < 2; jb++)
            mma_bf16(acc[m * 8 + jj * 2 + jb], ah[m], bl + jb * 2);   // hi*lo
    #pragma unroll
    for (int m = 0; m < 2; m++)
        #pragma unroll
        for (int jb = 0; jb < 2; jb++)
            mma_bf16(acc[m * 8 + jj * 2 + jb], al[m], bh + jb * 2);   // lo*hi
}

// ---------------------------------------------------------------------------
// K1: transpose input [B][D][Q] -> g_tgt fp32 + g_tgtH/L bf16 split, [B][Q][D]
// ---------------------------------------------------------------------------
__global__ void __launch_bounds__(256) k_transpose(const float* __restrict__ in) {
    __shared__ float tile[32][33];
    const int b  = blockIdx.z;
    const int q0 = blockIdx.x * 32;
    const int d0 = blockIdx.y * 32;
    const int tx = threadIdx.x, ty = threadIdx.y;  // 32 x 8
    #pragma unroll
    for (int j = 0; j < 4; j++)
        tile[ty + j * 8][tx] = in[((size_t)b * D_ + d0 + ty + j * 8) * Q_ + q0 + tx];
    __syncthreads();
    #pragma unroll
    for (int j = 0; j < 4; j++) {
        float x = tile[tx][ty + j * 8];
        size_t idx = ((size_t)b * Q_ + q0 + ty + j * 8) * D_ + d0 + tx;
        g_tgt[idx] = x;
        __nv_bfloat16 h, l; split1(x, h, l);
        g_tgtH[idx] = h; g_tgtL[idx] = l;
    }
}

// ---------------------------------------------------------------------------
// K1b: split Wcat fp32 -> bf16 hi/lo
// ---------------------------------------------------------------------------
__global__ void __launch_bounds__(256) k_splitW(const float* __restrict__ Wcat) {
    int idx = blockIdx.x * 1024 + threadIdx.x * 4;
    #pragma unroll
    for (int i = 0; i < 4; i++) {
        float x = Wcat[idx + i];
        __nv_bfloat16 h, l; split1(x, h, l);
        g_WcatH[idx + i] = h; g_WcatL[idx + i] = l;
    }
}

// K1c: split Wc fp32 -> bf16 hi/lo
__global__ void __launch_bounds__(256) k_splitWc(const float* __restrict__ Wc) {
    int idx = blockIdx.x * 1024 + threadIdx.x * 4;
    #pragma unroll
    for (int i = 0; i < 4; i++) {
        float x = Wc[idx + i];
        __nv_bfloat16 h, l; split1(x, h, l);
        g_WcH[idx + i] = h; g_WcL[idx + i] = l;
    }
}

// ---------------------------------------------------------------------------
// K1d: transpose+split contexts [nb][c][l] fp32 -> g_ctxTH/L [nb][l][c] bf16
// ---------------------------------------------------------------------------
__global__ void __launch_bounds__(256) k_ctxT(const float* __restrict__ ctx) {
    __shared__ float tile[32][33];
    const int nb = blockIdx.z;
    const int l0 = blockIdx.x * 32;
    const int c0 = blockIdx.y * 32;
    const int tx = threadIdx.x, ty = threadIdx.y;  // 32 x 8
    const float* cp = ctx + (size_t)nb * C_ * L_;
    #pragma unroll
    for (int j = 0; j < 4; j++)
        tile[ty + j * 8][tx] = cp[(size_t)(c0 + ty + j * 8) * L_ + l0 + tx];
    __syncthreads();
    #pragma unroll
    for (int j = 0; j < 4; j++) {
        float x = tile[tx][ty + j * 8];   // ctx[c0+tx][l0+ty+j*8]
        size_t idx = ((size_t)nb * L_ + l0 + ty + j * 8) * C_ + c0 + tx;
        __nv_bfloat16 h, l; split1(x, h, l);
        g_ctxTH[idx] = h; g_ctxTL[idx] = l;
    }
}

// ---------------------------------------------------------------------------
// Shared tile constants for the 128x128 mma kernels
// ---------------------------------------------------------------------------
constexpr int ROWB    = 80;
constexpr int PLANE   = 128 * ROWB;      // 10240
constexpr int BUFSZ   = 4 * PLANE;       // 40960
constexpr int LSTRIDE = 129;
constexpr int MMA_SMEM = 2 * BUFSZ;      // 81920 (attn logits 66048 reuses it)
constexpr int NCH = 8;                   // K=256 in chunks of 32

// ---------------------------------------------------------------------------
// K2 (mma.sync): src[l,d] = sum_c ctxT[l,c] * Wc[d,c]  (3-term bf16 split)
// tile 128 l (M) x 128 d (N), K = 512 in 16 chunks; emits bf16 hi/lo.
// ---------------------------------------------------------------------------
constexpr int SRC_NCH = C_ / 32;  // 16

__global__ void __launch_bounds__(256, 2) k_source_mma() {
    extern __shared__ __align__(16) char smem[];
    const uint32_t sb = smem_u32(smem);
    const int t = threadIdx.x;
    const int lane = t & 31, wid = t >> 5;
    const int qw = (wid & 3) * 32;   // l dir (M)
    const int lw = (wid >> 2) * 64;  // d dir (N)
    const int nb = blockIdx.y;
    const int d0 = blockIdx.x * 128;

    const __nv_bfloat16* aH = g_ctxTH + (size_t)nb * L_ * C_;
    const __nv_bfloat16* aL = g_ctxTL + (size_t)nb * L_ * C_;
    const __nv_bfloat16* bH = g_WcH + (size_t)d0 * C_;
    const __nv_bfloat16* bL = g_WcL + (size_t)d0 * C_;

    auto prefetch = [&](int c, int buf) {
        const int kd = c * 32;
        const uint32_t sbase = sb + buf * BUFSZ;
        #pragma unroll
        for (int i = 0; i < 8; i++) {
            int idx = t + i * 256;
            int pl = idx >> 9;
            int p2 = idx & 511;
            int row = p2 >> 2, c4 = p2 & 3;
            const __nv_bfloat16* sp =
                (pl == 0) ? aH : (pl == 1) ? aL : (pl == 2) ? bH : bL;
            cp16(sbase + pl * PLANE + row * ROWB + c4 * 16,
                 sp + (size_t)row * C_ + kd + c4 * 8);
        }
        CP_COMMIT();
    };

    float acc[16][4] = {};   // [m*8 + jj*2 + jb][frag]

    prefetch(0, 0);
    for (int c = 0; c < SRC_NCH; c++) {
        const int buf = c & 1;
        __syncthreads();
        if (c + 1 < SRC_NCH) { prefetch(c + 1, buf ^ 1); CP_WAIT(1); }
        else                 { CP_WAIT(0); }
        __syncthreads();
        const uint32_t sbase = sb + buf * BUFSZ;
        #pragma unroll
        for (int kh = 0; kh < 2; kh++) {
            uint32_t ah[2][4], al[2][4];
            #pragma unroll
            for (int m = 0; m < 2; m++) {
                uint32_t addr = sbase + (qw + m * 16 + (lane & 15)) * ROWB
                              + (lane >> 4) * 16 + kh * 32;
                ldsm_x4(ah[m][0], ah[m][1], ah[m][2], ah[m][3], addr);
                ldsm_x4(al[m][0], al[m][1], al[m][2], al[m][3], addr + PLANE);
            }
            const int nrow = (lane & 7) + ((lane >> 4) << 3);
            const int koff = ((lane >> 3) & 1) * 16;
            #pragma unroll
            for (int jj = 0; jj < 4; jj++) {
                uint32_t addr = sbase + 2 * PLANE + (lw + jj * 16 + nrow) * ROWB
                              + kh * 32 + koff;
                uint32_t bh[4], bl[4];
                ldsm_x4(bh[0], bh[1], bh[2], bh[3], addr);
                ldsm_x4(bl[0], bl[1], bl[2], bl[3], addr + PLANE);
                mma_group(acc, jj, ah, al, bh, bl);
            }
        }
    }
    #pragma unroll
    for (int m = 0; m < 2; m++)
        #pragma unroll
        for (int j = 0; j < 8; j++) {
            int lr  = qw + m * 16 + (lane >> 2);
            int col = d0 + lw + j * 8 + (lane & 3) * 2;
            float* d = acc[m * 8 + j];
            size_t off0 = ((size_t)nb * L_ + lr) * D_ + col;
            size_t off1 = ((size_t)nb * L_ + lr + 8) * D_ + col;
            st_pair(g_srcH, g_srcL, off0, d[0], d[1]);
            st_pair(g_srcH, g_srcL, off1, d[2], d[3]);
        }
}

// ---------------------------------------------------------------------------
// K3 (mma.sync): logits[128q,128l] = tgt·src^T (3-term bf16 split), softmax,
// write w as bf16 hi/lo. 8 warps: 4 along q, 2 along l.
// ---------------------------------------------------------------------------
__global__ void __launch_bounds__(256, 2) k_attn_mma() {
    extern __shared__ __align__(16) char smem[];
    float* logits = (float*)smem;
    const uint32_t sb = smem_u32(smem);
    const int t = threadIdx.x;
    const int lane = t & 31, wid = t >> 5;
    const int qw = (wid & 3) * 32;
    const int lw = (wid >> 2) * 64;
    const int nb = blockIdx.y;
    const int n = nb >> 5, b = nb & 31;
    const int q0 = blockIdx.x * 128;

    const __nv_bfloat16* aH = g_tgtH + ((size_t)b * Q_ + q0) * D_;
    const __nv_bfloat16* aL = g_tgtL + ((size_t)b * Q_ + q0) * D_;
    const __nv_bfloat16* bH = g_srcH + (size_t)nb * L_ * D_;
    const __nv_bfloat16* bL = g_srcL + (size_t)nb * L_ * D_;

    auto prefetch = [&](int c, int buf) {
        const int kd = c * 32;
        const uint32_t sbase = sb + buf * BUFSZ;
        #pragma unroll
        for (int i = 0; i < 8; i++) {
            int idx = t + i * 256;
            int pl = idx >> 9;
            int p2 = idx & 511;
            int row = p2 >> 2, c4 = p2 & 3;
            const __nv_bfloat16* sp =
                (pl == 0) ? aH : (pl == 1) ? aL : (pl == 2) ? bH : bL;
            cp16(sbase + pl * PLANE + row * ROWB + c4 * 16,
                 sp + (size_t)row * D_ + kd + c4 * 8);
        }
        CP_COMMIT();
    };

    float acc[16][4] = {};

    prefetch(0, 0);
    for (int c = 0; c < NCH; c++) {
        const int buf = c & 1;
        __syncthreads();
        if (c + 1 < NCH) { prefetch(c + 1, buf ^ 1); CP_WAIT(1); }
        else             { CP_WAIT(0); }
        __syncthreads();
        const uint32_t sbase = sb + buf * BUFSZ;
        #pragma unroll
        for (int kh = 0; kh < 2; kh++) {
            uint32_t ah[2][4], al[2][4];
            #pragma unroll
            for (int m = 0; m < 2; m++) {
                uint32_t addr = sbase + (qw + m * 16 + (lane & 15)) * ROWB
                              + (lane >> 4) * 16 + kh * 32;
                ldsm_x4(ah[m][0], ah[m][1], ah[m][2], ah[m][3], addr);
                ldsm_x4(al[m][0], al[m][1], al[m][2], al[m][3], addr + PLANE);
            }
            const int nrow = (lane & 7) + ((lane >> 4) << 3);
            const int koff = ((lane >> 3) & 1) * 16;
            #pragma unroll
            for (int jj = 0; jj < 4; jj++) {
                uint32_t addr = sbase + 2 * PLANE + (lw + jj * 16 + nrow) * ROWB
                              + kh * 32 + koff;
                uint32_t bh[4], bl[4];
                ldsm_x4(bh[0], bh[1], bh[2], bh[3], addr);
                ldsm_x4(bl[0], bl[1], bl[2], bl[3], addr + PLANE);
                mma_group(acc, jj, ah, al, bh, bl);
            }
        }
    }
    __syncthreads();
    #pragma unroll
    for (int m = 0; m < 2; m++)
        #pragma unroll
        for (int j = 0; j < 8; j++) {
            int qr  = qw + m * 16 + (lane >> 2);
            int col = lw + j * 8 + (lane & 3) * 2;
            float* d = acc[m * 8 + j];
            logits[qr * LSTRIDE + col]           = d[0];
            logits[qr * LSTRIDE + col + 1]       = d[1];
            logits[(qr + 8) * LSTRIDE + col]     = d[2];
            logits[(qr + 8) * LSTRIDE + col + 1] = d[3];
        }
    __syncthreads();
    if (t < 128) {
        float* row = logits + t * LSTRIDE;
        float m = row[0];
        #pragma unroll 8
        for (int j = 1; j < 128; j++) m = fmaxf(m, row[j]);
        float s = 0.f;
        #pragma unroll 8
        for (int j = 0; j < 128; j++) {
            float ev = __expf(row[j] - m);
            row[j] = ev;
            s += ev;
        }
        float inv = 1.0f / s;
        size_t base = (((size_t)b * Q_ + q0 + t) * N_ + n) * L_;
        #pragma unroll
        for (int j = 0; j < 128; j += 2)
            st_pair(g_wH, g_wL, base + j, row[j] * inv, row[j + 1] * inv);
    }
}

// ---------------------------------------------------------------------------
// K4 (mma.sync): S2[e,l] = sum_d Wcat[e, n*D+d] * src[l,d] -> bf16 hi/lo
// ---------------------------------------------------------------------------
__global__ void __launch_bounds__(256, 2) k_s2_mma() {
    extern __shared__ __align__(16) char smem[];
    const uint32_t sb = smem_u32(smem);
    const int t = threadIdx.x;
    const int lane = t & 31, wid = t >> 5;
    const int qw = (wid & 3) * 32;   // e dir
    const int lw = (wid >> 2) * 64;  // l dir
    const int nb = blockIdx.y;
    const int n = nb >> 5, b = nb & 31;
    const int e0 = blockIdx.x * 128;

    const __nv_bfloat16* aH = g_WcatH + (size_t)e0 * ND_ + n * D_;
    const __nv_bfloat16* aL = g_WcatL + (size_t)e0 * ND_ + n * D_;
    const __nv_bfloat16* bH = g_srcH + (size_t)nb * L_ * D_;
    const __nv_bfloat16* bL = g_srcL + (size_t)nb * L_ * D_;

    auto prefetch = [&](int c, int buf) {
        const int kd = c * 32;
        const uint32_t sbase = sb + buf * BUFSZ;
        #pragma unroll
        for (int i = 0; i < 8; i++) {
            int idx = t + i * 256;
            int pl = idx >> 9;
            int p2 = idx & 511;
            int row = p2 >> 2, c4 = p2 & 3;
            const __nv_bfloat16* sp;
            size_t stride;
            if (pl < 2) { sp = pl ? aL : aH; stride = ND_; }
            else        { sp = (pl == 3) ? bL : bH; stride = D_; }
            cp16(sbase + pl * PLANE + row * ROWB + c4 * 16,
                 sp + (size_t)row * stride + kd + c4 * 8);
        }
        CP_COMMIT();
    };

    float acc[16][4] = {};

    prefetch(0, 0);
    for (int c = 0; c < NCH; c++) {
        const int buf = c & 1;
        __syncthreads();
        if (c + 1 < NCH) { prefetch(c + 1, buf ^ 1); CP_WAIT(1); }
        else             { CP_WAIT(0); }
        __syncthreads();
        const uint32_t sbase = sb + buf * BUFSZ;
        #pragma unroll
        for (int kh = 0; kh < 2; kh++) {
            uint32_t ah[2][4], al[2][4];
            #pragma unroll
            for (int m = 0; m < 2; m++) {
                uint32_t addr = sbase + (qw + m * 16 + (lane & 15)) * ROWB
                              + (lane >> 4) * 16 + kh * 32;
                ldsm_x4(ah[m][0], ah[m][1], ah[m][2], ah[m][3], addr);
                ldsm_x4(al[m][0], al[m][1], al[m][2], al[m][3], addr + PLANE);
            }
            const int nrow = (lane & 7) + ((lane >> 4) << 3);
            const int koff = ((lane >> 3) & 1) * 16;
            #pragma unroll
            for (int jj = 0; jj < 4; jj++) {
                uint32_t addr = sbase + 2 * PLANE + (lw + jj * 16 + nrow) * ROWB
                              + kh * 32 + koff;
                uint32_t bh[4], bl[4];
                ldsm_x4(bh[0], bh[1], bh[2], bh[3], addr);
                ldsm_x4(bl[0], bl[1], bl[2], bl[3], addr + PLANE);
                mma_group(acc, jj, ah, al, bh, bl);
            }
        }
    }
    #pragma unroll
    for (int m = 0; m < 2; m++)
        #pragma unroll
        for (int j = 0; j < 8; j++) {
            int er  = e0 + qw + m * 16 + (lane >> 2);
            int col = lw + j * 8 + (lane & 3) * 2;
            float* d = acc[m * 8 + j];
            size_t off0 = (((size_t)b * D_ + er) * N_ + n) * L_ + col;
            size_t off1 = (((size_t)b * D_ + er + 8) * N_ + n) * L_ + col;
            st_pair(g_s2H, g_s2L, off0, d[0], d[1]);
            st_pair(g_s2H, g_s2L, off1, d[2], d[3]);
        }
}

// ---------------------------------------------------------------------------
// K5 (mma.sync): x[q,e] = sum_k w[q,k]*s2[e,k], K=1280, tile 64q x 256e.
// 8 warps: 2 along q (32 rows), 4 along e (64 cols).
// Epilogue: stage x to smem, then bias+relu+residual+LayerNorm -> out.
// ---------------------------------------------------------------------------
constexpr int O_ROWB = 80;
constexpr int O_APL  = 64 * O_ROWB;    // 5120
constexpr int O_BPL  = 256 * O_ROWB;   // 20480
constexpr int O_BUF  = 2 * O_APL + 2 * O_BPL;  // 51200
constexpr int O_SMEM = 2 * O_BUF;      // 102400 (x-staging 66560 reuses it)
constexpr int O_NCH  = K2_ / 32;       // 40
constexpr int XS     = 260;            // x staging row stride (floats)

__global__ void __launch_bounds__(256, 2) k_out_mma(const float* __restrict__ Wb,
                                                    const float* __restrict__ gamma,
                                                    const float* __restrict__ beta,
                                                    float* __restrict__ out) {
    extern __shared__ __align__(16) char smem[];
    const uint32_t sb = smem_u32(smem);
    const int t = threadIdx.x;
    const int lane = t & 31, wid = t >> 5;
    const int qw = (wid & 1) * 32;   // q dir
    const int ew = (wid >> 1) * 64;  // e dir
    const int b  = blockIdx.y;
    const int q0 = blockIdx.x * 64;

    const __nv_bfloat16* wHp = g_wH + ((size_t)b * Q_ + q0) * K2_;
    const __nv_bfloat16* wLp = g_wL + ((size_t)b * Q_ + q0) * K2_;
    const __nv_bfloat16* sHp = g_s2H + (size_t)b * D_ * K2_;
    const __nv_bfloat16* sLp = g_s2L + (size_t)b * D_ * K2_;

    auto prefetch = [&](int c, int buf) {
        const int k0 = c * 32;
        const uint32_t sbase = sb + buf * O_BUF;
        #pragma unroll
        for (int i = 0; i < 10; i++) {
            int idx = t + i * 256;
            if (idx < 512) {       // A planes: 64 rows x 4 c4 x 2
                int pl = idx >> 8, p = idx & 255, row = p >> 2, c4 = p & 3;
                const __nv_bfloat16* sp = pl ? wLp : wHp;
                cp16(sbase + pl * O_APL + row * O_ROWB + c4 * 16,
                     sp + (size_t)row * K2_ + k0 + c4 * 8);
            } else {               // B planes: 256 rows x 4 c4 x 2
                int idx2 = idx - 512;
                int pl = idx2 >> 10, p = idx2 & 1023, row = p >> 2, c4 = p & 3;
                const __nv_bfloat16* sp = pl ? sLp : sHp;
                cp16(sbase + 2 * O_APL + pl * O_BPL + row * O_ROWB + c4 * 16,
                     sp + (size_t)row * K2_ + k0 + c4 * 8);
            }
        }
        CP_COMMIT();
    };

    float acc[16][4] = {};

    prefetch(0, 0);
    for (int c = 0; c < O_NCH; c++) {
        const int buf = c & 1;
        __syncthreads();
        if (c + 1 < O_NCH) { prefetch(c + 1, buf ^ 1); CP_WAIT(1); }
        else               { CP_WAIT(0); }
        __syncthreads();
        const uint32_t sbase = sb + buf * O_BUF;
        #pragma unroll
        for (int kh = 0; kh < 2; kh++) {
            uint32_t ah[2][4], al[2][4];
            #pragma unroll
            for (int m = 0; m < 2; m++) {
                uint32_t addr = sbase + (qw + m * 16 + (lane & 15)) * O_ROWB
                              + (lane >> 4) * 16 + kh * 32;
                ldsm_x4(ah[m][0], ah[m][1], ah[m][2], ah[m][3], addr);
                ldsm_x4(al[m][0], al[m][1], al[m][2], al[m][3], addr + O_APL);
            }
            const int nrow = (lane & 7) + ((lane >> 4) << 3);
            const int koff = ((lane >> 3) & 1) * 16;
            #pragma unroll
            for (int jj = 0; jj < 4; jj++) {
                uint32_t addr = sbase + 2 * O_APL + (ew + jj * 16 + nrow) * O_ROWB
                              + kh * 32 + koff;
                uint32_t bh[4], bl[4];
                ldsm_x4(bh[0], bh[1], bh[2], bh[3], addr);
                ldsm_x4(bl[0], bl[1], bl[2], bl[3], addr + O_BPL);
                mma_group(acc, jj, ah, al, bh, bl);
            }
        }
    }
    __syncthreads();   // all tile reads done; safe to overwrite with staging
    float* sx = (float*)smem;
    #pragma unroll
    for (int m = 0; m < 2; m++)
        #pragma unroll
        for (int j = 0; j < 8; j++) {
            int qr  = qw + m * 16 + (lane >> 2);
            int col = ew + j * 8 + (lane & 3) * 2;
            float* d = acc[m * 8 + j];
            sx[qr * XS + col]           = d[0];
            sx[qr * XS + col + 1]       = d[1];
            sx[(qr + 8) * XS + col]     = d[2];
            sx[(qr + 8) * XS + col + 1] = d[3];
        }
    __syncthreads();
    // LN epilogue: warp wid -> rows wid*8..+7; lane -> e {lane*4, 128+lane*4}
    float wb[8], gm[8], be[8];
    {
        float4 w0 = *(const float4*)&Wb[lane * 4];
        float4 w1 = *(const float4*)&Wb[lane * 4 + 128];
        float4 g0 = *(const float4*)&gamma[lane * 4];
        float4 g1 = *(const float4*)&gamma[lane * 4 + 128];
        float4 e0 = *(const float4*)&beta[lane * 4];
        float4 e1 = *(const float4*)&beta[lane * 4 + 128];
        wb[0]=w0.x; wb[1]=w0.y; wb[2]=w0.z; wb[3]=w0.w; wb[4]=w1.x; wb[5]=w1.y; wb[6]=w1.z; wb[7]=w1.w;
        gm[0]=g0.x; gm[1]=g0.y; gm[2]=g0.z; gm[3]=g0.w; gm[4]=g1.x; gm[5]=g1.y; gm[6]=g1.z; gm[7]=g1.w;
        be[0]=e0.x; be[1]=e0.y; be[2]=e0.z; be[3]=e0.w; be[4]=e1.x; be[5]=e1.y; be[6]=e1.z; be[7]=e1.w;
    }
    const float* tgt = g_tgt + (size_t)b * Q_ * D_;
    #pragma unroll
    for (int i = 0; i < 8; i++) {
        const int r = wid * 8 + i;          // local q row
        const int q = q0 + r;
        float4 a0 = *(const float4*)&sx[r * XS + lane * 4];
        float4 a1 = *(const float4*)&sx[r * XS + lane * 4 + 128];
        float av[8] = {a0.x, a0.y, a0.z, a0.w, a1.x, a1.y, a1.z, a1.w};
        float4 t0 = *(const float4*)&tgt[(size_t)q * D_ + lane * 4];
        float4 t1 = *(const float4*)&tgt[(size_t)q * D_ + lane * 4 + 128];
        float tv[8] = {t0.x, t0.y, t0.z, t0.w, t1.x, t1.y, t1.z, t1.w};
        float v[8], s = 0.f;
        #pragma unroll
        for (int j = 0; j < 8; j++) {
            v[j] = fmaxf(av[j] + wb[j], 0.f) + tv[j];
            s += v[j];
        }
        s = warpSum32(s);
        const float mu = s * (1.0f / 256.0f);
        float d2 = 0.f;
        #pragma unroll
        for (int j = 0; j < 8; j++) { float dd = v[j] - mu; d2 += dd * dd; }
        d2 = warpSum32(d2);
        const float rs = rsqrtf(d2 * (1.0f / 256.0f));
        float o[8];
        #pragma unroll
        for (int j = 0; j < 8; j++) o[j] = (v[j] - mu) * rs * gm[j] + be[j];
        float* orow = out + (size_t)(b * Q_ + q) * D_;
        *(float4*)&orow[lane * 4]       = make_float4(o[0], o[1], o[2], o[3]);
        *(float4*)&orow[lane * 4 + 128] = make_float4(o[4], o[5], o[6], o[7]);
    }
}

// ---------------------------------------------------------------------------
extern "C" void kernel_launch(void* const* d_in, const int* in_sizes, int n_in,
                              void* d_out, int out_size) {
    const float* input    = (const float*)d_in[0];  // [B, D, 32, 32]
    const float* contexts = (const float*)d_in[1];  // [N, B, C, L]
    const float* Wc       = (const float*)d_in[2];  // [D, C]
    const float* Wcat     = (const float*)d_in[3];  // [D, N*D]
    const float* Wb       = (const float*)d_in[4];  // [D]
    const float* gamma    = (const float*)d_in[5];  // [D]
    const float* beta     = (const float*)d_in[6];  // [D]
    float* out = (float*)d_out;                     // [B, Q, D]

    cudaFuncSetAttribute(k_source_mma, cudaFuncAttributeMaxDynamicSharedMemorySize, MMA_SMEM);
    cudaFuncSetAttribute(k_attn_mma,   cudaFuncAttributeMaxDynamicSharedMemorySize, MMA_SMEM);
    cudaFuncSetAttribute(k_s2_mma,     cudaFuncAttributeMaxDynamicSharedMemorySize, MMA_SMEM);
    cudaFuncSetAttribute(k_out_mma,    cudaFuncAttributeMaxDynamicSharedMemorySize, O_SMEM);

    k_transpose <<<dim3(Q_ / 32, D_ / 32, B_), dim3(32, 8)>>>(input);
    k_splitW    <<<D_ * ND_ / 1024, 256>>>(Wcat);
    k_splitWc   <<<D_ * C_ / 1024, 256>>>(Wc);
    k_ctxT      <<<dim3(L_ / 32, C_ / 32, N_ * B_), dim3(32, 8)>>>(contexts);
    k_source_mma<<<dim3(2,        N_ * B_),    256, MMA_SMEM>>>();
    k_attn_mma  <<<dim3(Q_ / 128, N_ * B_),    256, MMA_SMEM>>>();
    k_s2_mma    <<<dim3(2,        N_ * B_),    256, MMA_SMEM>>>();
    k_out_mma   <<<dim3(Q_ / 64,  B_),         256, O_SMEM>>>(Wb, gamma, beta, out);
}

// round 11
// speedup vs baseline: 2.9611x; 1.0294x over previous
#include <cuda_runtime.h>
#include <cuda_bf16.h>
#include <cstdint>

// Problem dims (fixed by the reference)
constexpr int B_  = 32;
constexpr int D_  = 256;   // idf
constexpr int Q_  = 1024;  // ih*iw
constexpr int C_  = 512;   // cdf
constexpr int L_  = 128;
constexpr int N_  = 10;    // contexts
constexpr int K2_ = N_ * L_;  // 1280
constexpr int ND_ = N_ * D_;  // 2560

// Scratch (static device globals — no allocation in kernel_launch)
__device__ float g_tgt[(size_t)B_ * Q_ * D_];          //  [b][q][d] fp32 (residual)
// bf16 split pairs (tensor-core operands)
__device__ __align__(16) __nv_bfloat16 g_tgtH[(size_t)B_ * Q_ * D_];
__device__ __align__(16) __nv_bfloat16 g_tgtL[(size_t)B_ * Q_ * D_];
__device__ __align__(16) __nv_bfloat16 g_srcH[(size_t)N_ * B_ * L_ * D_];
__device__ __align__(16) __nv_bfloat16 g_srcL[(size_t)N_ * B_ * L_ * D_];
__device__ __align__(16) __nv_bfloat16 g_wH [(size_t)B_ * Q_ * N_ * L_];
__device__ __align__(16) __nv_bfloat16 g_wL [(size_t)B_ * Q_ * N_ * L_];
__device__ __align__(16) __nv_bfloat16 g_s2H[(size_t)B_ * D_ * N_ * L_];
__device__ __align__(16) __nv_bfloat16 g_s2L[(size_t)B_ * D_ * N_ * L_];
__device__ __align__(16) __nv_bfloat16 g_WcatH[(size_t)D_ * ND_];
__device__ __align__(16) __nv_bfloat16 g_WcatL[(size_t)D_ * ND_];
__device__ __align__(16) __nv_bfloat16 g_WcH[(size_t)D_ * C_];
__device__ __align__(16) __nv_bfloat16 g_WcL[(size_t)D_ * C_];
__device__ __align__(16) __nv_bfloat16 g_ctxTH[(size_t)N_ * B_ * L_ * C_];
__device__ __align__(16) __nv_bfloat16 g_ctxTL[(size_t)N_ * B_ * L_ * C_];

typedef unsigned long long u64;

__device__ __forceinline__ float warpSum32(float v) {
    #pragma unroll
    for (int o = 16; o; o >>= 1) v += __shfl_xor_sync(0xffffffffu, v, o);
    return v;
}

// ---- bf16 split helpers ----
__device__ __forceinline__ void split1(float x, __nv_bfloat16& h, __nv_bfloat16& l) {
    h = __float2bfloat16(x);
    l = __float2bfloat16(x - __bfloat162float(h));
}
__device__ __forceinline__ void st_pair(__nv_bfloat16* H, __nv_bfloat16* L,
                                        size_t off, float x0, float x1) {
    __nv_bfloat16 h0, l0, h1, l1;
    split1(x0, h0, l0); split1(x1, h1, l1);
    uint32_t hu = (uint32_t)__bfloat16_as_ushort(h0) |
                  ((uint32_t)__bfloat16_as_ushort(h1) << 16);
    uint32_t lu = (uint32_t)__bfloat16_as_ushort(l0) |
                  ((uint32_t)__bfloat16_as_ushort(l1) << 16);
    *(uint32_t*)&H[off] = hu;
    *(uint32_t*)&L[off] = lu;
}

// ---- warp-level tensor core helpers (sm_80 baseline; no 'a' features) ----
__device__ __forceinline__ uint32_t smem_u32(const void* p) {
    uint32_t a;
    asm("{ .reg .u64 t; cvta.to.shared.u64 t, %1; cvt.u32.u64 %0, t; }" : "=r"(a) : "l"(p));
    return a;
}
__device__ __forceinline__ void ldsm_x4(uint32_t& r0, uint32_t& r1, uint32_t& r2,
                                        uint32_t& r3, uint32_t a) {
    asm volatile("ldmatrix.sync.aligned.m8n8.x4.shared.b16 {%0,%1,%2,%3}, [%4];"
                 : "=r"(r0), "=r"(r1), "=r"(r2), "=r"(r3) : "r"(a));
}
__device__ __forceinline__ void mma_bf16(float* d, const uint32_t* a, const uint32_t* b) {
    asm volatile("mma.sync.aligned.m16n8k16.row.col.f32.bf16.bf16.f32 "
        "{%0,%1,%2,%3}, {%4,%5,%6,%7}, {%8,%9}, {%0,%1,%2,%3};"
        : "+f"(d[0]), "+f"(d[1]), "+f"(d[2]), "+f"(d[3])
        : "r"(a[0]), "r"(a[1]), "r"(a[2]), "r"(a[3]), "r"(b[0]), "r"(b[1]));
}
__device__ __forceinline__ void cp16(uint32_t saddr, const void* gaddr) {
    asm volatile("cp.async.cg.shared.global [%0], [%1], 16;"
                 :: "r"(saddr), "l"(gaddr) : "memory");
}
#define CP_COMMIT() asm volatile("cp.async.commit_group;" ::: "memory")
#define CP_WAIT(n)  asm volatile("cp.async.wait_group %0;" :: "n"(n) : "memory")

// XOR-swizzled 64B-row tile offset: row-major, 4 16B chunks per row,
// conflict-free for ldmatrix 8-row groups and for the cp.async write pattern.
__device__ __forceinline__ uint32_t swz(int row, int c4) {
    return (uint32_t)(row * 64 + ((c4 ^ ((row >> 1) & 3)) << 4));
}

// 3-term split MMA for one jj-group, term-outer ordering
__device__ __forceinline__ void mma_group(float (*acc)[4], int jj,
                                          uint32_t (&ah)[2][4], uint32_t (&al)[2][4],
                                          const uint32_t* bh, const uint32_t* bl) {
    #pragma unroll
    for (int m = 0; m < 2; m++)
        #pragma unroll
        for (int jb = 0; jb < 2; jb++)
            mma_bf16(acc[m * 8 + jj * 2 + jb], ah[m], bh + jb * 2);
    #pragma unroll
    for (int m = 0; m < 2; m++)
        #pragma unroll
        for (int jb = 0; jb < 2; jb++)
            mma_bf16(acc[m * 8 + jj * 2 + jb], ah[m], bl + jb * 2);
    #pragma unroll
    for (int m = 0; m < 2; m++)
        #pragma unroll
        for (int jb = 0; jb < 2; jb++)
            mma_bf16(acc[m * 8 + jj * 2 + jb], al[m], bh + jb * 2);
}

// ---------------------------------------------------------------------------
// K1: transpose input [B][D][Q] -> g_tgt fp32 + g_tgtH/L bf16 split, [B][Q][D]
// ---------------------------------------------------------------------------
__global__ void __launch_bounds__(256) k_transpose(const float* __restrict__ in) {
    __shared__ float tile[32][33];
    const int b  = blockIdx.z;
    const int q0 = blockIdx.x * 32;
    const int d0 = blockIdx.y * 32;
    const int tx = threadIdx.x, ty = threadIdx.y;  // 32 x 8
    #pragma unroll
    for (int j = 0; j < 4; j++)
        tile[ty + j * 8][tx] = in[((size_t)b * D_ + d0 + ty + j * 8) * Q_ + q0 + tx];
    __syncthreads();
    #pragma unroll
    for (int j = 0; j < 4; j++) {
        float x = tile[tx][ty + j * 8];
        size_t idx = ((size_t)b * Q_ + q0 + ty + j * 8) * D_ + d0 + tx;
        g_tgt[idx] = x;
        __nv_bfloat16 h, l; split1(x, h, l);
        g_tgtH[idx] = h; g_tgtL[idx] = l;
    }
}

// K1b/K1c: split weights fp32 -> bf16 hi/lo
__global__ void __launch_bounds__(256) k_splitW(const float* __restrict__ Wcat) {
    int idx = blockIdx.x * 1024 + threadIdx.x * 4;
    #pragma unroll
    for (int i = 0; i < 4; i++) {
        float x = Wcat[idx + i];
        __nv_bfloat16 h, l; split1(x, h, l);
        g_WcatH[idx + i] = h; g_WcatL[idx + i] = l;
    }
}
__global__ void __launch_bounds__(256) k_splitWc(const float* __restrict__ Wc) {
    int idx = blockIdx.x * 1024 + threadIdx.x * 4;
    #pragma unroll
    for (int i = 0; i < 4; i++) {
        float x = Wc[idx + i];
        __nv_bfloat16 h, l; split1(x, h, l);
        g_WcH[idx + i] = h; g_WcL[idx + i] = l;
    }
}

// K1d: transpose+split contexts [nb][c][l] fp32 -> g_ctxTH/L [nb][l][c] bf16
__global__ void __launch_bounds__(256) k_ctxT(const float* __restrict__ ctx) {
    __shared__ float tile[32][33];
    const int nb = blockIdx.z;
    const int l0 = blockIdx.x * 32;
    const int c0 = blockIdx.y * 32;
    const int tx = threadIdx.x, ty = threadIdx.y;  // 32 x 8
    const float* cp = ctx + (size_t)nb * C_ * L_;
    #pragma unroll
    for (int j = 0; j < 4; j++)
        tile[ty + j * 8][tx] = cp[(size_t)(c0 + ty + j * 8) * L_ + l0 + tx];
    __syncthreads();
    #pragma unroll
    for (int j = 0; j < 4; j++) {
        float x = tile[tx][ty + j * 8];
        size_t idx = ((size_t)nb * L_ + l0 + ty + j * 8) * C_ + c0 + tx;
        __nv_bfloat16 h, l; split1(x, h, l);
        g_ctxTH[idx] = h; g_ctxTL[idx] = l;
    }
}

// ---------------------------------------------------------------------------
// Shared tile constants for the 128x128 mma kernels (swizzled 64B rows, 3 bufs)
// ---------------------------------------------------------------------------
constexpr int PLANE64 = 128 * 64;        // 8192
constexpr int BUF64   = 4 * PLANE64;     // 32768
constexpr int MMA_SMEM = 3 * BUF64;      // 98304 (attn logits 66048 reuses it)
constexpr int LSTRIDE = 129;
constexpr int NCH = 8;                   // K=256 in chunks of 32

// ---------------------------------------------------------------------------
// K2 (mma.sync): src[l,d] = sum_c ctxT[l,c] * Wc[d,c]  (3-term bf16 split)
// tile 128 l (M) x 128 d (N), K = 512 in 16 chunks; 3-buffer single-sync.
// ---------------------------------------------------------------------------
constexpr int SRC_NCH = C_ / 32;  // 16

__global__ void __launch_bounds__(256, 2) k_source_mma() {
    extern __shared__ __align__(16) char smem[];
    const uint32_t sb = smem_u32(smem);
    const int t = threadIdx.x;
    const int lane = t & 31, wid = t >> 5;
    const int qw = (wid & 3) * 32;   // l dir (M)
    const int lw = (wid >> 2) * 64;  // d dir (N)
    const int nb = blockIdx.y;
    const int d0 = blockIdx.x * 128;

    const __nv_bfloat16* aH = g_ctxTH + (size_t)nb * L_ * C_;
    const __nv_bfloat16* aL = g_ctxTL + (size_t)nb * L_ * C_;
    const __nv_bfloat16* bH = g_WcH + (size_t)d0 * C_;
    const __nv_bfloat16* bL = g_WcL + (size_t)d0 * C_;

    auto prefetch = [&](int c) {
        const int kd = c * 32;
        const uint32_t sbase = sb + (c % 3) * BUF64;
        #pragma unroll
        for (int i = 0; i < 8; i++) {
            int idx = t + i * 256;
            int pl = idx >> 9;
            int p2 = idx & 511;
            int row = p2 >> 2, c4 = p2 & 3;
            const __nv_bfloat16* sp =
                (pl == 0) ? aH : (pl == 1) ? aL : (pl == 2) ? bH : bL;
            cp16(sbase + pl * PLANE64 + swz(row, c4),
                 sp + (size_t)row * C_ + kd + c4 * 8);
        }
        CP_COMMIT();
    };

    float acc[16][4] = {};

    prefetch(0); prefetch(1);
    for (int c = 0; c < SRC_NCH; c++) {
        if (c + 1 < SRC_NCH) CP_WAIT(1); else CP_WAIT(0);
        __syncthreads();
        if (c + 2 < SRC_NCH) prefetch(c + 2);
        const uint32_t sbase = sb + (c % 3) * BUF64;
        #pragma unroll
        for (int kh = 0; kh < 2; kh++) {
            uint32_t ah[2][4], al[2][4];
            #pragma unroll
            for (int m = 0; m < 2; m++) {
                uint32_t addr = sbase + swz(qw + m * 16 + (lane & 15),
                                            kh * 2 + (lane >> 4));
                ldsm_x4(ah[m][0], ah[m][1], ah[m][2], ah[m][3], addr);
                ldsm_x4(al[m][0], al[m][1], al[m][2], al[m][3], addr + PLANE64);
            }
            const int nrow = (lane & 7) + ((lane >> 4) << 3);
            const int nc4  = kh * 2 + ((lane >> 3) & 1);
            #pragma unroll
            for (int jj = 0; jj < 4; jj++) {
                uint32_t addr = sbase + 2 * PLANE64 + swz(lw + jj * 16 + nrow, nc4);
                uint32_t bh[4], bl[4];
                ldsm_x4(bh[0], bh[1], bh[2], bh[3], addr);
                ldsm_x4(bl[0], bl[1], bl[2], bl[3], addr + PLANE64);
                mma_group(acc, jj, ah, al, bh, bl);
            }
        }
    }
    #pragma unroll
    for (int m = 0; m < 2; m++)
        #pragma unroll
        for (int j = 0; j < 8; j++) {
            int lr  = qw + m * 16 + (lane >> 2);
            int col = d0 + lw + j * 8 + (lane & 3) * 2;
            float* d = acc[m * 8 + j];
            size_t off0 = ((size_t)nb * L_ + lr) * D_ + col;
            size_t off1 = ((size_t)nb * L_ + lr + 8) * D_ + col;
            st_pair(g_srcH, g_srcL, off0, d[0], d[1]);
            st_pair(g_srcH, g_srcL, off1, d[2], d[3]);
        }
}

// ---------------------------------------------------------------------------
// K3 (mma.sync): logits[128q,128l] = tgt·src^T, softmax, w as bf16 hi/lo.
// 3-buffer single-sync pipeline; 256-thread softmax (2 lanes/row).
// ---------------------------------------------------------------------------
__global__ void __launch_bounds__(256, 2) k_attn_mma() {
    extern __shared__ __align__(16) char smem[];
    float* logits = (float*)smem;
    const uint32_t sb = smem_u32(smem);
    const int t = threadIdx.x;
    const int lane = t & 31, wid = t >> 5;
    const int qw = (wid & 3) * 32;
    const int lw = (wid >> 2) * 64;
    const int nb = blockIdx.y;
    const int n = nb >> 5, b = nb & 31;
    const int q0 = blockIdx.x * 128;

    const __nv_bfloat16* aH = g_tgtH + ((size_t)b * Q_ + q0) * D_;
    const __nv_bfloat16* aL = g_tgtL + ((size_t)b * Q_ + q0) * D_;
    const __nv_bfloat16* bH = g_srcH + (size_t)nb * L_ * D_;
    const __nv_bfloat16* bL = g_srcL + (size_t)nb * L_ * D_;

    auto prefetch = [&](int c) {
        const int kd = c * 32;
        const uint32_t sbase = sb + (c % 3) * BUF64;
        #pragma unroll
        for (int i = 0; i < 8; i++) {
            int idx = t + i * 256;
            int pl = idx >> 9;
            int p2 = idx & 511;
            int row = p2 >> 2, c4 = p2 & 3;
            const __nv_bfloat16* sp =
                (pl == 0) ? aH : (pl == 1) ? aL : (pl == 2) ? bH : bL;
            cp16(sbase + pl * PLANE64 + swz(row, c4),
                 sp + (size_t)row * D_ + kd + c4 * 8);
        }
        CP_COMMIT();
    };

    float acc[16][4] = {};

    prefetch(0); prefetch(1);
    for (int c = 0; c < NCH; c++) {
        if (c + 1 < NCH) CP_WAIT(1); else CP_WAIT(0);
        __syncthreads();
        if (c + 2 < NCH) prefetch(c + 2);
        const uint32_t sbase = sb + (c % 3) * BUF64;
        #pragma unroll
        for (int kh = 0; kh < 2; kh++) {
            uint32_t ah[2][4], al[2][4];
            #pragma unroll
            for (int m = 0; m < 2; m++) {
                uint32_t addr = sbase + swz(qw + m * 16 + (lane & 15),
                                            kh * 2 + (lane >> 4));
                ldsm_x4(ah[m][0], ah[m][1], ah[m][2], ah[m][3], addr);
                ldsm_x4(al[m][0], al[m][1], al[m][2], al[m][3], addr + PLANE64);
            }
            const int nrow = (lane & 7) + ((lane >> 4) << 3);
            const int nc4  = kh * 2 + ((lane >> 3) & 1);
            #pragma unroll
            for (int jj = 0; jj < 4; jj++) {
                uint32_t addr = sbase + 2 * PLANE64 + swz(lw + jj * 16 + nrow, nc4);
                uint32_t bh[4], bl[4];
                ldsm_x4(bh[0], bh[1], bh[2], bh[3], addr);
                ldsm_x4(bl[0], bl[1], bl[2], bl[3], addr + PLANE64);
                mma_group(acc, jj, ah, al, bh, bl);
            }
        }
    }
    __syncthreads();
    #pragma unroll
    for (int m = 0; m < 2; m++)
        #pragma unroll
        for (int j = 0; j < 8; j++) {
            int qr  = qw + m * 16 + (lane >> 2);
            int col = lw + j * 8 + (lane & 3) * 2;
            float* d = acc[m * 8 + j];
            logits[qr * LSTRIDE + col]           = d[0];
            logits[qr * LSTRIDE + col + 1]       = d[1];
            logits[(qr + 8) * LSTRIDE + col]     = d[2];
            logits[(qr + 8) * LSTRIDE + col + 1] = d[3];
        }
    __syncthreads();
    {
        // 2 lanes per row (adjacent lanes -> same warp); each handles 64 cols
        const int row = t >> 1, half = t & 1;
        float* rp = logits + row * LSTRIDE + half * 64;
        float m = rp[0];
        #pragma unroll 8
        for (int j = 1; j < 64; j++) m = fmaxf(m, rp[j]);
        m = fmaxf(m, __shfl_xor_sync(0xffffffffu, m, 1));
        float s = 0.f;
        #pragma unroll 8
        for (int j = 0; j < 64; j++) {
            float ev = __expf(rp[j] - m);
            rp[j] = ev;
            s += ev;
        }
        s += __shfl_xor_sync(0xffffffffu, s, 1);
        float inv = 1.0f / s;
        size_t base = (((size_t)b * Q_ + q0 + row) * N_ + n) * L_ + half * 64;
        #pragma unroll
        for (int j = 0; j < 64; j += 2)
            st_pair(g_wH, g_wL, base + j, rp[j] * inv, rp[j + 1] * inv);
    }
}

// ---------------------------------------------------------------------------
// K4 (mma.sync): S2[e,l] = sum_d Wcat[e, n*D+d] * src[l,d] -> bf16 hi/lo
// 3-buffer single-sync pipeline.
// ---------------------------------------------------------------------------
__global__ void __launch_bounds__(256, 2) k_s2_mma() {
    extern __shared__ __align__(16) char smem[];
    const uint32_t sb = smem_u32(smem);
    const int t = threadIdx.x;
    const int lane = t & 31, wid = t >> 5;
    const int qw = (wid & 3) * 32;   // e dir
    const int lw = (wid >> 2) * 64;  // l dir
    const int nb = blockIdx.y;
    const int n = nb >> 5, b = nb & 31;
    const int e0 = blockIdx.x * 128;

    const __nv_bfloat16* aH = g_WcatH + (size_t)e0 * ND_ + n * D_;
    const __nv_bfloat16* aL = g_WcatL + (size_t)e0 * ND_ + n * D_;
    const __nv_bfloat16* bH = g_srcH + (size_t)nb * L_ * D_;
    const __nv_bfloat16* bL = g_srcL + (size_t)nb * L_ * D_;

    auto prefetch = [&](int c) {
        const int kd = c * 32;
        const uint32_t sbase = sb + (c % 3) * BUF64;
        #pragma unroll
        for (int i = 0; i < 8; i++) {
            int idx = t + i * 256;
            int pl = idx >> 9;
            int p2 = idx & 511;
            int row = p2 >> 2, c4 = p2 & 3;
            const __nv_bfloat16* sp;
            size_t stride;
            if (pl < 2) { sp = pl ? aL : aH; stride = ND_; }
            else        { sp = (pl == 3) ? bL : bH; stride = D_; }
            cp16(sbase + pl * PLANE64 + swz(row, c4),
                 sp + (size_t)row * stride + kd + c4 * 8);
        }
        CP_COMMIT();
    };

    float acc[16][4] = {};

    prefetch(0); prefetch(1);
    for (int c = 0; c < NCH; c++) {
        if (c + 1 < NCH) CP_WAIT(1); else CP_WAIT(0);
        __syncthreads();
        if (c + 2 < NCH) prefetch(c + 2);
        const uint32_t sbase = sb + (c % 3) * BUF64;
        #pragma unroll
        for (int kh = 0; kh < 2; kh++) {
            uint32_t ah[2][4], al[2][4];
            #pragma unroll
            for (int m = 0; m < 2; m++) {
                uint32_t addr = sbase + swz(qw + m * 16 + (lane & 15),
                                            kh * 2 + (lane >> 4));
                ldsm_x4(ah[m][0], ah[m][1], ah[m][2], ah[m][3], addr);
                ldsm_x4(al[m][0], al[m][1], al[m][2], al[m][3], addr + PLANE64);
            }
            const int nrow = (lane & 7) + ((lane >> 4) << 3);
            const int nc4  = kh * 2 + ((lane >> 3) & 1);
            #pragma unroll
            for (int jj = 0; jj < 4; jj++) {
                uint32_t addr = sbase + 2 * PLANE64 + swz(lw + jj * 16 + nrow, nc4);
                uint32_t bh[4], bl[4];
                ldsm_x4(bh[0], bh[1], bh[2], bh[3], addr);
                ldsm_x4(bl[0], bl[1], bl[2], bl[3], addr + PLANE64);
                mma_group(acc, jj, ah, al, bh, bl);
            }
        }
    }
    #pragma unroll
    for (int m = 0; m < 2; m++)
        #pragma unroll
        for (int j = 0; j < 8; j++) {
            int er  = e0 + qw + m * 16 + (lane >> 2);
            int col = lw + j * 8 + (lane & 3) * 2;
            float* d = acc[m * 8 + j];
            size_t off0 = (((size_t)b * D_ + er) * N_ + n) * L_ + col;
            size_t off1 = (((size_t)b * D_ + er + 8) * N_ + n) * L_ + col;
            st_pair(g_s2H, g_s2L, off0, d[0], d[1]);
            st_pair(g_s2H, g_s2L, off1, d[2], d[3]);
        }
}

// ---------------------------------------------------------------------------
// K5 (mma.sync): x[q,e] = sum_k w[q,k]*s2[e,k], K=1280, tile 64q x 256e.
// (unchanged 2-buffer version — 3-buf doesn't fit at 2 CTAs/SM)
// ---------------------------------------------------------------------------
constexpr int O_ROWB = 80;
constexpr int O_APL  = 64 * O_ROWB;    // 5120
constexpr int O_BPL  = 256 * O_ROWB;   // 20480
constexpr int O_BUF  = 2 * O_APL + 2 * O_BPL;  // 51200
constexpr int O_SMEM = 2 * O_BUF;      // 102400
constexpr int O_NCH  = K2_ / 32;       // 40
constexpr int XS     = 260;

__global__ void __launch_bounds__(256, 2) k_out_mma(const float* __restrict__ Wb,
                                                    const float* __restrict__ gamma,
                                                    const float* __restrict__ beta,
                                                    float* __restrict__ out) {
    extern __shared__ __align__(16) char smem[];
    const uint32_t sb = smem_u32(smem);
    const int t = threadIdx.x;
    const int lane = t & 31, wid = t >> 5;
    const int qw = (wid & 1) * 32;   // q dir
    const int ew = (wid >> 1) * 64;  // e dir
    const int b  = blockIdx.y;
    const int q0 = blockIdx.x * 64;

    const __nv_bfloat16* wHp = g_wH + ((size_t)b * Q_ + q0) * K2_;
    const __nv_bfloat16* wLp = g_wL + ((size_t)b * Q_ + q0) * K2_;
    const __nv_bfloat16* sHp = g_s2H + (size_t)b * D_ * K2_;
    const __nv_bfloat16* sLp = g_s2L + (size_t)b * D_ * K2_;

    auto prefetch = [&](int c, int buf) {
        const int k0 = c * 32;
        const uint32_t sbase = sb + buf * O_BUF;
        #pragma unroll
        for (int i = 0; i < 10; i++) {
            int idx = t + i * 256;
            if (idx < 512) {
                int pl = idx >> 8, p = idx & 255, row = p >> 2, c4 = p & 3;
                const __nv_bfloat16* sp = pl ? wLp : wHp;
                cp16(sbase + pl * O_APL + row * O_ROWB + c4 * 16,
                     sp + (size_t)row * K2_ + k0 + c4 * 8);
            } else {
                int idx2 = idx - 512;
                int pl = idx2 >> 10, p = idx2 & 1023, row = p >> 2, c4 = p & 3;
                const __nv_bfloat16* sp = pl ? sLp : sHp;
                cp16(sbase + 2 * O_APL + pl * O_BPL + row * O_ROWB + c4 * 16,
                     sp + (size_t)row * K2_ + k0 + c4 * 8);
            }
        }
        CP_COMMIT();
    };

    float acc[16][4] = {};

    prefetch(0, 0);
    for (int c = 0; c < O_NCH; c++) {
        const int buf = c & 1;
        __syncthreads();
        if (c + 1 < O_NCH) { prefetch(c + 1, buf ^ 1); CP_WAIT(1); }
        else               { CP_WAIT(0); }
        __syncthreads();
        const uint32_t sbase = sb + buf * O_BUF;
        #pragma unroll
        for (int kh = 0; kh < 2; kh++) {
            uint32_t ah[2][4], al[2][4];
            #pragma unroll
            for (int m = 0; m < 2; m++) {
                uint32_t addr = sbase + (qw + m * 16 + (lane & 15)) * O_ROWB
                              + (lane >> 4) * 16 + kh * 32;
                ldsm_x4(ah[m][0], ah[m][1], ah[m][2], ah[m][3], addr);
                ldsm_x4(al[m][0], al[m][1], al[m][2], al[m][3], addr + O_APL);
            }
            const int nrow = (lane & 7) + ((lane >> 4) << 3);
            const int koff = ((lane >> 3) & 1) * 16;
            #pragma unroll
            for (int jj = 0; jj < 4; jj++) {
                uint32_t addr = sbase + 2 * O_APL + (ew + jj * 16 + nrow) * O_ROWB
                              + kh * 32 + koff;
                uint32_t bh[4], bl[4];
                ldsm_x4(bh[0], bh[1], bh[2], bh[3], addr);
                ldsm_x4(bl[0], bl[1], bl[2], bl[3], addr + O_BPL);
                mma_group(acc, jj, ah, al, bh, bl);
            }
        }
    }
    __syncthreads();
    float* sx = (float*)smem;
    #pragma unroll
    for (int m = 0; m < 2; m++)
        #pragma unroll
        for (int j = 0; j < 8; j++) {
            int qr  = qw + m * 16 + (lane >> 2);
            int col = ew + j * 8 + (lane & 3) * 2;
            float* d = acc[m * 8 + j];
            sx[qr * XS + col]           = d[0];
            sx[qr * XS + col + 1]       = d[1];
            sx[(qr + 8) * XS + col]     = d[2];
            sx[(qr + 8) * XS + col + 1] = d[3];
        }
    __syncthreads();
    float wb[8], gm[8], be[8];
    {
        float4 w0 = *(const float4*)&Wb[lane * 4];
        float4 w1 = *(const float4*)&Wb[lane * 4 + 128];
        float4 g0 = *(const float4*)&gamma[lane * 4];
        float4 g1 = *(const float4*)&gamma[lane * 4 + 128];
        float4 e0 = *(const float4*)&beta[lane * 4];
        float4 e1 = *(const float4*)&beta[lane * 4 + 128];
        wb[0]=w0.x; wb[1]=w0.y; wb[2]=w0.z; wb[3]=w0.w; wb[4]=w1.x; wb[5]=w1.y; wb[6]=w1.z; wb[7]=w1.w;
        gm[0]=g0.x; gm[1]=g0.y; gm[2]=g0.z; gm[3]=g0.w; gm[4]=g1.x; gm[5]=g1.y; gm[6]=g1.z; gm[7]=g1.w;
        be[0]=e0.x; be[1]=e0.y; be[2]=e0.z; be[3]=e0.w; be[4]=e1.x; be[5]=e1.y; be[6]=e1.z; be[7]=e1.w;
    }
    const float* tgt = g_tgt + (size_t)b * Q_ * D_;
    #pragma unroll
    for (int i = 0; i < 8; i++) {
        const int r = wid * 8 + i;
        const int q = q0 + r;
        float4 a0 = *(const float4*)&sx[r * XS + lane * 4];
        float4 a1 = *(const float4*)&sx[r * XS + lane * 4 + 128];
        float av[8] = {a0.x, a0.y, a0.z, a0.w, a1.x, a1.y, a1.z, a1.w};
        float4 t0 = *(const float4*)&tgt[(size_t)q * D_ + lane * 4];
        float4 t1 = *(const float4*)&tgt[(size_t)q * D_ + lane * 4 + 128];
        float tv[8] = {t0.x, t0.y, t0.z, t0.w, t1.x, t1.y, t1.z, t1.w};
        float v[8], s = 0.f;
        #pragma unroll
        for (int j = 0; j < 8; j++) {
            v[j] = fmaxf(av[j] + wb[j], 0.f) + tv[j];
            s += v[j];
        }
        s = warpSum32(s);
        const float mu = s * (1.0f / 256.0f);
        float d2 = 0.f;
        #pragma unroll
        for (int j = 0; j < 8; j++) { float dd = v[j] - mu; d2 += dd * dd; }
        d2 = warpSum32(d2);
        const float rs = rsqrtf(d2 * (1.0f / 256.0f));
        float o[8];
        #pragma unroll
        for (int j = 0; j < 8; j++) o[j] = (v[j] - mu) * rs * gm[j] + be[j];
        float* orow = out + (size_t)(b * Q_ + q) * D_;
        *(float4*)&orow[lane * 4]       = make_float4(o[0], o[1], o[2], o[3]);
        *(float4*)&orow[lane * 4 + 128] = make_float4(o[4], o[5], o[6], o[7]);
    }
}

// ---------------------------------------------------------------------------
extern "C" void kernel_launch(void* const* d_in, const int* in_sizes, int n_in,
                              void* d_out, int out_size) {
    const float* input    = (const float*)d_in[0];  // [B, D, 32, 32]
    const float* contexts = (const float*)d_in[1];  // [N, B, C, L]
    const float* Wc       = (const float*)d_in[2];  // [D, C]
    const float* Wcat     = (const float*)d_in[3];  // [D, N*D]
    const float* Wb       = (const float*)d_in[4];  // [D]
    const float* gamma    = (const float*)d_in[5];  // [D]
    const float* beta     = (const float*)d_in[6];  // [D]
    float* out = (float*)d_out;                     // [B, Q, D]

    cudaFuncSetAttribute(k_source_mma, cudaFuncAttributeMaxDynamicSharedMemorySize, MMA_SMEM);
    cudaFuncSetAttribute(k_attn_mma,   cudaFuncAttributeMaxDynamicSharedMemorySize, MMA_SMEM);
    cudaFuncSetAttribute(k_s2_mma,     cudaFuncAttributeMaxDynamicSharedMemorySize, MMA_SMEM);
    cudaFuncSetAttribute(k_out_mma,    cudaFuncAttributeMaxDynamicSharedMemorySize, O_SMEM);

    k_transpose <<<dim3(Q_ / 32, D_ / 32, B_), dim3(32, 8)>>>(input);
    k_splitW    <<<D_ * ND_ / 1024, 256>>>(Wcat);
    k_splitWc   <<<D_ * C_ / 1024, 256>>>(Wc);
    k_ctxT      <<<dim3(L_ / 32, C_ / 32, N_ * B_), dim3(32, 8)>>>(contexts);
    k_source_mma<<<dim3(2,        N_ * B_),    256, MMA_SMEM>>>();
    k_attn_mma  <<<dim3(Q_ / 128, N_ * B_),    256, MMA_SMEM>>>();
    k_s2_mma    <<<dim3(2,        N_ * B_),    256, MMA_SMEM>>>();
    k_out_mma   <<<dim3(Q_ / 64,  B_),         256, O_SMEM>>>(Wb, gamma, beta, out);
}

// round 12
// speedup vs baseline: 3.1428x; 1.0614x over previous
#include <cuda_runtime.h>
#include <cuda_bf16.h>
#include <cstdint>

// Problem dims (fixed by the reference)
constexpr int B_  = 32;
constexpr int D_  = 256;   // idf
constexpr int Q_  = 1024;  // ih*iw
constexpr int C_  = 512;   // cdf
constexpr int L_  = 128;
constexpr int N_  = 10;    // contexts
constexpr int K2_ = N_ * L_;  // 1280
constexpr int ND_ = N_ * D_;  // 2560

// Scratch (static device globals — no allocation in kernel_launch)
__device__ float g_tgt[(size_t)B_ * Q_ * D_];          //  [b][q][d] fp32 (residual)
// bf16 split pairs (tensor-core operands)
__device__ __align__(16) __nv_bfloat16 g_tgtH[(size_t)B_ * Q_ * D_];
__device__ __align__(16) __nv_bfloat16 g_tgtL[(size_t)B_ * Q_ * D_];
__device__ __align__(16) __nv_bfloat16 g_srcH[(size_t)N_ * B_ * L_ * D_];
__device__ __align__(16) __nv_bfloat16 g_srcL[(size_t)N_ * B_ * L_ * D_];
__device__ __align__(16) __nv_bfloat16 g_wH [(size_t)B_ * Q_ * N_ * L_];
__device__ __align__(16) __nv_bfloat16 g_wL [(size_t)B_ * Q_ * N_ * L_];
__device__ __align__(16) __nv_bfloat16 g_s2H[(size_t)B_ * D_ * N_ * L_];
__device__ __align__(16) __nv_bfloat16 g_s2L[(size_t)B_ * D_ * N_ * L_];
__device__ __align__(16) __nv_bfloat16 g_WcatH[(size_t)D_ * ND_];
__device__ __align__(16) __nv_bfloat16 g_WcatL[(size_t)D_ * ND_];
__device__ __align__(16) __nv_bfloat16 g_WcH[(size_t)D_ * C_];
__device__ __align__(16) __nv_bfloat16 g_WcL[(size_t)D_ * C_];
__device__ __align__(16) __nv_bfloat16 g_ctxTH[(size_t)N_ * B_ * L_ * C_];
__device__ __align__(16) __nv_bfloat16 g_ctxTL[(size_t)N_ * B_ * L_ * C_];

typedef unsigned long long u64;

__device__ __forceinline__ float warpSum32(float v) {
    #pragma unroll
    for (int o = 16; o; o >>= 1) v += __shfl_xor_sync(0xffffffffu, v, o);
    return v;
}

// ---- bf16 split helpers ----
__device__ __forceinline__ void split1(float x, __nv_bfloat16& h, __nv_bfloat16& l) {
    h = __float2bfloat16(x);
    l = __float2bfloat16(x - __bfloat162float(h));
}
__device__ __forceinline__ void st_pair(__nv_bfloat16* H, __nv_bfloat16* L,
                                        size_t off, float x0, float x1) {
    __nv_bfloat16 h0, l0, h1, l1;
    split1(x0, h0, l0); split1(x1, h1, l1);
    uint32_t hu = (uint32_t)__bfloat16_as_ushort(h0) |
                  ((uint32_t)__bfloat16_as_ushort(h1) << 16);
    uint32_t lu = (uint32_t)__bfloat16_as_ushort(l0) |
                  ((uint32_t)__bfloat16_as_ushort(l1) << 16);
    *(uint32_t*)&H[off] = hu;
    *(uint32_t*)&L[off] = lu;
}

// ---- warp-level tensor core helpers (sm_80 baseline; no 'a' features) ----
__device__ __forceinline__ uint32_t smem_u32(const void* p) {
    uint32_t a;
    asm("{ .reg .u64 t; cvta.to.shared.u64 t, %1; cvt.u32.u64 %0, t; }" : "=r"(a) : "l"(p));
    return a;
}
__device__ __forceinline__ void ldsm_x4(uint32_t& r0, uint32_t& r1, uint32_t& r2,
                                        uint32_t& r3, uint32_t a) {
    asm volatile("ldmatrix.sync.aligned.m8n8.x4.shared.b16 {%0,%1,%2,%3}, [%4];"
                 : "=r"(r0), "=r"(r1), "=r"(r2), "=r"(r3) : "r"(a));
}
__device__ __forceinline__ void mma_bf16(float* d, const uint32_t* a, const uint32_t* b) {
    asm volatile("mma.sync.aligned.m16n8k16.row.col.f32.bf16.bf16.f32 "
        "{%0,%1,%2,%3}, {%4,%5,%6,%7}, {%8,%9}, {%0,%1,%2,%3};"
        : "+f"(d[0]), "+f"(d[1]), "+f"(d[2]), "+f"(d[3])
        : "r"(a[0]), "r"(a[1]), "r"(a[2]), "r"(a[3]), "r"(b[0]), "r"(b[1]));
}
__device__ __forceinline__ void cp16(uint32_t saddr, const void* gaddr) {
    asm volatile("cp.async.cg.shared.global [%0], [%1], 16;"
                 :: "r"(saddr), "l"(gaddr) : "memory");
}
#define CP_COMMIT() asm volatile("cp.async.commit_group;" ::: "memory")
#define CP_WAIT(n)  asm volatile("cp.async.wait_group %0;" :: "n"(n) : "memory")

// XOR-swizzled 64B-row tile offset: row-major, 4 16B chunks per row,
// conflict-free for ldmatrix 8-row groups and for the cp.async write pattern.
__device__ __forceinline__ uint32_t swz(int row, int c4) {
    return (uint32_t)(row * 64 + ((c4 ^ ((row >> 1) & 3)) << 4));
}

// 3-term split MMA for one jj-group, term-outer ordering
__device__ __forceinline__ void mma_group(float (*acc)[4], int jj,
                                          uint32_t (&ah)[2][4], uint32_t (&al)[2][4],
                                          const uint32_t* bh, const uint32_t* bl) {
    #pragma unroll
    for (int m = 0; m < 2; m++)
        #pragma unroll
        for (int jb = 0; jb < 2; jb++)
            mma_bf16(acc[m * 8 + jj * 2 + jb], ah[m], bh + jb * 2);
    #pragma unroll
    for (int m = 0; m < 2; m++)
        #pragma unroll
        for (int jb = 0; jb < 2; jb++)
            mma_bf16(acc[m * 8 + jj * 2 + jb], ah[m], bl + jb * 2);
    #pragma unroll
    for (int m = 0; m < 2; m++)
        #pragma unroll
        for (int jb = 0; jb < 2; jb++)
            mma_bf16(acc[m * 8 + jj * 2 + jb], al[m], bh + jb * 2);
}

// ---------------------------------------------------------------------------
// K1: transpose input [B][D][Q] -> g_tgt fp32 + g_tgtH/L bf16 split, [B][Q][D]
// ---------------------------------------------------------------------------
__global__ void __launch_bounds__(256) k_transpose(const float* __restrict__ in) {
    __shared__ float tile[32][33];
    const int b  = blockIdx.z;
    const int q0 = blockIdx.x * 32;
    const int d0 = blockIdx.y * 32;
    const int tx = threadIdx.x, ty = threadIdx.y;  // 32 x 8
    #pragma unroll
    for (int j = 0; j < 4; j++)
        tile[ty + j * 8][tx] = in[((size_t)b * D_ + d0 + ty + j * 8) * Q_ + q0 + tx];
    __syncthreads();
    #pragma unroll
    for (int j = 0; j < 4; j++) {
        float x = tile[tx][ty + j * 8];
        size_t idx = ((size_t)b * Q_ + q0 + ty + j * 8) * D_ + d0 + tx;
        g_tgt[idx] = x;
        __nv_bfloat16 h, l; split1(x, h, l);
        g_tgtH[idx] = h; g_tgtL[idx] = l;
    }
}

// K1b/K1c: split weights fp32 -> bf16 hi/lo
__global__ void __launch_bounds__(256) k_splitW(const float* __restrict__ Wcat) {
    int idx = blockIdx.x * 1024 + threadIdx.x * 4;
    #pragma unroll
    for (int i = 0; i < 4; i++) {
        float x = Wcat[idx + i];
        __nv_bfloat16 h, l; split1(x, h, l);
        g_WcatH[idx + i] = h; g_WcatL[idx + i] = l;
    }
}
__global__ void __launch_bounds__(256) k_splitWc(const float* __restrict__ Wc) {
    int idx = blockIdx.x * 1024 + threadIdx.x * 4;
    #pragma unroll
    for (int i = 0; i < 4; i++) {
        float x = Wc[idx + i];
        __nv_bfloat16 h, l; split1(x, h, l);
        g_WcH[idx + i] = h; g_WcL[idx + i] = l;
    }
}

// K1d: transpose+split contexts [nb][c][l] fp32 -> g_ctxTH/L [nb][l][c] bf16
__global__ void __launch_bounds__(256) k_ctxT(const float* __restrict__ ctx) {
    __shared__ float tile[32][33];
    const int nb = blockIdx.z;
    const int l0 = blockIdx.x * 32;
    const int c0 = blockIdx.y * 32;
    const int tx = threadIdx.x, ty = threadIdx.y;  // 32 x 8
    const float* cp = ctx + (size_t)nb * C_ * L_;
    #pragma unroll
    for (int j = 0; j < 4; j++)
        tile[ty + j * 8][tx] = cp[(size_t)(c0 + ty + j * 8) * L_ + l0 + tx];
    __syncthreads();
    #pragma unroll
    for (int j = 0; j < 4; j++) {
        float x = tile[tx][ty + j * 8];
        size_t idx = ((size_t)nb * L_ + l0 + ty + j * 8) * C_ + c0 + tx;
        __nv_bfloat16 h, l; split1(x, h, l);
        g_ctxTH[idx] = h; g_ctxTL[idx] = l;
    }
}

// ---------------------------------------------------------------------------
// Shared tile constants for the 128x128 mma kernels (swizzled 64B rows, 3 bufs)
// ---------------------------------------------------------------------------
constexpr int PLANE64 = 128 * 64;        // 8192
constexpr int BUF64   = 4 * PLANE64;     // 32768
constexpr int MMA_SMEM = 3 * BUF64;      // 98304 (attn logits 66048 reuses it)
constexpr int LSTRIDE = 129;
constexpr int NCH = 8;                   // K=256 in chunks of 32

// ---------------------------------------------------------------------------
// K2 (mma.sync): src[l,d] = sum_c ctxT[l,c] * Wc[d,c]  (3-term bf16 split)
// tile 128 l (M) x 128 d (N), K = 512 in 16 chunks; 3-buffer single-sync.
// ---------------------------------------------------------------------------
constexpr int SRC_NCH = C_ / 32;  // 16

__global__ void __launch_bounds__(256, 2) k_source_mma() {
    extern __shared__ __align__(16) char smem[];
    const uint32_t sb = smem_u32(smem);
    const int t = threadIdx.x;
    const int lane = t & 31, wid = t >> 5;
    const int qw = (wid & 3) * 32;   // l dir (M)
    const int lw = (wid >> 2) * 64;  // d dir (N)
    const int nb = blockIdx.y;
    const int d0 = blockIdx.x * 128;

    const __nv_bfloat16* aH = g_ctxTH + (size_t)nb * L_ * C_;
    const __nv_bfloat16* aL = g_ctxTL + (size_t)nb * L_ * C_;
    const __nv_bfloat16* bH = g_WcH + (size_t)d0 * C_;
    const __nv_bfloat16* bL = g_WcL + (size_t)d0 * C_;

    auto prefetch = [&](int c) {
        const int kd = c * 32;
        const uint32_t sbase = sb + (c % 3) * BUF64;
        #pragma unroll
        for (int i = 0; i < 8; i++) {
            int idx = t + i * 256;
            int pl = idx >> 9;
            int p2 = idx & 511;
            int row = p2 >> 2, c4 = p2 & 3;
            const __nv_bfloat16* sp =
                (pl == 0) ? aH : (pl == 1) ? aL : (pl == 2) ? bH : bL;
            cp16(sbase + pl * PLANE64 + swz(row, c4),
                 sp + (size_t)row * C_ + kd + c4 * 8);
        }
        CP_COMMIT();
    };

    float acc[16][4] = {};

    prefetch(0); prefetch(1);
    for (int c = 0; c < SRC_NCH; c++) {
        if (c + 1 < SRC_NCH) CP_WAIT(1); else CP_WAIT(0);
        __syncthreads();
        if (c + 2 < SRC_NCH) prefetch(c + 2);
        const uint32_t sbase = sb + (c % 3) * BUF64;
        #pragma unroll
        for (int kh = 0; kh < 2; kh++) {
            uint32_t ah[2][4], al[2][4];
            #pragma unroll
            for (int m = 0; m < 2; m++) {
                uint32_t addr = sbase + swz(qw + m * 16 + (lane & 15),
                                            kh * 2 + (lane >> 4));
                ldsm_x4(ah[m][0], ah[m][1], ah[m][2], ah[m][3], addr);
                ldsm_x4(al[m][0], al[m][1], al[m][2], al[m][3], addr + PLANE64);
            }
            const int nrow = (lane & 7) + ((lane >> 4) << 3);
            const int nc4  = kh * 2 + ((lane >> 3) & 1);
            #pragma unroll
            for (int jj = 0; jj < 4; jj++) {
                uint32_t addr = sbase + 2 * PLANE64 + swz(lw + jj * 16 + nrow, nc4);
                uint32_t bh[4], bl[4];
                ldsm_x4(bh[0], bh[1], bh[2], bh[3], addr);
                ldsm_x4(bl[0], bl[1], bl[2], bl[3], addr + PLANE64);
                mma_group(acc, jj, ah, al, bh, bl);
            }
        }
    }
    #pragma unroll
    for (int m = 0; m < 2; m++)
        #pragma unroll
        for (int j = 0; j < 8; j++) {
            int lr  = qw + m * 16 + (lane >> 2);
            int col = d0 + lw + j * 8 + (lane & 3) * 2;
            float* d = acc[m * 8 + j];
            size_t off0 = ((size_t)nb * L_ + lr) * D_ + col;
            size_t off1 = ((size_t)nb * L_ + lr + 8) * D_ + col;
            st_pair(g_srcH, g_srcL, off0, d[0], d[1]);
            st_pair(g_srcH, g_srcL, off1, d[2], d[3]);
        }
}

// ---------------------------------------------------------------------------
// K3 (mma.sync): logits[128q,128l] = tgt·src^T, softmax, w as bf16 hi/lo.
// 3-buffer single-sync pipeline; 256-thread softmax (2 lanes/row).
// ---------------------------------------------------------------------------
__global__ void __launch_bounds__(256, 2) k_attn_mma() {
    extern __shared__ __align__(16) char smem[];
    float* logits = (float*)smem;
    const uint32_t sb = smem_u32(smem);
    const int t = threadIdx.x;
    const int lane = t & 31, wid = t >> 5;
    const int qw = (wid & 3) * 32;
    const int lw = (wid >> 2) * 64;
    const int nb = blockIdx.y;
    const int n = nb >> 5, b = nb & 31;
    const int q0 = blockIdx.x * 128;

    const __nv_bfloat16* aH = g_tgtH + ((size_t)b * Q_ + q0) * D_;
    const __nv_bfloat16* aL = g_tgtL + ((size_t)b * Q_ + q0) * D_;
    const __nv_bfloat16* bH = g_srcH + (size_t)nb * L_ * D_;
    const __nv_bfloat16* bL = g_srcL + (size_t)nb * L_ * D_;

    auto prefetch = [&](int c) {
        const int kd = c * 32;
        const uint32_t sbase = sb + (c % 3) * BUF64;
        #pragma unroll
        for (int i = 0; i < 8; i++) {
            int idx = t + i * 256;
            int pl = idx >> 9;
            int p2 = idx & 511;
            int row = p2 >> 2, c4 = p2 & 3;
            const __nv_bfloat16* sp =
                (pl == 0) ? aH : (pl == 1) ? aL : (pl == 2) ? bH : bL;
            cp16(sbase + pl * PLANE64 + swz(row, c4),
                 sp + (size_t)row * D_ + kd + c4 * 8);
        }
        CP_COMMIT();
    };

    float acc[16][4] = {};

    prefetch(0); prefetch(1);
    for (int c = 0; c < NCH; c++) {
        if (c + 1 < NCH) CP_WAIT(1); else CP_WAIT(0);
        __syncthreads();
        if (c + 2 < NCH) prefetch(c + 2);
        const uint32_t sbase = sb + (c % 3) * BUF64;
        #pragma unroll
        for (int kh = 0; kh < 2; kh++) {
            uint32_t ah[2][4], al[2][4];
            #pragma unroll
            for (int m = 0; m < 2; m++) {
                uint32_t addr = sbase + swz(qw + m * 16 + (lane & 15),
                                            kh * 2 + (lane >> 4));
                ldsm_x4(ah[m][0], ah[m][1], ah[m][2], ah[m][3], addr);
                ldsm_x4(al[m][0], al[m][1], al[m][2], al[m][3], addr + PLANE64);
            }
            const int nrow = (lane & 7) + ((lane >> 4) << 3);
            const int nc4  = kh * 2 + ((lane >> 3) & 1);
            #pragma unroll
            for (int jj = 0; jj < 4; jj++) {
                uint32_t addr = sbase + 2 * PLANE64 + swz(lw + jj * 16 + nrow, nc4);
                uint32_t bh[4], bl[4];
                ldsm_x4(bh[0], bh[1], bh[2], bh[3], addr);
                ldsm_x4(bl[0], bl[1], bl[2], bl[3], addr + PLANE64);
                mma_group(acc, jj, ah, al, bh, bl);
            }
        }
    }
    __syncthreads();
    #pragma unroll
    for (int m = 0; m < 2; m++)
        #pragma unroll
        for (int j = 0; j < 8; j++) {
            int qr  = qw + m * 16 + (lane >> 2);
            int col = lw + j * 8 + (lane & 3) * 2;
            float* d = acc[m * 8 + j];
            logits[qr * LSTRIDE + col]           = d[0];
            logits[qr * LSTRIDE + col + 1]       = d[1];
            logits[(qr + 8) * LSTRIDE + col]     = d[2];
            logits[(qr + 8) * LSTRIDE + col + 1] = d[3];
        }
    __syncthreads();
    {
        // 2 lanes per row (adjacent lanes -> same warp); each handles 64 cols
        const int row = t >> 1, half = t & 1;
        float* rp = logits + row * LSTRIDE + half * 64;
        float m = rp[0];
        #pragma unroll 8
        for (int j = 1; j < 64; j++) m = fmaxf(m, rp[j]);
        m = fmaxf(m, __shfl_xor_sync(0xffffffffu, m, 1));
        float s = 0.f;
        #pragma unroll 8
        for (int j = 0; j < 64; j++) {
            float ev = __expf(rp[j] - m);
            rp[j] = ev;
            s += ev;
        }
        s += __shfl_xor_sync(0xffffffffu, s, 1);
        float inv = 1.0f / s;
        size_t base = (((size_t)b * Q_ + q0 + row) * N_ + n) * L_ + half * 64;
        #pragma unroll
        for (int j = 0; j < 64; j += 2)
            st_pair(g_wH, g_wL, base + j, rp[j] * inv, rp[j + 1] * inv);
    }
}

// ---------------------------------------------------------------------------
// K4 (mma.sync): S2[e,l] = sum_d Wcat[e, n*D+d] * src[l,d] -> bf16 hi/lo
// 3-buffer single-sync pipeline.
// ---------------------------------------------------------------------------
__global__ void __launch_bounds__(256, 2) k_s2_mma() {
    extern __shared__ __align__(16) char smem[];
    const uint32_t sb = smem_u32(smem);
    const int t = threadIdx.x;
    const int lane = t & 31, wid = t >> 5;
    const int qw = (wid & 3) * 32;   // e dir
    const int lw = (wid >> 2) * 64;  // l dir
    const int nb = blockIdx.y;
    const int n = nb >> 5, b = nb & 31;
    const int e0 = blockIdx.x * 128;

    const __nv_bfloat16* aH = g_WcatH + (size_t)e0 * ND_ + n * D_;
    const __nv_bfloat16* aL = g_WcatL + (size_t)e0 * ND_ + n * D_;
    const __nv_bfloat16* bH = g_srcH + (size_t)nb * L_ * D_;
    const __nv_bfloat16* bL = g_srcL + (size_t)nb * L_ * D_;

    auto prefetch = [&](int c) {
        const int kd = c * 32;
        const uint32_t sbase = sb + (c % 3) * BUF64;
        #pragma unroll
        for (int i = 0; i < 8; i++) {
            int idx = t + i * 256;
            int pl = idx >> 9;
            int p2 = idx & 511;
            int row = p2 >> 2, c4 = p2 & 3;
            const __nv_bfloat16* sp;
            size_t stride;
            if (pl < 2) { sp = pl ? aL : aH; stride = ND_; }
            else        { sp = (pl == 3) ? bL : bH; stride = D_; }
            cp16(sbase + pl * PLANE64 + swz(row, c4),
                 sp + (size_t)row * stride + kd + c4 * 8);
        }
        CP_COMMIT();
    };

    float acc[16][4] = {};

    prefetch(0); prefetch(1);
    for (int c = 0; c < NCH; c++) {
        if (c + 1 < NCH) CP_WAIT(1); else CP_WAIT(0);
        __syncthreads();
        if (c + 2 < NCH) prefetch(c + 2);
        const uint32_t sbase = sb + (c % 3) * BUF64;
        #pragma unroll
        for (int kh = 0; kh < 2; kh++) {
            uint32_t ah[2][4], al[2][4];
            #pragma unroll
            for (int m = 0; m < 2; m++) {
                uint32_t addr = sbase + swz(qw + m * 16 + (lane & 15),
                                            kh * 2 + (lane >> 4));
                ldsm_x4(ah[m][0], ah[m][1], ah[m][2], ah[m][3], addr);
                ldsm_x4(al[m][0], al[m][1], al[m][2], al[m][3], addr + PLANE64);
            }
            const int nrow = (lane & 7) + ((lane >> 4) << 3);
            const int nc4  = kh * 2 + ((lane >> 3) & 1);
            #pragma unroll
            for (int jj = 0; jj < 4; jj++) {
                uint32_t addr = sbase + 2 * PLANE64 + swz(lw + jj * 16 + nrow, nc4);
                uint32_t bh[4], bl[4];
                ldsm_x4(bh[0], bh[1], bh[2], bh[3], addr);
                ldsm_x4(bl[0], bl[1], bl[2], bl[3], addr + PLANE64);
                mma_group(acc, jj, ah, al, bh, bl);
            }
        }
    }
    #pragma unroll
    for (int m = 0; m < 2; m++)
        #pragma unroll
        for (int j = 0; j < 8; j++) {
            int er  = e0 + qw + m * 16 + (lane >> 2);
            int col = lw + j * 8 + (lane & 3) * 2;
            float* d = acc[m * 8 + j];
            size_t off0 = (((size_t)b * D_ + er) * N_ + n) * L_ + col;
            size_t off1 = (((size_t)b * D_ + er + 8) * N_ + n) * L_ + col;
            st_pair(g_s2H, g_s2L, off0, d[0], d[1]);
            st_pair(g_s2H, g_s2L, off1, d[2], d[3]);
        }
}

// ---------------------------------------------------------------------------
// K5 (mma.sync): x[q,e] = sum_k w[q,k]*s2[e,k], K=1280, tile 64q x 256e.
// Swizzled 64B rows, 2-buffer SINGLE-sync pipeline (loop-top sync proves
// compute(c-1) done everywhere, so prefetch(c+1) may reuse its buffer).
// Epilogue: stage x to smem, then bias+relu+residual+LayerNorm -> out.
// ---------------------------------------------------------------------------
constexpr int O_APL  = 64 * 64;        // 4096  (A plane: 64 q rows x 64B)
constexpr int O_BPL  = 256 * 64;       // 16384 (B plane: 256 e rows x 64B)
constexpr int O_BUF  = 2 * O_APL + 2 * O_BPL;  // 40960
constexpr int O_SMEM = 2 * O_BUF;      // 81920 (x-staging 66560 reuses it)
constexpr int O_NCH  = K2_ / 32;       // 40
constexpr int XS     = 260;            // x staging row stride (floats)

__global__ void __launch_bounds__(256, 2) k_out_mma(const float* __restrict__ Wb,
                                                    const float* __restrict__ gamma,
                                                    const float* __restrict__ beta,
                                                    float* __restrict__ out) {
    extern __shared__ __align__(16) char smem[];
    const uint32_t sb = smem_u32(smem);
    const int t = threadIdx.x;
    const int lane = t & 31, wid = t >> 5;
    const int qw = (wid & 1) * 32;   // q dir
    const int ew = (wid >> 1) * 64;  // e dir
    const int b  = blockIdx.y;
    const int q0 = blockIdx.x * 64;

    const __nv_bfloat16* wHp = g_wH + ((size_t)b * Q_ + q0) * K2_;
    const __nv_bfloat16* wLp = g_wL + ((size_t)b * Q_ + q0) * K2_;
    const __nv_bfloat16* sHp = g_s2H + (size_t)b * D_ * K2_;
    const __nv_bfloat16* sLp = g_s2L + (size_t)b * D_ * K2_;

    auto prefetch = [&](int c) {
        const int k0 = c * 32;
        const uint32_t sbase = sb + (c & 1) * O_BUF;
        #pragma unroll
        for (int i = 0; i < 10; i++) {
            int idx = t + i * 256;
            if (idx < 512) {       // A planes: 2 x 64 rows x 4 c4
                int pl = idx >> 8, p = idx & 255, row = p >> 2, c4 = p & 3;
                const __nv_bfloat16* sp = pl ? wLp : wHp;
                cp16(sbase + pl * O_APL + swz(row, c4),
                     sp + (size_t)row * K2_ + k0 + c4 * 8);
            } else {               // B planes: 2 x 256 rows x 4 c4
                int idx2 = idx - 512;
                int pl = idx2 >> 10, p = idx2 & 1023, row = p >> 2, c4 = p & 3;
                const __nv_bfloat16* sp = pl ? sLp : sHp;
                cp16(sbase + 2 * O_APL + pl * O_BPL + swz(row, c4),
                     sp + (size_t)row * K2_ + k0 + c4 * 8);
            }
        }
        CP_COMMIT();
    };

    float acc[16][4] = {};

    prefetch(0);
    for (int c = 0; c < O_NCH; c++) {
        CP_WAIT(0);          // chunk c data arrived
        __syncthreads();     // all warps done with compute(c-1) -> its buffer free
        if (c + 1 < O_NCH) prefetch(c + 1);
        const uint32_t sbase = sb + (c & 1) * O_BUF;
        #pragma unroll
        for (int kh = 0; kh < 2; kh++) {
            uint32_t ah[2][4], al[2][4];
            #pragma unroll
            for (int m = 0; m < 2; m++) {
                uint32_t addr = sbase + swz(qw + m * 16 + (lane & 15),
                                            kh * 2 + (lane >> 4));
                ldsm_x4(ah[m][0], ah[m][1], ah[m][2], ah[m][3], addr);
                ldsm_x4(al[m][0], al[m][1], al[m][2], al[m][3], addr + O_APL);
            }
            const int nrow = (lane & 7) + ((lane >> 4) << 3);
            const int nc4  = kh * 2 + ((lane >> 3) & 1);
            #pragma unroll
            for (int jj = 0; jj < 4; jj++) {
                uint32_t addr = sbase + 2 * O_APL + swz(ew + jj * 16 + nrow, nc4);
                uint32_t bh[4], bl[4];
                ldsm_x4(bh[0], bh[1], bh[2], bh[3], addr);
                ldsm_x4(bl[0], bl[1], bl[2], bl[3], addr + O_BPL);
                mma_group(acc, jj, ah, al, bh, bl);
            }
        }
    }
    __syncthreads();   // all tile reads done; safe to overwrite with staging
    float* sx = (float*)smem;
    #pragma unroll
    for (int m = 0; m < 2; m++)
        #pragma unroll
        for (int j = 0; j < 8; j++) {
            int qr  = qw + m * 16 + (lane >> 2);
            int col = ew + j * 8 + (lane & 3) * 2;
            float* d = acc[m * 8 + j];
            sx[qr * XS + col]           = d[0];
            sx[qr * XS + col + 1]       = d[1];
            sx[(qr + 8) * XS + col]     = d[2];
            sx[(qr + 8) * XS + col + 1] = d[3];
        }
    __syncthreads();
    float wb[8], gm[8], be[8];
    {
        float4 w0 = *(const float4*)&Wb[lane * 4];
        float4 w1 = *(const float4*)&Wb[lane * 4 + 128];
        float4 g0 = *(const float4*)&gamma[lane * 4];
        float4 g1 = *(const float4*)&gamma[lane * 4 + 128];
        float4 e0 = *(const float4*)&beta[lane * 4];
        float4 e1 = *(const float4*)&beta[lane * 4 + 128];
        wb[0]=w0.x; wb[1]=w0.y; wb[2]=w0.z; wb[3]=w0.w; wb[4]=w1.x; wb[5]=w1.y; wb[6]=w1.z; wb[7]=w1.w;
        gm[0]=g0.x; gm[1]=g0.y; gm[2]=g0.z; gm[3]=g0.w; gm[4]=g1.x; gm[5]=g1.y; gm[6]=g1.z; gm[7]=g1.w;
        be[0]=e0.x; be[1]=e0.y; be[2]=e0.z; be[3]=e0.w; be[4]=e1.x; be[5]=e1.y; be[6]=e1.z; be[7]=e1.w;
    }
    const float* tgt = g_tgt + (size_t)b * Q_ * D_;
    #pragma unroll
    for (int i = 0; i < 8; i++) {
        const int r = wid * 8 + i;
        const int q = q0 + r;
        float4 a0 = *(const float4*)&sx[r * XS + lane * 4];
        float4 a1 = *(const float4*)&sx[r * XS + lane * 4 + 128];
        float av[8] = {a0.x, a0.y, a0.z, a0.w, a1.x, a1.y, a1.z, a1.w};
        float4 t0 = *(const float4*)&tgt[(size_t)q * D_ + lane * 4];
        float4 t1 = *(const float4*)&tgt[(size_t)q * D_ + lane * 4 + 128];
        float tv[8] = {t0.x, t0.y, t0.z, t0.w, t1.x, t1.y, t1.z, t1.w};
        float v[8], s = 0.f;
        #pragma unroll
        for (int j = 0; j < 8; j++) {
            v[j] = fmaxf(av[j] + wb[j], 0.f) + tv[j];
            s += v[j];
        }
        s = warpSum32(s);
        const float mu = s * (1.0f / 256.0f);
        float d2 = 0.f;
        #pragma unroll
        for (int j = 0; j < 8; j++) { float dd = v[j] - mu; d2 += dd * dd; }
        d2 = warpSum32(d2);
        const float rs = rsqrtf(d2 * (1.0f / 256.0f));
        float o[8];
        #pragma unroll
        for (int j = 0; j < 8; j++) o[j] = (v[j] - mu) * rs * gm[j] + be[j];
        float* orow = out + (size_t)(b * Q_ + q) * D_;
        *(float4*)&orow[lane * 4]       = make_float4(o[0], o[1], o[2], o[3]);
        *(float4*)&orow[lane * 4 + 128] = make_float4(o[4], o[5], o[6], o[7]);
    }
}

// ---------------------------------------------------------------------------
extern "C" void kernel_launch(void* const* d_in, const int* in_sizes, int n_in,
                              void* d_out, int out_size) {
    const float* input    = (const float*)d_in[0];  // [B, D, 32, 32]
    const float* contexts = (const float*)d_in[1];  // [N, B, C, L]
    const float* Wc       = (const float*)d_in[2];  // [D, C]
    const float* Wcat     = (const float*)d_in[3];  // [D, N*D]
    const float* Wb       = (const float*)d_in[4];  // [D]
    const float* gamma    = (const float*)d_in[5];  // [D]
    const float* beta     = (const float*)d_in[6];  // [D]
    float* out = (float*)d_out;                     // [B, Q, D]

    cudaFuncSetAttribute(k_source_mma, cudaFuncAttributeMaxDynamicSharedMemorySize, MMA_SMEM);
    cudaFuncSetAttribute(k_attn_mma,   cudaFuncAttributeMaxDynamicSharedMemorySize, MMA_SMEM);
    cudaFuncSetAttribute(k_s2_mma,     cudaFuncAttributeMaxDynamicSharedMemorySize, MMA_SMEM);
    cudaFuncSetAttribute(k_out_mma,    cudaFuncAttributeMaxDynamicSharedMemorySize, O_SMEM);

    k_transpose <<<dim3(Q_ / 32, D_ / 32, B_), dim3(32, 8)>>>(input);
    k_splitW    <<<D_ * ND_ / 1024, 256>>>(Wcat);
    k_splitWc   <<<D_ * C_ / 1024, 256>>>(Wc);
    k_ctxT      <<<dim3(L_ / 32, C_ / 32, N_ * B_), dim3(32, 8)>>>(contexts);
    k_source_mma<<<dim3(2,        N_ * B_),    256, MMA_SMEM>>>();
    k_attn_mma  <<<dim3(Q_ / 128, N_ * B_),    256, MMA_SMEM>>>();
    k_s2_mma    <<<dim3(2,        N_ * B_),    256, MMA_SMEM>>>();
    k_out_mma   <<<dim3(Q_ / 64,  B_),         256, O_SMEM>>>(Wb, gamma, beta, out);
}

// round 13
// speedup vs baseline: 3.3511x; 1.0663x over previous
#include <cuda_runtime.h>
#include <cuda_bf16.h>
#include <cstdint>

// Problem dims (fixed by the reference)
constexpr int B_  = 32;
constexpr int D_  = 256;   // idf
constexpr int Q_  = 1024;  // ih*iw
constexpr int C_  = 512;   // cdf
constexpr int L_  = 128;
constexpr int N_  = 10;    // contexts
constexpr int K2_ = N_ * L_;  // 1280
constexpr int ND_ = N_ * D_;  // 2560

// Scratch (static device globals — no allocation in kernel_launch)
// bf16 split pairs (tensor-core operands)
__device__ __align__(16) __nv_bfloat16 g_tgtH[(size_t)B_ * Q_ * D_];
__device__ __align__(16) __nv_bfloat16 g_tgtL[(size_t)B_ * Q_ * D_];
__device__ __align__(16) __nv_bfloat16 g_srcH[(size_t)N_ * B_ * L_ * D_];
__device__ __align__(16) __nv_bfloat16 g_srcL[(size_t)N_ * B_ * L_ * D_];
__device__ __align__(16) __nv_bfloat16 g_wH [(size_t)B_ * Q_ * N_ * L_];
__device__ __align__(16) __nv_bfloat16 g_wL [(size_t)B_ * Q_ * N_ * L_];
__device__ __align__(16) __nv_bfloat16 g_s2H[(size_t)B_ * D_ * N_ * L_];
__device__ __align__(16) __nv_bfloat16 g_s2L[(size_t)B_ * D_ * N_ * L_];
__device__ __align__(16) __nv_bfloat16 g_WcatH[(size_t)D_ * ND_];
__device__ __align__(16) __nv_bfloat16 g_WcatL[(size_t)D_ * ND_];
__device__ __align__(16) __nv_bfloat16 g_WcH[(size_t)D_ * C_];
__device__ __align__(16) __nv_bfloat16 g_WcL[(size_t)D_ * C_];
__device__ __align__(16) __nv_bfloat16 g_ctxTH[(size_t)N_ * B_ * L_ * C_];
__device__ __align__(16) __nv_bfloat16 g_ctxTL[(size_t)N_ * B_ * L_ * C_];

typedef unsigned long long u64;

__device__ __forceinline__ float warpSum32(float v) {
    #pragma unroll
    for (int o = 16; o; o >>= 1) v += __shfl_xor_sync(0xffffffffu, v, o);
    return v;
}

// ---- bf16 split helpers ----
__device__ __forceinline__ void split1(float x, __nv_bfloat16& h, __nv_bfloat16& l) {
    h = __float2bfloat16(x);
    l = __float2bfloat16(x - __bfloat162float(h));
}
__device__ __forceinline__ void st_pair(__nv_bfloat16* H, __nv_bfloat16* L,
                                        size_t off, float x0, float x1) {
    __nv_bfloat16 h0, l0, h1, l1;
    split1(x0, h0, l0); split1(x1, h1, l1);
    uint32_t hu = (uint32_t)__bfloat16_as_ushort(h0) |
                  ((uint32_t)__bfloat16_as_ushort(h1) << 16);
    uint32_t lu = (uint32_t)__bfloat16_as_ushort(l0) |
                  ((uint32_t)__bfloat16_as_ushort(l1) << 16);
    *(uint32_t*)&H[off] = hu;
    *(uint32_t*)&L[off] = lu;
}
// reconstruct 8 fp32 from bf16 hi/lo pairs at off (and off+128 handled by caller)
__device__ __forceinline__ void rec4(const __nv_bfloat16* __restrict__ H,
                                     const __nv_bfloat16* __restrict__ L,
                                     size_t off, float* o) {
    #pragma unroll
    for (int k = 0; k < 2; k++) {
        float2 h = __bfloat1622float2(*(const __nv_bfloat162*)&H[off + 2 * k]);
        float2 l = __bfloat1622float2(*(const __nv_bfloat162*)&L[off + 2 * k]);
        o[2 * k]     = h.x + l.x;
        o[2 * k + 1] = h.y + l.y;
    }
}

// ---- warp-level tensor core helpers (sm_80 baseline; no 'a' features) ----
__device__ __forceinline__ uint32_t smem_u32(const void* p) {
    uint32_t a;
    asm("{ .reg .u64 t; cvta.to.shared.u64 t, %1; cvt.u32.u64 %0, t; }" : "=r"(a) : "l"(p));
    return a;
}
__device__ __forceinline__ void ldsm_x4(uint32_t& r0, uint32_t& r1, uint32_t& r2,
                                        uint32_t& r3, uint32_t a) {
    asm volatile("ldmatrix.sync.aligned.m8n8.x4.shared.b16 {%0,%1,%2,%3}, [%4];"
                 : "=r"(r0), "=r"(r1), "=r"(r2), "=r"(r3) : "r"(a));
}
__device__ __forceinline__ void mma_bf16(float* d, const uint32_t* a, const uint32_t* b) {
    asm volatile("mma.sync.aligned.m16n8k16.row.col.f32.bf16.bf16.f32 "
        "{%0,%1,%2,%3}, {%4,%5,%6,%7}, {%8,%9}, {%0,%1,%2,%3};"
        : "+f"(d[0]), "+f"(d[1]), "+f"(d[2]), "+f"(d[3])
        : "r"(a[0]), "r"(a[1]), "r"(a[2]), "r"(a[3]), "r"(b[0]), "r"(b[1]));
}
__device__ __forceinline__ void cp16(uint32_t saddr, const void* gaddr) {
    asm volatile("cp.async.cg.shared.global [%0], [%1], 16;"
                 :: "r"(saddr), "l"(gaddr) : "memory");
}
#define CP_COMMIT() asm volatile("cp.async.commit_group;" ::: "memory")
#define CP_WAIT(n)  asm volatile("cp.async.wait_group %0;" :: "n"(n) : "memory")

// XOR-swizzled 64B-row tile offset
__device__ __forceinline__ uint32_t swz(int row, int c4) {
    return (uint32_t)(row * 64 + ((c4 ^ ((row >> 1) & 3)) << 4));
}

// 3-term split MMA for one jj-group, term-outer ordering
__device__ __forceinline__ void mma_group(float (*acc)[4], int jj,
                                          uint32_t (&ah)[2][4], uint32_t (&al)[2][4],
                                          const uint32_t* bh, const uint32_t* bl) {
    #pragma unroll
    for (int m = 0; m < 2; m++)
        #pragma unroll
        for (int jb = 0; jb < 2; jb++)
            mma_bf16(acc[m * 8 + jj * 2 + jb], ah[m], bh + jb * 2);
    #pragma unroll
    for (int m = 0; m < 2; m++)
        #pragma unroll
        for (int jb = 0; jb < 2; jb++)
            mma_bf16(acc[m * 8 + jj * 2 + jb], ah[m], bl + jb * 2);
    #pragma unroll
    for (int m = 0; m < 2; m++)
        #pragma unroll
        for (int jb = 0; jb < 2; jb++)
            mma_bf16(acc[m * 8 + jj * 2 + jb], al[m], bh + jb * 2);
}

// ---------------------------------------------------------------------------
// K1: transpose input [B][D][Q] -> g_tgtH/L bf16 split, [B][Q][D]
// ---------------------------------------------------------------------------
__global__ void __launch_bounds__(256) k_transpose(const float* __restrict__ in) {
    __shared__ float tile[32][33];
    const int b  = blockIdx.z;
    const int q0 = blockIdx.x * 32;
    const int d0 = blockIdx.y * 32;
    const int tx = threadIdx.x, ty = threadIdx.y;  // 32 x 8
    #pragma unroll
    for (int j = 0; j < 4; j++)
        tile[ty + j * 8][tx] = in[((size_t)b * D_ + d0 + ty + j * 8) * Q_ + q0 + tx];
    __syncthreads();
    #pragma unroll
    for (int j = 0; j < 4; j++) {
        float x = tile[tx][ty + j * 8];
        size_t idx = ((size_t)b * Q_ + q0 + ty + j * 8) * D_ + d0 + tx;
        __nv_bfloat16 h, l; split1(x, h, l);
        g_tgtH[idx] = h; g_tgtL[idx] = l;
    }
}

// K1b/K1c: split weights fp32 -> bf16 hi/lo
__global__ void __launch_bounds__(256) k_splitW(const float* __restrict__ Wcat) {
    int idx = blockIdx.x * 1024 + threadIdx.x * 4;
    #pragma unroll
    for (int i = 0; i < 4; i++) {
        float x = Wcat[idx + i];
        __nv_bfloat16 h, l; split1(x, h, l);
        g_WcatH[idx + i] = h; g_WcatL[idx + i] = l;
    }
}
__global__ void __launch_bounds__(256) k_splitWc(const float* __restrict__ Wc) {
    int idx = blockIdx.x * 1024 + threadIdx.x * 4;
    #pragma unroll
    for (int i = 0; i < 4; i++) {
        float x = Wc[idx + i];
        __nv_bfloat16 h, l; split1(x, h, l);
        g_WcH[idx + i] = h; g_WcL[idx + i] = l;
    }
}

// K1d: transpose+split contexts [nb][c][l] fp32 -> g_ctxTH/L [nb][l][c] bf16
__global__ void __launch_bounds__(256) k_ctxT(const float* __restrict__ ctx) {
    __shared__ float tile[32][33];
    const int nb = blockIdx.z;
    const int l0 = blockIdx.x * 32;
    const int c0 = blockIdx.y * 32;
    const int tx = threadIdx.x, ty = threadIdx.y;  // 32 x 8
    const float* cp = ctx + (size_t)nb * C_ * L_;
    #pragma unroll
    for (int j = 0; j < 4; j++)
        tile[ty + j * 8][tx] = cp[(size_t)(c0 + ty + j * 8) * L_ + l0 + tx];
    __syncthreads();
    #pragma unroll
    for (int j = 0; j < 4; j++) {
        float x = tile[tx][ty + j * 8];
        size_t idx = ((size_t)nb * L_ + l0 + ty + j * 8) * C_ + c0 + tx;
        __nv_bfloat16 h, l; split1(x, h, l);
        g_ctxTH[idx] = h; g_ctxTL[idx] = l;
    }
}

// ---------------------------------------------------------------------------
// Shared tile constants for the 128x128 mma kernels (swizzled 64B rows, 3 bufs)
// ---------------------------------------------------------------------------
constexpr int PLANE64 = 128 * 64;        // 8192
constexpr int BUF64   = 4 * PLANE64;     // 32768
constexpr int MMA_SMEM = 3 * BUF64;      // 98304 (staging/logits reuse it)
constexpr int LSTRIDE = 129;
constexpr int NCH = 8;                   // K=256 in chunks of 32

// ---------------------------------------------------------------------------
// K2 (mma.sync): src[l,d] = sum_c ctxT[l,c] * Wc[d,c]  (3-term bf16 split)
// tile 128 l (M) x 128 d (N), K = 512 in 16 chunks; 3-buffer single-sync.
// Epilogue: stage accs to smem, coalesced bf16-pair store.
// ---------------------------------------------------------------------------
constexpr int SRC_NCH = C_ / 32;  // 16

__global__ void __launch_bounds__(256, 2) k_source_mma() {
    extern __shared__ __align__(16) char smem[];
    const uint32_t sb = smem_u32(smem);
    const int t = threadIdx.x;
    const int lane = t & 31, wid = t >> 5;
    const int qw = (wid & 3) * 32;   // l dir (M)
    const int lw = (wid >> 2) * 64;  // d dir (N)
    const int nb = blockIdx.y;
    const int d0 = blockIdx.x * 128;

    const __nv_bfloat16* aH = g_ctxTH + (size_t)nb * L_ * C_;
    const __nv_bfloat16* aL = g_ctxTL + (size_t)nb * L_ * C_;
    const __nv_bfloat16* bH = g_WcH + (size_t)d0 * C_;
    const __nv_bfloat16* bL = g_WcL + (size_t)d0 * C_;

    auto prefetch = [&](int c) {
        const int kd = c * 32;
        const uint32_t sbase = sb + (c % 3) * BUF64;
        #pragma unroll
        for (int i = 0; i < 8; i++) {
            int idx = t + i * 256;
            int pl = idx >> 9;
            int p2 = idx & 511;
            int row = p2 >> 2, c4 = p2 & 3;
            const __nv_bfloat16* sp =
                (pl == 0) ? aH : (pl == 1) ? aL : (pl == 2) ? bH : bL;
            cp16(sbase + pl * PLANE64 + swz(row, c4),
                 sp + (size_t)row * C_ + kd + c4 * 8);
        }
        CP_COMMIT();
    };

    float acc[16][4] = {};

    prefetch(0); prefetch(1);
    for (int c = 0; c < SRC_NCH; c++) {
        if (c + 1 < SRC_NCH) CP_WAIT(1); else CP_WAIT(0);
        __syncthreads();
        if (c + 2 < SRC_NCH) prefetch(c + 2);
        const uint32_t sbase = sb + (c % 3) * BUF64;
        #pragma unroll
        for (int kh = 0; kh < 2; kh++) {
            uint32_t ah[2][4], al[2][4];
            #pragma unroll
            for (int m = 0; m < 2; m++) {
                uint32_t addr = sbase + swz(qw + m * 16 + (lane & 15),
                                            kh * 2 + (lane >> 4));
                ldsm_x4(ah[m][0], ah[m][1], ah[m][2], ah[m][3], addr);
                ldsm_x4(al[m][0], al[m][1], al[m][2], al[m][3], addr + PLANE64);
            }
            const int nrow = (lane & 7) + ((lane >> 4) << 3);
            const int nc4  = kh * 2 + ((lane >> 3) & 1);
            #pragma unroll
            for (int jj = 0; jj < 4; jj++) {
                uint32_t addr = sbase + 2 * PLANE64 + swz(lw + jj * 16 + nrow, nc4);
                uint32_t bh[4], bl[4];
                ldsm_x4(bh[0], bh[1], bh[2], bh[3], addr);
                ldsm_x4(bl[0], bl[1], bl[2], bl[3], addr + PLANE64);
                mma_group(acc, jj, ah, al, bh, bl);
            }
        }
    }
    // stage to smem, then coalesced store
    __syncthreads();
    float* sx = (float*)smem;
    #pragma unroll
    for (int m = 0; m < 2; m++)
        #pragma unroll
        for (int j = 0; j < 8; j++) {
            int lr  = qw + m * 16 + (lane >> 2);
            int col = lw + j * 8 + (lane & 3) * 2;
            float* d = acc[m * 8 + j];
            sx[lr * 128 + col]           = d[0];
            sx[lr * 128 + col + 1]       = d[1];
            sx[(lr + 8) * 128 + col]     = d[2];
            sx[(lr + 8) * 128 + col + 1] = d[3];
        }
    __syncthreads();
    #pragma unroll
    for (int i = 0; i < 32; i++) {
        int p = t + i * 256;           // 8192 pairs
        int row = p >> 6;
        int col = (p & 63) * 2;
        st_pair(g_srcH, g_srcL, ((size_t)nb * L_ + row) * D_ + d0 + col,
                sx[row * 128 + col], sx[row * 128 + col + 1]);
    }
}

// ---------------------------------------------------------------------------
// K3 (mma.sync): logits[128q,128l] = tgt·src^T, softmax, w as bf16 hi/lo.
// 3-buffer single-sync pipeline; 256-thread softmax; coalesced w store.
// ---------------------------------------------------------------------------
__global__ void __launch_bounds__(256, 2) k_attn_mma() {
    extern __shared__ __align__(16) char smem[];
    float* logits = (float*)smem;
    float* sinv   = logits + 128 * LSTRIDE;   // 128 floats
    const uint32_t sb = smem_u32(smem);
    const int t = threadIdx.x;
    const int lane = t & 31, wid = t >> 5;
    const int qw = (wid & 3) * 32;
    const int lw = (wid >> 2) * 64;
    const int nb = blockIdx.y;
    const int n = nb >> 5, b = nb & 31;
    const int q0 = blockIdx.x * 128;

    const __nv_bfloat16* aH = g_tgtH + ((size_t)b * Q_ + q0) * D_;
    const __nv_bfloat16* aL = g_tgtL + ((size_t)b * Q_ + q0) * D_;
    const __nv_bfloat16* bH = g_srcH + (size_t)nb * L_ * D_;
    const __nv_bfloat16* bL = g_srcL + (size_t)nb * L_ * D_;

    auto prefetch = [&](int c) {
        const int kd = c * 32;
        const uint32_t sbase = sb + (c % 3) * BUF64;
        #pragma unroll
        for (int i = 0; i < 8; i++) {
            int idx = t + i * 256;
            int pl = idx >> 9;
            int p2 = idx & 511;
            int row = p2 >> 2, c4 = p2 & 3;
            const __nv_bfloat16* sp =
                (pl == 0) ? aH : (pl == 1) ? aL : (pl == 2) ? bH : bL;
            cp16(sbase + pl * PLANE64 + swz(row, c4),
                 sp + (size_t)row * D_ + kd + c4 * 8);
        }
        CP_COMMIT();
    };

    float acc[16][4] = {};

    prefetch(0); prefetch(1);
    for (int c = 0; c < NCH; c++) {
        if (c + 1 < NCH) CP_WAIT(1); else CP_WAIT(0);
        __syncthreads();
        if (c + 2 < NCH) prefetch(c + 2);
        const uint32_t sbase = sb + (c % 3) * BUF64;
        #pragma unroll
        for (int kh = 0; kh < 2; kh++) {
            uint32_t ah[2][4], al[2][4];
            #pragma unroll
            for (int m = 0; m < 2; m++) {
                uint32_t addr = sbase + swz(qw + m * 16 + (lane & 15),
                                            kh * 2 + (lane >> 4));
                ldsm_x4(ah[m][0], ah[m][1], ah[m][2], ah[m][3], addr);
                ldsm_x4(al[m][0], al[m][1], al[m][2], al[m][3], addr + PLANE64);
            }
            const int nrow = (lane & 7) + ((lane >> 4) << 3);
            const int nc4  = kh * 2 + ((lane >> 3) & 1);
            #pragma unroll
            for (int jj = 0; jj < 4; jj++) {
                uint32_t addr = sbase + 2 * PLANE64 + swz(lw + jj * 16 + nrow, nc4);
                uint32_t bh[4], bl[4];
                ldsm_x4(bh[0], bh[1], bh[2], bh[3], addr);
                ldsm_x4(bl[0], bl[1], bl[2], bl[3], addr + PLANE64);
                mma_group(acc, jj, ah, al, bh, bl);
            }
        }
    }
    __syncthreads();
    #pragma unroll
    for (int m = 0; m < 2; m++)
        #pragma unroll
        for (int j = 0; j < 8; j++) {
            int qr  = qw + m * 16 + (lane >> 2);
            int col = lw + j * 8 + (lane & 3) * 2;
            float* d = acc[m * 8 + j];
            logits[qr * LSTRIDE + col]           = d[0];
            logits[qr * LSTRIDE + col + 1]       = d[1];
            logits[(qr + 8) * LSTRIDE + col]     = d[2];
            logits[(qr + 8) * LSTRIDE + col + 1] = d[3];
        }
    __syncthreads();
    {
        // softmax: 2 lanes per row; exp kept in smem; per-row inv stored
        const int row = t >> 1, half = t & 1;
        float* rp = logits + row * LSTRIDE + half * 64;
        float m = rp[0];
        #pragma unroll 8
        for (int j = 1; j < 64; j++) m = fmaxf(m, rp[j]);
        m = fmaxf(m, __shfl_xor_sync(0xffffffffu, m, 1));
        float s = 0.f;
        #pragma unroll 8
        for (int j = 0; j < 64; j++) {
            float ev = __expf(rp[j] - m);
            rp[j] = ev;
            s += ev;
        }
        s += __shfl_xor_sync(0xffffffffu, s, 1);
        if (half == 0) sinv[row] = 1.0f / s;
    }
    __syncthreads();
    // coalesced w store: consecutive lanes -> consecutive column pairs
    #pragma unroll
    for (int i = 0; i < 32; i++) {
        int p = t + i * 256;
        int row = p >> 6;
        int col = (p & 63) * 2;
        float iv = sinv[row];
        st_pair(g_wH, g_wL, (((size_t)b * Q_ + q0 + row) * N_ + n) * L_ + col,
                logits[row * LSTRIDE + col] * iv,
                logits[row * LSTRIDE + col + 1] * iv);
    }
}

// ---------------------------------------------------------------------------
// K4 (mma.sync): S2[e,l] = sum_d Wcat[e, n*D+d] * src[l,d] -> bf16 hi/lo
// 3-buffer single-sync pipeline; staged coalesced store.
// ---------------------------------------------------------------------------
__global__ void __launch_bounds__(256, 2) k_s2_mma() {
    extern __shared__ __align__(16) char smem[];
    const uint32_t sb = smem_u32(smem);
    const int t = threadIdx.x;
    const int lane = t & 31, wid = t >> 5;
    const int qw = (wid & 3) * 32;   // e dir
    const int lw = (wid >> 2) * 64;  // l dir
    const int nb = blockIdx.y;
    const int n = nb >> 5, b = nb & 31;
    const int e0 = blockIdx.x * 128;

    const __nv_bfloat16* aH = g_WcatH + (size_t)e0 * ND_ + n * D_;
    const __nv_bfloat16* aL = g_WcatL + (size_t)e0 * ND_ + n * D_;
    const __nv_bfloat16* bH = g_srcH + (size_t)nb * L_ * D_;
    const __nv_bfloat16* bL = g_srcL + (size_t)nb * L_ * D_;

    auto prefetch = [&](int c) {
        const int kd = c * 32;
        const uint32_t sbase = sb + (c % 3) * BUF64;
        #pragma unroll
        for (int i = 0; i < 8; i++) {
            int idx = t + i * 256;
            int pl = idx >> 9;
            int p2 = idx & 511;
            int row = p2 >> 2, c4 = p2 & 3;
            const __nv_bfloat16* sp;
            size_t stride;
            if (pl < 2) { sp = pl ? aL : aH; stride = ND_; }
            else        { sp = (pl == 3) ? bL : bH; stride = D_; }
            cp16(sbase + pl * PLANE64 + swz(row, c4),
                 sp + (size_t)row * stride + kd + c4 * 8);
        }
        CP_COMMIT();
    };

    float acc[16][4] = {};

    prefetch(0); prefetch(1);
    for (int c = 0; c < NCH; c++) {
        if (c + 1 < NCH) CP_WAIT(1); else CP_WAIT(0);
        __syncthreads();
        if (c + 2 < NCH) prefetch(c + 2);
        const uint32_t sbase = sb + (c % 3) * BUF64;
        #pragma unroll
        for (int kh = 0; kh < 2; kh++) {
            uint32_t ah[2][4], al[2][4];
            #pragma unroll
            for (int m = 0; m < 2; m++) {
                uint32_t addr = sbase + swz(qw + m * 16 + (lane & 15),
                                            kh * 2 + (lane >> 4));
                ldsm_x4(ah[m][0], ah[m][1], ah[m][2], ah[m][3], addr);
                ldsm_x4(al[m][0], al[m][1], al[m][2], al[m][3], addr + PLANE64);
            }
            const int nrow = (lane & 7) + ((lane >> 4) << 3);
            const int nc4  = kh * 2 + ((lane >> 3) & 1);
            #pragma unroll
            for (int jj = 0; jj < 4; jj++) {
                uint32_t addr = sbase + 2 * PLANE64 + swz(lw + jj * 16 + nrow, nc4);
                uint32_t bh[4], bl[4];
                ldsm_x4(bh[0], bh[1], bh[2], bh[3], addr);
                ldsm_x4(bl[0], bl[1], bl[2], bl[3], addr + PLANE64);
                mma_group(acc, jj, ah, al, bh, bl);
            }
        }
    }
    // stage to smem, then coalesced store (rows=e, cols=l)
    __syncthreads();
    float* sx = (float*)smem;
    #pragma unroll
    for (int m = 0; m < 2; m++)
        #pragma unroll
        for (int j = 0; j < 8; j++) {
            int er  = qw + m * 16 + (lane >> 2);
            int col = lw + j * 8 + (lane & 3) * 2;
            float* d = acc[m * 8 + j];
            sx[er * 128 + col]           = d[0];
            sx[er * 128 + col + 1]       = d[1];
            sx[(er + 8) * 128 + col]     = d[2];
            sx[(er + 8) * 128 + col + 1] = d[3];
        }
    __syncthreads();
    #pragma unroll
    for (int i = 0; i < 32; i++) {
        int p = t + i * 256;
        int row = p >> 6;
        int col = (p & 63) * 2;
        st_pair(g_s2H, g_s2L,
                (((size_t)b * D_ + e0 + row) * N_ + n) * L_ + col,
                sx[row * 128 + col], sx[row * 128 + col + 1]);
    }
}

// ---------------------------------------------------------------------------
// K5 (mma.sync): x[q,e] = sum_k w[q,k]*s2[e,k], K=1280, tile 64q x 256e.
// Swizzled 64B rows, 2-buffer single-sync pipeline.
// Epilogue: stage x to smem, then bias+relu+residual+LayerNorm -> out.
// Residual reconstructed from tgtH+tgtL (no fp32 tgt copy).
// ---------------------------------------------------------------------------
constexpr int O_APL  = 64 * 64;        // 4096
constexpr int O_BPL  = 256 * 64;       // 16384
constexpr int O_BUF  = 2 * O_APL + 2 * O_BPL;  // 40960
constexpr int O_SMEM = 2 * O_BUF;      // 81920 (x-staging 66560 reuses it)
constexpr int O_NCH  = K2_ / 32;       // 40
constexpr int XS     = 260;            // x staging row stride (floats)

__global__ void __launch_bounds__(256, 2) k_out_mma(const float* __restrict__ Wb,
                                                    const float* __restrict__ gamma,
                                                    const float* __restrict__ beta,
                                                    float* __restrict__ out) {
    extern __shared__ __align__(16) char smem[];
    const uint32_t sb = smem_u32(smem);
    const int t = threadIdx.x;
    const int lane = t & 31, wid = t >> 5;
    const int qw = (wid & 1) * 32;   // q dir
    const int ew = (wid >> 1) * 64;  // e dir
    const int b  = blockIdx.y;
    const int q0 = blockIdx.x * 64;

    const __nv_bfloat16* wHp = g_wH + ((size_t)b * Q_ + q0) * K2_;
    const __nv_bfloat16* wLp = g_wL + ((size_t)b * Q_ + q0) * K2_;
    const __nv_bfloat16* sHp = g_s2H + (size_t)b * D_ * K2_;
    const __nv_bfloat16* sLp = g_s2L + (size_t)b * D_ * K2_;

    auto prefetch = [&](int c) {
        const int k0 = c * 32;
        const uint32_t sbase = sb + (c & 1) * O_BUF;
        #pragma unroll
        for (int i = 0; i < 10; i++) {
            int idx = t + i * 256;
            if (idx < 512) {
                int pl = idx >> 8, p = idx & 255, row = p >> 2, c4 = p & 3;
                const __nv_bfloat16* sp = pl ? wLp : wHp;
                cp16(sbase + pl * O_APL + swz(row, c4),
                     sp + (size_t)row * K2_ + k0 + c4 * 8);
            } else {
                int idx2 = idx - 512;
                int pl = idx2 >> 10, p = idx2 & 1023, row = p >> 2, c4 = p & 3;
                const __nv_bfloat16* sp = pl ? sLp : sHp;
                cp16(sbase + 2 * O_APL + pl * O_BPL + swz(row, c4),
                     sp + (size_t)row * K2_ + k0 + c4 * 8);
            }
        }
        CP_COMMIT();
    };

    float acc[16][4] = {};

    prefetch(0);
    for (int c = 0; c < O_NCH; c++) {
        CP_WAIT(0);
        __syncthreads();
        if (c + 1 < O_NCH) prefetch(c + 1);
        const uint32_t sbase = sb + (c & 1) * O_BUF;
        #pragma unroll
        for (int kh = 0; kh < 2; kh++) {
            uint32_t ah[2][4], al[2][4];
            #pragma unroll
            for (int m = 0; m < 2; m++) {
                uint32_t addr = sbase + swz(qw + m * 16 + (lane & 15),
                                            kh * 2 + (lane >> 4));
                ldsm_x4(ah[m][0], ah[m][1], ah[m][2], ah[m][3], addr);
                ldsm_x4(al[m][0], al[m][1], al[m][2], al[m][3], addr + O_APL);
            }
            const int nrow = (lane & 7) + ((lane >> 4) << 3);
            const int nc4  = kh * 2 + ((lane >> 3) & 1);
            #pragma unroll
            for (int jj = 0; jj < 4; jj++) {
                uint32_t addr = sbase + 2 * O_APL + swz(ew + jj * 16 + nrow, nc4);
                uint32_t bh[4], bl[4];
                ldsm_x4(bh[0], bh[1], bh[2], bh[3], addr);
                ldsm_x4(bl[0], bl[1], bl[2], bl[3], addr + O_BPL);
                mma_group(acc, jj, ah, al, bh, bl);
            }
        }
    }
    __syncthreads();
    float* sx = (float*)smem;
    #pragma unroll
    for (int m = 0; m < 2; m++)
        #pragma unroll
        for (int j = 0; j < 8; j++) {
            int qr  = qw + m * 16 + (lane >> 2);
            int col = ew + j * 8 + (lane & 3) * 2;
            float* d = acc[m * 8 + j];
            sx[qr * XS + col]           = d[0];
            sx[qr * XS + col + 1]       = d[1];
            sx[(qr + 8) * XS + col]     = d[2];
            sx[(qr + 8) * XS + col + 1] = d[3];
        }
    __syncthreads();
    float wb[8], gm[8], be[8];
    {
        float4 w0 = *(const float4*)&Wb[lane * 4];
        float4 w1 = *(const float4*)&Wb[lane * 4 + 128];
        float4 g0 = *(const float4*)&gamma[lane * 4];
        float4 g1 = *(const float4*)&gamma[lane * 4 + 128];
        float4 e0 = *(const float4*)&beta[lane * 4];
        float4 e1 = *(const float4*)&beta[lane * 4 + 128];
        wb[0]=w0.x; wb[1]=w0.y; wb[2]=w0.z; wb[3]=w0.w; wb[4]=w1.x; wb[5]=w1.y; wb[6]=w1.z; wb[7]=w1.w;
        gm[0]=g0.x; gm[1]=g0.y; gm[2]=g0.z; gm[3]=g0.w; gm[4]=g1.x; gm[5]=g1.y; gm[6]=g1.z; gm[7]=g1.w;
        be[0]=e0.x; be[1]=e0.y; be[2]=e0.z; be[3]=e0.w; be[4]=e1.x; be[5]=e1.y; be[6]=e1.z; be[7]=e1.w;
    }
    const __nv_bfloat16* tH = g_tgtH + (size_t)b * Q_ * D_;
    const __nv_bfloat16* tL = g_tgtL + (size_t)b * Q_ * D_;
    #pragma unroll
    for (int i = 0; i < 8; i++) {
        const int r = wid * 8 + i;
        const int q = q0 + r;
        float4 a0 = *(const float4*)&sx[r * XS + lane * 4];
        float4 a1 = *(const float4*)&sx[r * XS + lane * 4 + 128];
        float av[8] = {a0.x, a0.y, a0.z, a0.w, a1.x, a1.y, a1.z, a1.w};
        float tv[8];
        rec4(tH, tL, (size_t)q * D_ + lane * 4, tv);
        rec4(tH, tL, (size_t)q * D_ + lane * 4 + 128, tv + 4);
        float v[8], s = 0.f;
        #pragma unroll
        for (int j = 0; j < 8; j++) {
            v[j] = fmaxf(av[j] + wb[j], 0.f) + tv[j];
            s += v[j];
        }
        s = warpSum32(s);
        const float mu = s * (1.0f / 256.0f);
        float d2 = 0.f;
        #pragma unroll
        for (int j = 0; j < 8; j++) { float dd = v[j] - mu; d2 += dd * dd; }
        d2 = warpSum32(d2);
        const float rs = rsqrtf(d2 * (1.0f / 256.0f));
        float o[8];
        #pragma unroll
        for (int j = 0; j < 8; j++) o[j] = (v[j] - mu) * rs * gm[j] + be[j];
        float* orow = out + (size_t)(b * Q_ + q) * D_;
        *(float4*)&orow[lane * 4]       = make_float4(o[0], o[1], o[2], o[3]);
        *(float4*)&orow[lane * 4 + 128] = make_float4(o[4], o[5], o[6], o[7]);
    }
}

// ---------------------------------------------------------------------------
extern "C" void kernel_launch(void* const* d_in, const int* in_sizes, int n_in,
                              void* d_out, int out_size) {
    const float* input    = (const float*)d_in[0];  // [B, D, 32, 32]
    const float* contexts = (const float*)d_in[1];  // [N, B, C, L]
    const float* Wc       = (const float*)d_in[2];  // [D, C]
    const float* Wcat     = (const float*)d_in[3];  // [D, N*D]
    const float* Wb       = (const float*)d_in[4];  // [D]
    const float* gamma    = (const float*)d_in[5];  // [D]
    const float* beta     = (const float*)d_in[6];  // [D]
    float* out = (float*)d_out;                     // [B, Q, D]

    cudaFuncSetAttribute(k_source_mma, cudaFuncAttributeMaxDynamicSharedMemorySize, MMA_SMEM);
    cudaFuncSetAttribute(k_attn_mma,   cudaFuncAttributeMaxDynamicSharedMemorySize, MMA_SMEM);
    cudaFuncSetAttribute(k_s2_mma,     cudaFuncAttributeMaxDynamicSharedMemorySize, MMA_SMEM);
    cudaFuncSetAttribute(k_out_mma,    cudaFuncAttributeMaxDynamicSharedMemorySize, O_SMEM);

    k_transpose <<<dim3(Q_ / 32, D_ / 32, B_), dim3(32, 8)>>>(input);
    k_splitW    <<<D_ * ND_ / 1024, 256>>>(Wcat);
    k_splitWc   <<<D_ * C_ / 1024, 256>>>(Wc);
    k_ctxT      <<<dim3(L_ / 32, C_ / 32, N_ * B_), dim3(32, 8)>>>(contexts);
    k_source_mma<<<dim3(2,        N_ * B_),    256, MMA_SMEM>>>();
    k_attn_mma  <<<dim3(Q_ / 128, N_ * B_),    256, MMA_SMEM>>>();
    k_s2_mma    <<<dim3(2,        N_ * B_),    256, MMA_SMEM>>>();
    k_out_mma   <<<dim3(Q_ / 64,  B_),         256, O_SMEM>>>(Wb, gamma, beta, out);
}

// round 14
// speedup vs baseline: 3.3564x; 1.0016x over previous
#include <cuda_runtime.h>
#include <cuda_bf16.h>
#include <cstdint>

// Problem dims (fixed by the reference)
constexpr int B_  = 32;
constexpr int D_  = 256;   // idf
constexpr int Q_  = 1024;  // ih*iw
constexpr int C_  = 512;   // cdf
constexpr int L_  = 128;
constexpr int N_  = 10;    // contexts
constexpr int K2_ = N_ * L_;  // 1280
constexpr int ND_ = N_ * D_;  // 2560

// Scratch (static device globals — no allocation in kernel_launch)
// bf16 split pairs (tensor-core operands)
__device__ __align__(16) __nv_bfloat16 g_tgtH[(size_t)B_ * Q_ * D_];
__device__ __align__(16) __nv_bfloat16 g_tgtL[(size_t)B_ * Q_ * D_];
__device__ __align__(16) __nv_bfloat16 g_srcH[(size_t)N_ * B_ * L_ * D_];
__device__ __align__(16) __nv_bfloat16 g_srcL[(size_t)N_ * B_ * L_ * D_];
__device__ __align__(16) __nv_bfloat16 g_wH [(size_t)B_ * Q_ * N_ * L_];
__device__ __align__(16) __nv_bfloat16 g_wL [(size_t)B_ * Q_ * N_ * L_];
__device__ __align__(16) __nv_bfloat16 g_s2H[(size_t)B_ * D_ * N_ * L_];
__device__ __align__(16) __nv_bfloat16 g_s2L[(size_t)B_ * D_ * N_ * L_];
__device__ __align__(16) __nv_bfloat16 g_WcatH[(size_t)D_ * ND_];
__device__ __align__(16) __nv_bfloat16 g_WcatL[(size_t)D_ * ND_];
__device__ __align__(16) __nv_bfloat16 g_WcH[(size_t)D_ * C_];
__device__ __align__(16) __nv_bfloat16 g_WcL[(size_t)D_ * C_];
__device__ __align__(16) __nv_bfloat16 g_ctxTH[(size_t)N_ * B_ * L_ * C_];
__device__ __align__(16) __nv_bfloat16 g_ctxTL[(size_t)N_ * B_ * L_ * C_];

typedef unsigned long long u64;

__device__ __forceinline__ float warpSum32(float v) {
    #pragma unroll
    for (int o = 16; o; o >>= 1) v += __shfl_xor_sync(0xffffffffu, v, o);
    return v;
}

// ---- bf16 split helpers ----
__device__ __forceinline__ void split1(float x, __nv_bfloat16& h, __nv_bfloat16& l) {
    h = __float2bfloat16(x);
    l = __float2bfloat16(x - __bfloat162float(h));
}
__device__ __forceinline__ void st_pair(__nv_bfloat16* H, __nv_bfloat16* L,
                                        size_t off, float x0, float x1) {
    __nv_bfloat16 h0, l0, h1, l1;
    split1(x0, h0, l0); split1(x1, h1, l1);
    uint32_t hu = (uint32_t)__bfloat16_as_ushort(h0) |
                  ((uint32_t)__bfloat16_as_ushort(h1) << 16);
    uint32_t lu = (uint32_t)__bfloat16_as_ushort(l0) |
                  ((uint32_t)__bfloat16_as_ushort(l1) << 16);
    *(uint32_t*)&H[off] = hu;
    *(uint32_t*)&L[off] = lu;
}
// reconstruct 4 fp32 from bf16 hi/lo pairs at off
__device__ __forceinline__ void rec4(const __nv_bfloat16* __restrict__ H,
                                     const __nv_bfloat16* __restrict__ L,
                                     size_t off, float* o) {
    #pragma unroll
    for (int k = 0; k < 2; k++) {
        float2 h = __bfloat1622float2(*(const __nv_bfloat162*)&H[off + 2 * k]);
        float2 l = __bfloat1622float2(*(const __nv_bfloat162*)&L[off + 2 * k]);
        o[2 * k]     = h.x + l.x;
        o[2 * k + 1] = h.y + l.y;
    }
}

// ---- warp-level tensor core helpers (sm_80 baseline; no 'a' features) ----
__device__ __forceinline__ uint32_t smem_u32(const void* p) {
    uint32_t a;
    asm("{ .reg .u64 t; cvta.to.shared.u64 t, %1; cvt.u32.u64 %0, t; }" : "=r"(a) : "l"(p));
    return a;
}
__device__ __forceinline__ void ldsm_x4(uint32_t& r0, uint32_t& r1, uint32_t& r2,
                                        uint32_t& r3, uint32_t a) {
    asm volatile("ldmatrix.sync.aligned.m8n8.x4.shared.b16 {%0,%1,%2,%3}, [%4];"
                 : "=r"(r0), "=r"(r1), "=r"(r2), "=r"(r3) : "r"(a));
}
__device__ __forceinline__ void mma_bf16(float* d, const uint32_t* a, const uint32_t* b) {
    asm volatile("mma.sync.aligned.m16n8k16.row.col.f32.bf16.bf16.f32 "
        "{%0,%1,%2,%3}, {%4,%5,%6,%7}, {%8,%9}, {%0,%1,%2,%3};"
        : "+f"(d[0]), "+f"(d[1]), "+f"(d[2]), "+f"(d[3])
        : "r"(a[0]), "r"(a[1]), "r"(a[2]), "r"(a[3]), "r"(b[0]), "r"(b[1]));
}
__device__ __forceinline__ void cp16(uint32_t saddr, const void* gaddr) {
    asm volatile("cp.async.cg.shared.global [%0], [%1], 16;"
                 :: "r"(saddr), "l"(gaddr) : "memory");
}
#define CP_COMMIT() asm volatile("cp.async.commit_group;" ::: "memory")
#define CP_WAIT(n)  asm volatile("cp.async.wait_group %0;" :: "n"(n) : "memory")

// XOR-swizzled 64B-row tile offset
__device__ __forceinline__ uint32_t swz(int row, int c4) {
    return (uint32_t)(row * 64 + ((c4 ^ ((row >> 1) & 3)) << 4));
}

// 3-term split MMA for one jj-group, term-outer ordering
__device__ __forceinline__ void mma_group(float (*acc)[4], int jj,
                                          uint32_t (&ah)[2][4], uint32_t (&al)[2][4],
                                          const uint32_t* bh, const uint32_t* bl) {
    #pragma unroll
    for (int m = 0; m < 2; m++)
        #pragma unroll
        for (int jb = 0; jb < 2; jb++)
            mma_bf16(acc[m * 8 + jj * 2 + jb], ah[m], bh + jb * 2);
    #pragma unroll
    for (int m = 0; m < 2; m++)
        #pragma unroll
        for (int jb = 0; jb < 2; jb++)
            mma_bf16(acc[m * 8 + jj * 2 + jb], ah[m], bl + jb * 2);
    #pragma unroll
    for (int m = 0; m < 2; m++)
        #pragma unroll
        for (int jb = 0; jb < 2; jb++)
            mma_bf16(acc[m * 8 + jj * 2 + jb], al[m], bh + jb * 2);
}

// ---------------------------------------------------------------------------
// K1: transpose input [B][D][Q] -> g_tgtH/L bf16 split, [B][Q][D]
// ---------------------------------------------------------------------------
__global__ void __launch_bounds__(256) k_transpose(const float* __restrict__ in) {
    __shared__ float tile[32][33];
    const int b  = blockIdx.z;
    const int q0 = blockIdx.x * 32;
    const int d0 = blockIdx.y * 32;
    const int tx = threadIdx.x, ty = threadIdx.y;  // 32 x 8
    #pragma unroll
    for (int j = 0; j < 4; j++)
        tile[ty + j * 8][tx] = in[((size_t)b * D_ + d0 + ty + j * 8) * Q_ + q0 + tx];
    __syncthreads();
    #pragma unroll
    for (int j = 0; j < 4; j++) {
        float x = tile[tx][ty + j * 8];
        size_t idx = ((size_t)b * Q_ + q0 + ty + j * 8) * D_ + d0 + tx;
        __nv_bfloat16 h, l; split1(x, h, l);
        g_tgtH[idx] = h; g_tgtL[idx] = l;
    }
}

// K1b/K1c: split weights fp32 -> bf16 hi/lo
__global__ void __launch_bounds__(256) k_splitW(const float* __restrict__ Wcat) {
    int idx = blockIdx.x * 1024 + threadIdx.x * 4;
    #pragma unroll
    for (int i = 0; i < 4; i++) {
        float x = Wcat[idx + i];
        __nv_bfloat16 h, l; split1(x, h, l);
        g_WcatH[idx + i] = h; g_WcatL[idx + i] = l;
    }
}
__global__ void __launch_bounds__(256) k_splitWc(const float* __restrict__ Wc) {
    int idx = blockIdx.x * 1024 + threadIdx.x * 4;
    #pragma unroll
    for (int i = 0; i < 4; i++) {
        float x = Wc[idx + i];
        __nv_bfloat16 h, l; split1(x, h, l);
        g_WcH[idx + i] = h; g_WcL[idx + i] = l;
    }
}

// K1d: transpose+split contexts [nb][c][l] fp32 -> g_ctxTH/L [nb][l][c] bf16
__global__ void __launch_bounds__(256) k_ctxT(const float* __restrict__ ctx) {
    __shared__ float tile[32][33];
    const int nb = blockIdx.z;
    const int l0 = blockIdx.x * 32;
    const int c0 = blockIdx.y * 32;
    const int tx = threadIdx.x, ty = threadIdx.y;  // 32 x 8
    const float* cp = ctx + (size_t)nb * C_ * L_;
    #pragma unroll
    for (int j = 0; j < 4; j++)
        tile[ty + j * 8][tx] = cp[(size_t)(c0 + ty + j * 8) * L_ + l0 + tx];
    __syncthreads();
    #pragma unroll
    for (int j = 0; j < 4; j++) {
        float x = tile[tx][ty + j * 8];
        size_t idx = ((size_t)nb * L_ + l0 + ty + j * 8) * C_ + c0 + tx;
        __nv_bfloat16 h, l; split1(x, h, l);
        g_ctxTH[idx] = h; g_ctxTL[idx] = l;
    }
}

// ---------------------------------------------------------------------------
// Shared tile constants for the 128x128 mma kernels (swizzled 64B rows, 3 bufs)
// ---------------------------------------------------------------------------
constexpr int PLANE64 = 128 * 64;        // 8192
constexpr int BUF64   = 4 * PLANE64;     // 32768
constexpr int MMA_SMEM = 3 * BUF64;      // 98304 (staging/logits reuse it)
constexpr int LSTRIDE = 129;
constexpr int NCH = 8;                   // K=256 in chunks of 32

// ---------------------------------------------------------------------------
// K2 (mma.sync): src[l,d] = sum_c ctxT[l,c] * Wc[d,c]  (3-term bf16 split)
// tile 128 l (M) x 128 d (N), K = 512 in 16 chunks; 3-buffer single-sync.
// ---------------------------------------------------------------------------
constexpr int SRC_NCH = C_ / 32;  // 16

__global__ void __launch_bounds__(256, 2) k_source_mma() {
    extern __shared__ __align__(16) char smem[];
    const uint32_t sb = smem_u32(smem);
    const int t = threadIdx.x;
    const int lane = t & 31, wid = t >> 5;
    const int qw = (wid & 3) * 32;   // l dir (M)
    const int lw = (wid >> 2) * 64;  // d dir (N)
    const int nb = blockIdx.y;
    const int d0 = blockIdx.x * 128;

    const __nv_bfloat16* aH = g_ctxTH + (size_t)nb * L_ * C_;
    const __nv_bfloat16* aL = g_ctxTL + (size_t)nb * L_ * C_;
    const __nv_bfloat16* bH = g_WcH + (size_t)d0 * C_;
    const __nv_bfloat16* bL = g_WcL + (size_t)d0 * C_;

    auto prefetch = [&](int c) {
        const int kd = c * 32;
        const uint32_t sbase = sb + (c % 3) * BUF64;
        #pragma unroll
        for (int i = 0; i < 8; i++) {
            int idx = t + i * 256;
            int pl = idx >> 9;
            int p2 = idx & 511;
            int row = p2 >> 2, c4 = p2 & 3;
            const __nv_bfloat16* sp =
                (pl == 0) ? aH : (pl == 1) ? aL : (pl == 2) ? bH : bL;
            cp16(sbase + pl * PLANE64 + swz(row, c4),
                 sp + (size_t)row * C_ + kd + c4 * 8);
        }
        CP_COMMIT();
    };

    float acc[16][4] = {};

    prefetch(0); prefetch(1);
    for (int c = 0; c < SRC_NCH; c++) {
        if (c + 1 < SRC_NCH) CP_WAIT(1); else CP_WAIT(0);
        __syncthreads();
        if (c + 2 < SRC_NCH) prefetch(c + 2);
        const uint32_t sbase = sb + (c % 3) * BUF64;
        #pragma unroll
        for (int kh = 0; kh < 2; kh++) {
            uint32_t ah[2][4], al[2][4];
            #pragma unroll
            for (int m = 0; m < 2; m++) {
                uint32_t addr = sbase + swz(qw + m * 16 + (lane & 15),
                                            kh * 2 + (lane >> 4));
                ldsm_x4(ah[m][0], ah[m][1], ah[m][2], ah[m][3], addr);
                ldsm_x4(al[m][0], al[m][1], al[m][2], al[m][3], addr + PLANE64);
            }
            const int nrow = (lane & 7) + ((lane >> 4) << 3);
            const int nc4  = kh * 2 + ((lane >> 3) & 1);
            #pragma unroll
            for (int jj = 0; jj < 4; jj++) {
                uint32_t addr = sbase + 2 * PLANE64 + swz(lw + jj * 16 + nrow, nc4);
                uint32_t bh[4], bl[4];
                ldsm_x4(bh[0], bh[1], bh[2], bh[3], addr);
                ldsm_x4(bl[0], bl[1], bl[2], bl[3], addr + PLANE64);
                mma_group(acc, jj, ah, al, bh, bl);
            }
        }
    }
    // stage to smem, then coalesced store
    __syncthreads();
    float* sx = (float*)smem;
    #pragma unroll
    for (int m = 0; m < 2; m++)
        #pragma unroll
        for (int j = 0; j < 8; j++) {
            int lr  = qw + m * 16 + (lane >> 2);
            int col = lw + j * 8 + (lane & 3) * 2;
            float* d = acc[m * 8 + j];
            sx[lr * 128 + col]           = d[0];
            sx[lr * 128 + col + 1]       = d[1];
            sx[(lr + 8) * 128 + col]     = d[2];
            sx[(lr + 8) * 128 + col + 1] = d[3];
        }
    __syncthreads();
    #pragma unroll
    for (int i = 0; i < 32; i++) {
        int p = t + i * 256;           // 8192 pairs
        int row = p >> 6;
        int col = (p & 63) * 2;
        st_pair(g_srcH, g_srcL, ((size_t)nb * L_ + row) * D_ + d0 + col,
                sx[row * 128 + col], sx[row * 128 + col + 1]);
    }
}

// ---------------------------------------------------------------------------
// K3 (mma.sync): logits[128q,128l] = tgt·src^T, softmax, w as bf16 hi/lo.
// 3-buffer single-sync pipeline; 256-thread softmax; coalesced w store.
// ---------------------------------------------------------------------------
__global__ void __launch_bounds__(256, 2) k_attn_mma() {
    extern __shared__ __align__(16) char smem[];
    float* logits = (float*)smem;
    float* sinv   = logits + 128 * LSTRIDE;   // 128 floats
    const uint32_t sb = smem_u32(smem);
    const int t = threadIdx.x;
    const int lane = t & 31, wid = t >> 5;
    const int qw = (wid & 3) * 32;
    const int lw = (wid >> 2) * 64;
    const int nb = blockIdx.y;
    const int n = nb >> 5, b = nb & 31;
    const int q0 = blockIdx.x * 128;

    const __nv_bfloat16* aH = g_tgtH + ((size_t)b * Q_ + q0) * D_;
    const __nv_bfloat16* aL = g_tgtL + ((size_t)b * Q_ + q0) * D_;
    const __nv_bfloat16* bH = g_srcH + (size_t)nb * L_ * D_;
    const __nv_bfloat16* bL = g_srcL + (size_t)nb * L_ * D_;

    auto prefetch = [&](int c) {
        const int kd = c * 32;
        const uint32_t sbase = sb + (c % 3) * BUF64;
        #pragma unroll
        for (int i = 0; i < 8; i++) {
            int idx = t + i * 256;
            int pl = idx >> 9;
            int p2 = idx & 511;
            int row = p2 >> 2, c4 = p2 & 3;
            const __nv_bfloat16* sp =
                (pl == 0) ? aH : (pl == 1) ? aL : (pl == 2) ? bH : bL;
            cp16(sbase + pl * PLANE64 + swz(row, c4),
                 sp + (size_t)row * D_ + kd + c4 * 8);
        }
        CP_COMMIT();
    };

    float acc[16][4] = {};

    prefetch(0); prefetch(1);
    for (int c = 0; c < NCH; c++) {
        if (c + 1 < NCH) CP_WAIT(1); else CP_WAIT(0);
        __syncthreads();
        if (c + 2 < NCH) prefetch(c + 2);
        const uint32_t sbase = sb + (c % 3) * BUF64;
        #pragma unroll
        for (int kh = 0; kh < 2; kh++) {
            uint32_t ah[2][4], al[2][4];
            #pragma unroll
            for (int m = 0; m < 2; m++) {
                uint32_t addr = sbase + swz(qw + m * 16 + (lane & 15),
                                            kh * 2 + (lane >> 4));
                ldsm_x4(ah[m][0], ah[m][1], ah[m][2], ah[m][3], addr);
                ldsm_x4(al[m][0], al[m][1], al[m][2], al[m][3], addr + PLANE64);
            }
            const int nrow = (lane & 7) + ((lane >> 4) << 3);
            const int nc4  = kh * 2 + ((lane >> 3) & 1);
            #pragma unroll
            for (int jj = 0; jj < 4; jj++) {
                uint32_t addr = sbase + 2 * PLANE64 + swz(lw + jj * 16 + nrow, nc4);
                uint32_t bh[4], bl[4];
                ldsm_x4(bh[0], bh[1], bh[2], bh[3], addr);
                ldsm_x4(bl[0], bl[1], bl[2], bl[3], addr + PLANE64);
                mma_group(acc, jj, ah, al, bh, bl);
            }
        }
    }
    __syncthreads();
    #pragma unroll
    for (int m = 0; m < 2; m++)
        #pragma unroll
        for (int j = 0; j < 8; j++) {
            int qr  = qw + m * 16 + (lane >> 2);
            int col = lw + j * 8 + (lane & 3) * 2;
            float* d = acc[m * 8 + j];
            logits[qr * LSTRIDE + col]           = d[0];
            logits[qr * LSTRIDE + col + 1]       = d[1];
            logits[(qr + 8) * LSTRIDE + col]     = d[2];
            logits[(qr + 8) * LSTRIDE + col + 1] = d[3];
        }
    __syncthreads();
    {
        // softmax: 2 lanes per row; exp kept in smem; per-row inv stored
        const int row = t >> 1, half = t & 1;
        float* rp = logits + row * LSTRIDE + half * 64;
        float m = rp[0];
        #pragma unroll 8
        for (int j = 1; j < 64; j++) m = fmaxf(m, rp[j]);
        m = fmaxf(m, __shfl_xor_sync(0xffffffffu, m, 1));
        float s = 0.f;
        #pragma unroll 8
        for (int j = 0; j < 64; j++) {
            float ev = __expf(rp[j] - m);
            rp[j] = ev;
            s += ev;
        }
        s += __shfl_xor_sync(0xffffffffu, s, 1);
        if (half == 0) sinv[row] = 1.0f / s;
    }
    __syncthreads();
    // coalesced w store: consecutive lanes -> consecutive column pairs
    #pragma unroll
    for (int i = 0; i < 32; i++) {
        int p = t + i * 256;
        int row = p >> 6;
        int col = (p & 63) * 2;
        float iv = sinv[row];
        st_pair(g_wH, g_wL, (((size_t)b * Q_ + q0 + row) * N_ + n) * L_ + col,
                logits[row * LSTRIDE + col] * iv,
                logits[row * LSTRIDE + col + 1] * iv);
    }
}

// ---------------------------------------------------------------------------
// K4 (mma.sync): S2[e,l] = sum_d Wcat[e, n*D+d] * src[l,d] -> bf16 hi/lo
// 3-buffer single-sync pipeline; staged coalesced store.
// ---------------------------------------------------------------------------
__global__ void __launch_bounds__(256, 2) k_s2_mma() {
    extern __shared__ __align__(16) char smem[];
    const uint32_t sb = smem_u32(smem);
    const int t = threadIdx.x;
    const int lane = t & 31, wid = t >> 5;
    const int qw = (wid & 3) * 32;   // e dir
    const int lw = (wid >> 2) * 64;  // l dir
    const int nb = blockIdx.y;
    const int n = nb >> 5, b = nb & 31;
    const int e0 = blockIdx.x * 128;

    const __nv_bfloat16* aH = g_WcatH + (size_t)e0 * ND_ + n * D_;
    const __nv_bfloat16* aL = g_WcatL + (size_t)e0 * ND_ + n * D_;
    const __nv_bfloat16* bH = g_srcH + (size_t)nb * L_ * D_;
    const __nv_bfloat16* bL = g_srcL + (size_t)nb * L_ * D_;

    auto prefetch = [&](int c) {
        const int kd = c * 32;
        const uint32_t sbase = sb + (c % 3) * BUF64;
        #pragma unroll
        for (int i = 0; i < 8; i++) {
            int idx = t + i * 256;
            int pl = idx >> 9;
            int p2 = idx & 511;
            int row = p2 >> 2, c4 = p2 & 3;
            const __nv_bfloat16* sp;
            size_t stride;
            if (pl < 2) { sp = pl ? aL : aH; stride = ND_; }
            else        { sp = (pl == 3) ? bL : bH; stride = D_; }
            cp16(sbase + pl * PLANE64 + swz(row, c4),
                 sp + (size_t)row * stride + kd + c4 * 8);
        }
        CP_COMMIT();
    };

    float acc[16][4] = {};

    prefetch(0); prefetch(1);
    for (int c = 0; c < NCH; c++) {
        if (c + 1 < NCH) CP_WAIT(1); else CP_WAIT(0);
        __syncthreads();
        if (c + 2 < NCH) prefetch(c + 2);
        const uint32_t sbase = sb + (c % 3) * BUF64;
        #pragma unroll
        for (int kh = 0; kh < 2; kh++) {
            uint32_t ah[2][4], al[2][4];
            #pragma unroll
            for (int m = 0; m < 2; m++) {
                uint32_t addr = sbase + swz(qw + m * 16 + (lane & 15),
                                            kh * 2 + (lane >> 4));
                ldsm_x4(ah[m][0], ah[m][1], ah[m][2], ah[m][3], addr);
                ldsm_x4(al[m][0], al[m][1], al[m][2], al[m][3], addr + PLANE64);
            }
            const int nrow = (lane & 7) + ((lane >> 4) << 3);
            const int nc4  = kh * 2 + ((lane >> 3) & 1);
            #pragma unroll
            for (int jj = 0; jj < 4; jj++) {
                uint32_t addr = sbase + 2 * PLANE64 + swz(lw + jj * 16 + nrow, nc4);
                uint32_t bh[4], bl[4];
                ldsm_x4(bh[0], bh[1], bh[2], bh[3], addr);
                ldsm_x4(bl[0], bl[1], bl[2], bl[3], addr + PLANE64);
                mma_group(acc, jj, ah, al, bh, bl);
            }
        }
    }
    // stage to smem, then coalesced store (rows=e, cols=l)
    __syncthreads();
    float* sx = (float*)smem;
    #pragma unroll
    for (int m = 0; m < 2; m++)
        #pragma unroll
        for (int j = 0; j < 8; j++) {
            int er  = qw + m * 16 + (lane >> 2);
            int col = lw + j * 8 + (lane & 3) * 2;
            float* d = acc[m * 8 + j];
            sx[er * 128 + col]           = d[0];
            sx[er * 128 + col + 1]       = d[1];
            sx[(er + 8) * 128 + col]     = d[2];
            sx[(er + 8) * 128 + col + 1] = d[3];
        }
    __syncthreads();
    #pragma unroll
    for (int i = 0; i < 32; i++) {
        int p = t + i * 256;
        int row = p >> 6;
        int col = (p & 63) * 2;
        st_pair(g_s2H, g_s2L,
                (((size_t)b * D_ + e0 + row) * N_ + n) * L_ + col,
                sx[row * 128 + col], sx[row * 128 + col + 1]);
    }
}

// ---------------------------------------------------------------------------
// K5 (mma.sync): x[q,e] = sum_k w[q,k]*s2[e,k], K=1280, tile 128q x 256e.
// 512 threads (16 warps: 4 along q, 4 along e), swizzled 64B rows,
// 2-buffer single-sync pipeline, 1 CTA/SM.
// Epilogue: stage x to smem, then bias+relu+residual+LayerNorm -> out.
// ---------------------------------------------------------------------------
constexpr int O_APL  = 128 * 64;       // 8192  (A plane: 128 q rows x 64B)
constexpr int O_BPL  = 256 * 64;       // 16384 (B plane: 256 e rows x 64B)
constexpr int O_BUF  = 2 * O_APL + 2 * O_BPL;  // 49152
constexpr int O_NCH  = K2_ / 32;       // 40
constexpr int XS     = 260;            // x staging row stride (floats)
constexpr int O_SMEM = 128 * XS * 4;   // 133120 (> 2*O_BUF = 98304)

__global__ void __launch_bounds__(512, 1) k_out_mma(const float* __restrict__ Wb,
                                                    const float* __restrict__ gamma,
                                                    const float* __restrict__ beta,
                                                    float* __restrict__ out) {
    extern __shared__ __align__(16) char smem[];
    const uint32_t sb = smem_u32(smem);
    const int t = threadIdx.x;
    const int lane = t & 31, wid = t >> 5;
    const int qw = (wid & 3) * 32;   // q dir (4 warps)
    const int ew = (wid >> 2) * 64;  // e dir (4 warps)
    const int b  = blockIdx.y;
    const int q0 = blockIdx.x * 128;

    const __nv_bfloat16* wHp = g_wH + ((size_t)b * Q_ + q0) * K2_;
    const __nv_bfloat16* wLp = g_wL + ((size_t)b * Q_ + q0) * K2_;
    const __nv_bfloat16* sHp = g_s2H + (size_t)b * D_ * K2_;
    const __nv_bfloat16* sLp = g_s2L + (size_t)b * D_ * K2_;

    auto prefetch = [&](int c) {
        const int k0 = c * 32;
        const uint32_t sbase = sb + (c & 1) * O_BUF;
        #pragma unroll
        for (int i = 0; i < 6; i++) {
            int idx = t + i * 512;           // 3072 pieces total
            if (idx < 1024) {                // A planes: 2 x 128 rows x 4 c4
                int pl = idx >> 9, p = idx & 511, row = p >> 2, c4 = p & 3;
                const __nv_bfloat16* sp = pl ? wLp : wHp;
                cp16(sbase + pl * O_APL + swz(row, c4),
                     sp + (size_t)row * K2_ + k0 + c4 * 8);
            } else {                         // B planes: 2 x 256 rows x 4 c4
                int idx2 = idx - 1024;
                int pl = idx2 >> 10, p = idx2 & 1023, row = p >> 2, c4 = p & 3;
                const __nv_bfloat16* sp = pl ? sLp : sHp;
                cp16(sbase + 2 * O_APL + pl * O_BPL + swz(row, c4),
                     sp + (size_t)row * K2_ + k0 + c4 * 8);
            }
        }
        CP_COMMIT();
    };

    float acc[16][4] = {};

    prefetch(0);
    for (int c = 0; c < O_NCH; c++) {
        CP_WAIT(0);          // chunk c data arrived
        __syncthreads();     // compute(c-1) done everywhere -> its buffer free
        if (c + 1 < O_NCH) prefetch(c + 1);
        const uint32_t sbase = sb + (c & 1) * O_BUF;
        #pragma unroll
        for (int kh = 0; kh < 2; kh++) {
            uint32_t ah[2][4], al[2][4];
            #pragma unroll
            for (int m = 0; m < 2; m++) {
                uint32_t addr = sbase + swz(qw + m * 16 + (lane & 15),
                                            kh * 2 + (lane >> 4));
                ldsm_x4(ah[m][0], ah[m][1], ah[m][2], ah[m][3], addr);
                ldsm_x4(al[m][0], al[m][1], al[m][2], al[m][3], addr + O_APL);
            }
            const int nrow = (lane & 7) + ((lane >> 4) << 3);
            const int nc4  = kh * 2 + ((lane >> 3) & 1);
            #pragma unroll
            for (int jj = 0; jj < 4; jj++) {
                uint32_t addr = sbase + 2 * O_APL + swz(ew + jj * 16 + nrow, nc4);
                uint32_t bh[4], bl[4];
                ldsm_x4(bh[0], bh[1], bh[2], bh[3], addr);
                ldsm_x4(bl[0], bl[1], bl[2], bl[3], addr + O_BPL);
                mma_group(acc, jj, ah, al, bh, bl);
            }
        }
    }
    __syncthreads();   // all tile reads done; safe to overwrite with staging
    float* sx = (float*)smem;
    #pragma unroll
    for (int m = 0; m < 2; m++)
        #pragma unroll
        for (int j = 0; j < 8; j++) {
            int qr  = qw + m * 16 + (lane >> 2);
            int col = ew + j * 8 + (lane & 3) * 2;
            float* d = acc[m * 8 + j];
            sx[qr * XS + col]           = d[0];
            sx[qr * XS + col + 1]       = d[1];
            sx[(qr + 8) * XS + col]     = d[2];
            sx[(qr + 8) * XS + col + 1] = d[3];
        }
    __syncthreads();
    float wb[8], gm[8], be[8];
    {
        float4 w0 = *(const float4*)&Wb[lane * 4];
        float4 w1 = *(const float4*)&Wb[lane * 4 + 128];
        float4 g0 = *(const float4*)&gamma[lane * 4];
        float4 g1 = *(const float4*)&gamma[lane * 4 + 128];
        float4 e0 = *(const float4*)&beta[lane * 4];
        float4 e1 = *(const float4*)&beta[lane * 4 + 128];
        wb[0]=w0.x; wb[1]=w0.y; wb[2]=w0.z; wb[3]=w0.w; wb[4]=w1.x; wb[5]=w1.y; wb[6]=w1.z; wb[7]=w1.w;
        gm[0]=g0.x; gm[1]=g0.y; gm[2]=g0.z; gm[3]=g0.w; gm[4]=g1.x; gm[5]=g1.y; gm[6]=g1.z; gm[7]=g1.w;
        be[0]=e0.x; be[1]=e0.y; be[2]=e0.z; be[3]=e0.w; be[4]=e1.x; be[5]=e1.y; be[6]=e1.z; be[7]=e1.w;
    }
    const __nv_bfloat16* tH = g_tgtH + (size_t)b * Q_ * D_;
    const __nv_bfloat16* tL = g_tgtL + (size_t)b * Q_ * D_;
    #pragma unroll
    for (int i = 0; i < 8; i++) {
        const int r = wid * 8 + i;          // local q row (16 warps x 8 = 128)
        const int q = q0 + r;
        float4 a0 = *(const float4*)&sx[r * XS + lane * 4];
        float4 a1 = *(const float4*)&sx[r * XS + lane * 4 + 128];
        float av[8] = {a0.x, a0.y, a0.z, a0.w, a1.x, a1.y, a1.z, a1.w};
        float tv[8];
        rec4(tH, tL, (size_t)q * D_ + lane * 4, tv);
        rec4(tH, tL, (size_t)q * D_ + lane * 4 + 128, tv + 4);
        float v[8], s = 0.f;
        #pragma unroll
        for (int j = 0; j < 8; j++) {
            v[j] = fmaxf(av[j] + wb[j], 0.f) + tv[j];
            s += v[j];
        }
        s = warpSum32(s);
        const float mu = s * (1.0f / 256.0f);
        float d2 = 0.f;
        #pragma unroll
        for (int j = 0; j < 8; j++) { float dd = v[j] - mu; d2 += dd * dd; }
        d2 = warpSum32(d2);
        const float rs = rsqrtf(d2 * (1.0f / 256.0f));
        float o[8];
        #pragma unroll
        for (int j = 0; j < 8; j++) o[j] = (v[j] - mu) * rs * gm[j] + be[j];
        float* orow = out + (size_t)(b * Q_ + q) * D_;
        *(float4*)&orow[lane * 4]       = make_float4(o[0], o[1], o[2], o[3]);
        *(float4*)&orow[lane * 4 + 128] = make_float4(o[4], o[5], o[6], o[7]);
    }
}

// ---------------------------------------------------------------------------
extern "C" void kernel_launch(void* const* d_in, const int* in_sizes, int n_in,
                              void* d_out, int out_size) {
    const float* input    = (const float*)d_in[0];  // [B, D, 32, 32]
    const float* contexts = (const float*)d_in[1];  // [N, B, C, L]
    const float* Wc       = (const float*)d_in[2];  // [D, C]
    const float* Wcat     = (const float*)d_in[3];  // [D, N*D]
    const float* Wb       = (const float*)d_in[4];  // [D]
    const float* gamma    = (const float*)d_in[5];  // [D]
    const float* beta     = (const float*)d_in[6];  // [D]
    float* out = (float*)d_out;                     // [B, Q, D]

    cudaFuncSetAttribute(k_source_mma, cudaFuncAttributeMaxDynamicSharedMemorySize, MMA_SMEM);
    cudaFuncSetAttribute(k_attn_mma,   cudaFuncAttributeMaxDynamicSharedMemorySize, MMA_SMEM);
    cudaFuncSetAttribute(k_s2_mma,     cudaFuncAttributeMaxDynamicSharedMemorySize, MMA_SMEM);
    cudaFuncSetAttribute(k_out_mma,    cudaFuncAttributeMaxDynamicSharedMemorySize, O_SMEM);

    k_transpose <<<dim3(Q_ / 32, D_ / 32, B_), dim3(32, 8)>>>(input);
    k_splitW    <<<D_ * ND_ / 1024, 256>>>(Wcat);
    k_splitWc   <<<D_ * C_ / 1024, 256>>>(Wc);
    k_ctxT      <<<dim3(L_ / 32, C_ / 32, N_ * B_), dim3(32, 8)>>>(contexts);
    k_source_mma<<<dim3(2,        N_ * B_),    256, MMA_SMEM>>>();
    k_attn_mma  <<<dim3(Q_ / 128, N_ * B_),    256, MMA_SMEM>>>();
    k_s2_mma    <<<dim3(2,        N_ * B_),    256, MMA_SMEM>>>();
    k_out_mma   <<<dim3(Q_ / 128, B_),         512, O_SMEM>>>(Wb, gamma, beta, out);
}

// round 15
// speedup vs baseline: 4.0602x; 1.2097x over previous
#include <cuda_runtime.h>
#include <cuda_bf16.h>
#include <cstdint>

// Problem dims (fixed by the reference)
constexpr int B_  = 32;
constexpr int D_  = 256;   // idf
constexpr int Q_  = 1024;  // ih*iw
constexpr int C_  = 512;   // cdf
constexpr int L_  = 128;
constexpr int N_  = 10;    // contexts
constexpr int K2_ = N_ * L_;  // 1280
constexpr int ND_ = N_ * D_;  // 2560

// Scratch (static device globals — no allocation in kernel_launch)
// bf16 split pairs (tensor-core operands); w and s2 are single-bf16.
__device__ __align__(16) __nv_bfloat16 g_tgtH[(size_t)B_ * Q_ * D_];
__device__ __align__(16) __nv_bfloat16 g_tgtL[(size_t)B_ * Q_ * D_];
__device__ __align__(16) __nv_bfloat16 g_srcH[(size_t)N_ * B_ * L_ * D_];
__device__ __align__(16) __nv_bfloat16 g_srcL[(size_t)N_ * B_ * L_ * D_];
__device__ __align__(16) __nv_bfloat16 g_wH [(size_t)B_ * Q_ * N_ * L_];
__device__ __align__(16) __nv_bfloat16 g_s2H[(size_t)B_ * D_ * N_ * L_];
__device__ __align__(16) __nv_bfloat16 g_WcatH[(size_t)D_ * ND_];
__device__ __align__(16) __nv_bfloat16 g_WcatL[(size_t)D_ * ND_];
__device__ __align__(16) __nv_bfloat16 g_WcH[(size_t)D_ * C_];
__device__ __align__(16) __nv_bfloat16 g_WcL[(size_t)D_ * C_];
__device__ __align__(16) __nv_bfloat16 g_ctxTH[(size_t)N_ * B_ * L_ * C_];
__device__ __align__(16) __nv_bfloat16 g_ctxTL[(size_t)N_ * B_ * L_ * C_];

typedef unsigned long long u64;

__device__ __forceinline__ float warpSum32(float v) {
    #pragma unroll
    for (int o = 16; o; o >>= 1) v += __shfl_xor_sync(0xffffffffu, v, o);
    return v;
}

// ---- bf16 split helpers ----
__device__ __forceinline__ void split1(float x, __nv_bfloat16& h, __nv_bfloat16& l) {
    h = __float2bfloat16(x);
    l = __float2bfloat16(x - __bfloat162float(h));
}
__device__ __forceinline__ void st_pair(__nv_bfloat16* H, __nv_bfloat16* L,
                                        size_t off, float x0, float x1) {
    __nv_bfloat16 h0, l0, h1, l1;
    split1(x0, h0, l0); split1(x1, h1, l1);
    uint32_t hu = (uint32_t)__bfloat16_as_ushort(h0) |
                  ((uint32_t)__bfloat16_as_ushort(h1) << 16);
    uint32_t lu = (uint32_t)__bfloat16_as_ushort(l0) |
                  ((uint32_t)__bfloat16_as_ushort(l1) << 16);
    *(uint32_t*)&H[off] = hu;
    *(uint32_t*)&L[off] = lu;
}
// single-bf16 pair store
__device__ __forceinline__ void st_one(__nv_bfloat16* H, size_t off,
                                       float x0, float x1) {
    *(__nv_bfloat162*)&H[off] = __floats2bfloat162_rn(x0, x1);
}
// reconstruct 4 fp32 from bf16 hi/lo pairs at off
__device__ __forceinline__ void rec4(const __nv_bfloat16* __restrict__ H,
                                     const __nv_bfloat16* __restrict__ L,
                                     size_t off, float* o) {
    #pragma unroll
    for (int k = 0; k < 2; k++) {
        float2 h = __bfloat1622float2(*(const __nv_bfloat162*)&H[off + 2 * k]);
        float2 l = __bfloat1622float2(*(const __nv_bfloat162*)&L[off + 2 * k]);
        o[2 * k]     = h.x + l.x;
        o[2 * k + 1] = h.y + l.y;
    }
}

// ---- warp-level tensor core helpers (sm_80 baseline; no 'a' features) ----
__device__ __forceinline__ uint32_t smem_u32(const void* p) {
    uint32_t a;
    asm("{ .reg .u64 t; cvta.to.shared.u64 t, %1; cvt.u32.u64 %0, t; }" : "=r"(a) : "l"(p));
    return a;
}
__device__ __forceinline__ void ldsm_x4(uint32_t& r0, uint32_t& r1, uint32_t& r2,
                                        uint32_t& r3, uint32_t a) {
    asm volatile("ldmatrix.sync.aligned.m8n8.x4.shared.b16 {%0,%1,%2,%3}, [%4];"
                 : "=r"(r0), "=r"(r1), "=r"(r2), "=r"(r3) : "r"(a));
}
__device__ __forceinline__ void mma_bf16(float* d, const uint32_t* a, const uint32_t* b) {
    asm volatile("mma.sync.aligned.m16n8k16.row.col.f32.bf16.bf16.f32 "
        "{%0,%1,%2,%3}, {%4,%5,%6,%7}, {%8,%9}, {%0,%1,%2,%3};"
        : "+f"(d[0]), "+f"(d[1]), "+f"(d[2]), "+f"(d[3])
        : "r"(a[0]), "r"(a[1]), "r"(a[2]), "r"(a[3]), "r"(b[0]), "r"(b[1]));
}
__device__ __forceinline__ void cp16(uint32_t saddr, const void* gaddr) {
    asm volatile("cp.async.cg.shared.global [%0], [%1], 16;"
                 :: "r"(saddr), "l"(gaddr) : "memory");
}
#define CP_COMMIT() asm volatile("cp.async.commit_group;" ::: "memory")
#define CP_WAIT(n)  asm volatile("cp.async.wait_group %0;" :: "n"(n) : "memory")

// XOR-swizzled 64B-row tile offset
__device__ __forceinline__ uint32_t swz(int row, int c4) {
    return (uint32_t)(row * 64 + ((c4 ^ ((row >> 1) & 3)) << 4));
}

// 3-term split MMA for one jj-group, term-outer ordering
__device__ __forceinline__ void mma_group(float (*acc)[4], int jj,
                                          uint32_t (&ah)[2][4], uint32_t (&al)[2][4],
                                          const uint32_t* bh, const uint32_t* bl) {
    #pragma unroll
    for (int m = 0; m < 2; m++)
        #pragma unroll
        for (int jb = 0; jb < 2; jb++)
            mma_bf16(acc[m * 8 + jj * 2 + jb], ah[m], bh + jb * 2);
    #pragma unroll
    for (int m = 0; m < 2; m++)
        #pragma unroll
        for (int jb = 0; jb < 2; jb++)
            mma_bf16(acc[m * 8 + jj * 2 + jb], ah[m], bl + jb * 2);
    #pragma unroll
    for (int m = 0; m < 2; m++)
        #pragma unroll
        for (int jb = 0; jb < 2; jb++)
            mma_bf16(acc[m * 8 + jj * 2 + jb], al[m], bh + jb * 2);
}

// ---------------------------------------------------------------------------
// K1: transpose input [B][D][Q] -> g_tgtH/L bf16 split, [B][Q][D]
// ---------------------------------------------------------------------------
__global__ void __launch_bounds__(256) k_transpose(const float* __restrict__ in) {
    __shared__ float tile[32][33];
    const int b  = blockIdx.z;
    const int q0 = blockIdx.x * 32;
    const int d0 = blockIdx.y * 32;
    const int tx = threadIdx.x, ty = threadIdx.y;  // 32 x 8
    #pragma unroll
    for (int j = 0; j < 4; j++)
        tile[ty + j * 8][tx] = in[((size_t)b * D_ + d0 + ty + j * 8) * Q_ + q0 + tx];
    __syncthreads();
    #pragma unroll
    for (int j = 0; j < 4; j++) {
        float x = tile[tx][ty + j * 8];
        size_t idx = ((size_t)b * Q_ + q0 + ty + j * 8) * D_ + d0 + tx;
        __nv_bfloat16 h, l; split1(x, h, l);
        g_tgtH[idx] = h; g_tgtL[idx] = l;
    }
}

// K1b/K1c: split weights fp32 -> bf16 hi/lo
__global__ void __launch_bounds__(256) k_splitW(const float* __restrict__ Wcat) {
    int idx = blockIdx.x * 1024 + threadIdx.x * 4;
    #pragma unroll
    for (int i = 0; i < 4; i++) {
        float x = Wcat[idx + i];
        __nv_bfloat16 h, l; split1(x, h, l);
        g_WcatH[idx + i] = h; g_WcatL[idx + i] = l;
    }
}
__global__ void __launch_bounds__(256) k_splitWc(const float* __restrict__ Wc) {
    int idx = blockIdx.x * 1024 + threadIdx.x * 4;
    #pragma unroll
    for (int i = 0; i < 4; i++) {
        float x = Wc[idx + i];
        __nv_bfloat16 h, l; split1(x, h, l);
        g_WcH[idx + i] = h; g_WcL[idx + i] = l;
    }
}

// K1d: transpose+split contexts [nb][c][l] fp32 -> g_ctxTH/L [nb][l][c] bf16
__global__ void __launch_bounds__(256) k_ctxT(const float* __restrict__ ctx) {
    __shared__ float tile[32][33];
    const int nb = blockIdx.z;
    const int l0 = blockIdx.x * 32;
    const int c0 = blockIdx.y * 32;
    const int tx = threadIdx.x, ty = threadIdx.y;  // 32 x 8
    const float* cp = ctx + (size_t)nb * C_ * L_;
    #pragma unroll
    for (int j = 0; j < 4; j++)
        tile[ty + j * 8][tx] = cp[(size_t)(c0 + ty + j * 8) * L_ + l0 + tx];
    __syncthreads();
    #pragma unroll
    for (int j = 0; j < 4; j++) {
        float x = tile[tx][ty + j * 8];
        size_t idx = ((size_t)nb * L_ + l0 + ty + j * 8) * C_ + c0 + tx;
        __nv_bfloat16 h, l; split1(x, h, l);
        g_ctxTH[idx] = h; g_ctxTL[idx] = l;
    }
}

// ---------------------------------------------------------------------------
// Shared tile constants for the 128x128 mma kernels (swizzled 64B rows, 3 bufs)
// ---------------------------------------------------------------------------
constexpr int PLANE64 = 128 * 64;        // 8192
constexpr int BUF64   = 4 * PLANE64;     // 32768
constexpr int MMA_SMEM = 3 * BUF64;      // 98304 (staging/logits reuse it)
constexpr int LSTRIDE = 129;
constexpr int NCH = 8;                   // K=256 in chunks of 32

// ---------------------------------------------------------------------------
// K2 (mma.sync): src[l,d] = sum_c ctxT[l,c] * Wc[d,c]  (3-term bf16 split)
// tile 128 l (M) x 128 d (N), K = 512 in 16 chunks; 3-buffer single-sync.
// ---------------------------------------------------------------------------
constexpr int SRC_NCH = C_ / 32;  // 16

__global__ void __launch_bounds__(256, 2) k_source_mma() {
    extern __shared__ __align__(16) char smem[];
    const uint32_t sb = smem_u32(smem);
    const int t = threadIdx.x;
    const int lane = t & 31, wid = t >> 5;
    const int qw = (wid & 3) * 32;   // l dir (M)
    const int lw = (wid >> 2) * 64;  // d dir (N)
    const int nb = blockIdx.y;
    const int d0 = blockIdx.x * 128;

    const __nv_bfloat16* aH = g_ctxTH + (size_t)nb * L_ * C_;
    const __nv_bfloat16* aL = g_ctxTL + (size_t)nb * L_ * C_;
    const __nv_bfloat16* bH = g_WcH + (size_t)d0 * C_;
    const __nv_bfloat16* bL = g_WcL + (size_t)d0 * C_;

    auto prefetch = [&](int c) {
        const int kd = c * 32;
        const uint32_t sbase = sb + (c % 3) * BUF64;
        #pragma unroll
        for (int i = 0; i < 8; i++) {
            int idx = t + i * 256;
            int pl = idx >> 9;
            int p2 = idx & 511;
            int row = p2 >> 2, c4 = p2 & 3;
            const __nv_bfloat16* sp =
                (pl == 0) ? aH : (pl == 1) ? aL : (pl == 2) ? bH : bL;
            cp16(sbase + pl * PLANE64 + swz(row, c4),
                 sp + (size_t)row * C_ + kd + c4 * 8);
        }
        CP_COMMIT();
    };

    float acc[16][4] = {};

    prefetch(0); prefetch(1);
    for (int c = 0; c < SRC_NCH; c++) {
        if (c + 1 < SRC_NCH) CP_WAIT(1); else CP_WAIT(0);
        __syncthreads();
        if (c + 2 < SRC_NCH) prefetch(c + 2);
        const uint32_t sbase = sb + (c % 3) * BUF64;
        #pragma unroll
        for (int kh = 0; kh < 2; kh++) {
            uint32_t ah[2][4], al[2][4];
            #pragma unroll
            for (int m = 0; m < 2; m++) {
                uint32_t addr = sbase + swz(qw + m * 16 + (lane & 15),
                                            kh * 2 + (lane >> 4));
                ldsm_x4(ah[m][0], ah[m][1], ah[m][2], ah[m][3], addr);
                ldsm_x4(al[m][0], al[m][1], al[m][2], al[m][3], addr + PLANE64);
            }
            const int nrow = (lane & 7) + ((lane >> 4) << 3);
            const int nc4  = kh * 2 + ((lane >> 3) & 1);
            #pragma unroll
            for (int jj = 0; jj < 4; jj++) {
                uint32_t addr = sbase + 2 * PLANE64 + swz(lw + jj * 16 + nrow, nc4);
                uint32_t bh[4], bl[4];
                ldsm_x4(bh[0], bh[1], bh[2], bh[3], addr);
                ldsm_x4(bl[0], bl[1], bl[2], bl[3], addr + PLANE64);
                mma_group(acc, jj, ah, al, bh, bl);
            }
        }
    }
    // stage to smem, then coalesced store (src keeps hi/lo — feeds 3-term GEMMs)
    __syncthreads();
    float* sx = (float*)smem;
    #pragma unroll
    for (int m = 0; m < 2; m++)
        #pragma unroll
        for (int j = 0; j < 8; j++) {
            int lr  = qw + m * 16 + (lane >> 2);
            int col = lw + j * 8 + (lane & 3) * 2;
            float* d = acc[m * 8 + j];
            sx[lr * 128 + col]           = d[0];
            sx[lr * 128 + col + 1]       = d[1];
            sx[(lr + 8) * 128 + col]     = d[2];
            sx[(lr + 8) * 128 + col + 1] = d[3];
        }
    __syncthreads();
    #pragma unroll
    for (int i = 0; i < 32; i++) {
        int p = t + i * 256;           // 8192 pairs
        int row = p >> 6;
        int col = (p & 63) * 2;
        st_pair(g_srcH, g_srcL, ((size_t)nb * L_ + row) * D_ + d0 + col,
                sx[row * 128 + col], sx[row * 128 + col + 1]);
    }
}

// ---------------------------------------------------------------------------
// K3 (mma.sync): logits[128q,128l] = tgt·src^T, softmax, w as single bf16.
// 3-buffer single-sync pipeline; 256-thread softmax; coalesced w store.
// ---------------------------------------------------------------------------
__global__ void __launch_bounds__(256, 2) k_attn_mma() {
    extern __shared__ __align__(16) char smem[];
    float* logits = (float*)smem;
    float* sinv   = logits + 128 * LSTRIDE;   // 128 floats
    const uint32_t sb = smem_u32(smem);
    const int t = threadIdx.x;
    const int lane = t & 31, wid = t >> 5;
    const int qw = (wid & 3) * 32;
    const int lw = (wid >> 2) * 64;
    const int nb = blockIdx.y;
    const int n = nb >> 5, b = nb & 31;
    const int q0 = blockIdx.x * 128;

    const __nv_bfloat16* aH = g_tgtH + ((size_t)b * Q_ + q0) * D_;
    const __nv_bfloat16* aL = g_tgtL + ((size_t)b * Q_ + q0) * D_;
    const __nv_bfloat16* bH = g_srcH + (size_t)nb * L_ * D_;
    const __nv_bfloat16* bL = g_srcL + (size_t)nb * L_ * D_;

    auto prefetch = [&](int c) {
        const int kd = c * 32;
        const uint32_t sbase = sb + (c % 3) * BUF64;
        #pragma unroll
        for (int i = 0; i < 8; i++) {
            int idx = t + i * 256;
            int pl = idx >> 9;
            int p2 = idx & 511;
            int row = p2 >> 2, c4 = p2 & 3;
            const __nv_bfloat16* sp =
                (pl == 0) ? aH : (pl == 1) ? aL : (pl == 2) ? bH : bL;
            cp16(sbase + pl * PLANE64 + swz(row, c4),
                 sp + (size_t)row * D_ + kd + c4 * 8);
        }
        CP_COMMIT();
    };

    float acc[16][4] = {};

    prefetch(0); prefetch(1);
    for (int c = 0; c < NCH; c++) {
        if (c + 1 < NCH) CP_WAIT(1); else CP_WAIT(0);
        __syncthreads();
        if (c + 2 < NCH) prefetch(c + 2);
        const uint32_t sbase = sb + (c % 3) * BUF64;
        #pragma unroll
        for (int kh = 0; kh < 2; kh++) {
            uint32_t ah[2][4], al[2][4];
            #pragma unroll
            for (int m = 0; m < 2; m++) {
                uint32_t addr = sbase + swz(qw + m * 16 + (lane & 15),
                                            kh * 2 + (lane >> 4));
                ldsm_x4(ah[m][0], ah[m][1], ah[m][2], ah[m][3], addr);
                ldsm_x4(al[m][0], al[m][1], al[m][2], al[m][3], addr + PLANE64);
            }
            const int nrow = (lane & 7) + ((lane >> 4) << 3);
            const int nc4  = kh * 2 + ((lane >> 3) & 1);
            #pragma unroll
            for (int jj = 0; jj < 4; jj++) {
                uint32_t addr = sbase + 2 * PLANE64 + swz(lw + jj * 16 + nrow, nc4);
                uint32_t bh[4], bl[4];
                ldsm_x4(bh[0], bh[1], bh[2], bh[3], addr);
                ldsm_x4(bl[0], bl[1], bl[2], bl[3], addr + PLANE64);
                mma_group(acc, jj, ah, al, bh, bl);
            }
        }
    }
    __syncthreads();
    #pragma unroll
    for (int m = 0; m < 2; m++)
        #pragma unroll
        for (int j = 0; j < 8; j++) {
            int qr  = qw + m * 16 + (lane >> 2);
            int col = lw + j * 8 + (lane & 3) * 2;
            float* d = acc[m * 8 + j];
            logits[qr * LSTRIDE + col]           = d[0];
            logits[qr * LSTRIDE + col + 1]       = d[1];
            logits[(qr + 8) * LSTRIDE + col]     = d[2];
            logits[(qr + 8) * LSTRIDE + col + 1] = d[3];
        }
    __syncthreads();
    {
        // softmax: 2 lanes per row; exp kept in smem; per-row inv stored
        const int row = t >> 1, half = t & 1;
        float* rp = logits + row * LSTRIDE + half * 64;
        float m = rp[0];
        #pragma unroll 8
        for (int j = 1; j < 64; j++) m = fmaxf(m, rp[j]);
        m = fmaxf(m, __shfl_xor_sync(0xffffffffu, m, 1));
        float s = 0.f;
        #pragma unroll 8
        for (int j = 0; j < 64; j++) {
            float ev = __expf(rp[j] - m);
            rp[j] = ev;
            s += ev;
        }
        s += __shfl_xor_sync(0xffffffffu, s, 1);
        if (half == 0) sinv[row] = 1.0f / s;
    }
    __syncthreads();
    // coalesced single-bf16 w store
    #pragma unroll
    for (int i = 0; i < 32; i++) {
        int p = t + i * 256;
        int row = p >> 6;
        int col = (p & 63) * 2;
        float iv = sinv[row];
        st_one(g_wH, (((size_t)b * Q_ + q0 + row) * N_ + n) * L_ + col,
               logits[row * LSTRIDE + col] * iv,
               logits[row * LSTRIDE + col + 1] * iv);
    }
}

// ---------------------------------------------------------------------------
// K4 (mma.sync): S2[e,l] = sum_d Wcat[e, n*D+d] * src[l,d] -> single bf16
// 3-buffer single-sync pipeline; staged coalesced store.
// ---------------------------------------------------------------------------
__global__ void __launch_bounds__(256, 2) k_s2_mma() {
    extern __shared__ __align__(16) char smem[];
    const uint32_t sb = smem_u32(smem);
    const int t = threadIdx.x;
    const int lane = t & 31, wid = t >> 5;
    const int qw = (wid & 3) * 32;   // e dir
    const int lw = (wid >> 2) * 64;  // l dir
    const int nb = blockIdx.y;
    const int n = nb >> 5, b = nb & 31;
    const int e0 = blockIdx.x * 128;

    const __nv_bfloat16* aH = g_WcatH + (size_t)e0 * ND_ + n * D_;
    const __nv_bfloat16* aL = g_WcatL + (size_t)e0 * ND_ + n * D_;
    const __nv_bfloat16* bH = g_srcH + (size_t)nb * L_ * D_;
    const __nv_bfloat16* bL = g_srcL + (size_t)nb * L_ * D_;

    auto prefetch = [&](int c) {
        const int kd = c * 32;
        const uint32_t sbase = sb + (c % 3) * BUF64;
        #pragma unroll
        for (int i = 0; i < 8; i++) {
            int idx = t + i * 256;
            int pl = idx >> 9;
            int p2 = idx & 511;
            int row = p2 >> 2, c4 = p2 & 3;
            const __nv_bfloat16* sp;
            size_t stride;
            if (pl < 2) { sp = pl ? aL : aH; stride = ND_; }
            else        { sp = (pl == 3) ? bL : bH; stride = D_; }
            cp16(sbase + pl * PLANE64 + swz(row, c4),
                 sp + (size_t)row * stride + kd + c4 * 8);
        }
        CP_COMMIT();
    };

    float acc[16][4] = {};

    prefetch(0); prefetch(1);
    for (int c = 0; c < NCH; c++) {
        if (c + 1 < NCH) CP_WAIT(1); else CP_WAIT(0);
        __syncthreads();
        if (c + 2 < NCH) prefetch(c + 2);
        const uint32_t sbase = sb + (c % 3) * BUF64;
        #pragma unroll
        for (int kh = 0; kh < 2; kh++) {
            uint32_t ah[2][4], al[2][4];
            #pragma unroll
            for (int m = 0; m < 2; m++) {
                uint32_t addr = sbase + swz(qw + m * 16 + (lane & 15),
                                            kh * 2 + (lane >> 4));
                ldsm_x4(ah[m][0], ah[m][1], ah[m][2], ah[m][3], addr);
                ldsm_x4(al[m][0], al[m][1], al[m][2], al[m][3], addr + PLANE64);
            }
            const int nrow = (lane & 7) + ((lane >> 4) << 3);
            const int nc4  = kh * 2 + ((lane >> 3) & 1);
            #pragma unroll
            for (int jj = 0; jj < 4; jj++) {
                uint32_t addr = sbase + 2 * PLANE64 + swz(lw + jj * 16 + nrow, nc4);
                uint32_t bh[4], bl[4];
                ldsm_x4(bh[0], bh[1], bh[2], bh[3], addr);
                ldsm_x4(bl[0], bl[1], bl[2], bl[3], addr + PLANE64);
                mma_group(acc, jj, ah, al, bh, bl);
            }
        }
    }
    // stage to smem, then coalesced single-bf16 store (rows=e, cols=l)
    __syncthreads();
    float* sx = (float*)smem;
    #pragma unroll
    for (int m = 0; m < 2; m++)
        #pragma unroll
        for (int j = 0; j < 8; j++) {
            int er  = qw + m * 16 + (lane >> 2);
            int col = lw + j * 8 + (lane & 3) * 2;
            float* d = acc[m * 8 + j];
            sx[er * 128 + col]           = d[0];
            sx[er * 128 + col + 1]       = d[1];
            sx[(er + 8) * 128 + col]     = d[2];
            sx[(er + 8) * 128 + col + 1] = d[3];
        }
    __syncthreads();
    #pragma unroll
    for (int i = 0; i < 32; i++) {
        int p = t + i * 256;
        int row = p >> 6;
        int col = (p & 63) * 2;
        st_one(g_s2H, (((size_t)b * D_ + e0 + row) * N_ + n) * L_ + col,
               sx[row * 128 + col], sx[row * 128 + col + 1]);
    }
}

// ---------------------------------------------------------------------------
// K5 (mma.sync): x[q,e] = sum_k w[q,k]*s2[e,k], K=1280, tile 128q x 256e.
// SINGLE-term bf16 GEMM (w and s2 are single-bf16 — precision analysis in
// header). 512 threads (16 warps: 4 q x 4 e), 2-buffer single-sync pipeline.
// Epilogue: stage x to smem, then bias+relu+residual+LayerNorm -> out.
// ---------------------------------------------------------------------------
constexpr int O_APL  = 128 * 64;       // 8192  (w plane: 128 q rows x 64B)
constexpr int O_BPL  = 256 * 64;       // 16384 (s2 plane: 256 e rows x 64B)
constexpr int O_BUF  = O_APL + O_BPL;  // 24576
constexpr int O_NCH  = K2_ / 32;       // 40
constexpr int XS     = 260;            // x staging row stride (floats)
constexpr int O_SMEM = 128 * XS * 4;   // 133120 (> 2*O_BUF = 49152)

__global__ void __launch_bounds__(512, 1) k_out_mma(const float* __restrict__ Wb,
                                                    const float* __restrict__ gamma,
                                                    const float* __restrict__ beta,
                                                    float* __restrict__ out) {
    extern __shared__ __align__(16) char smem[];
    const uint32_t sb = smem_u32(smem);
    const int t = threadIdx.x;
    const int lane = t & 31, wid = t >> 5;
    const int qw = (wid & 3) * 32;   // q dir (4 warps)
    const int ew = (wid >> 2) * 64;  // e dir (4 warps)
    const int b  = blockIdx.y;
    const int q0 = blockIdx.x * 128;

    const __nv_bfloat16* wHp = g_wH + ((size_t)b * Q_ + q0) * K2_;
    const __nv_bfloat16* sHp = g_s2H + (size_t)b * D_ * K2_;

    auto prefetch = [&](int c) {
        const int k0 = c * 32;
        const uint32_t sbase = sb + (c & 1) * O_BUF;
        #pragma unroll
        for (int i = 0; i < 3; i++) {
            int idx = t + i * 512;           // 1536 pieces total
            if (idx < 512) {                 // A plane: 128 rows x 4 c4
                int row = idx >> 2, c4 = idx & 3;
                cp16(sbase + swz(row, c4),
                     wHp + (size_t)row * K2_ + k0 + c4 * 8);
            } else {                         // B plane: 256 rows x 4 c4
                int idx2 = idx - 512;
                int row = idx2 >> 2, c4 = idx2 & 3;
                cp16(sbase + O_APL + swz(row, c4),
                     sHp + (size_t)row * K2_ + k0 + c4 * 8);
            }
        }
        CP_COMMIT();
    };

    float acc[16][4] = {};

    prefetch(0);
    for (int c = 0; c < O_NCH; c++) {
        CP_WAIT(0);          // chunk c data arrived
        __syncthreads();     // compute(c-1) done everywhere -> its buffer free
        if (c + 1 < O_NCH) prefetch(c + 1);
        const uint32_t sbase = sb + (c & 1) * O_BUF;
        #pragma unroll
        for (int kh = 0; kh < 2; kh++) {
            uint32_t ah[2][4];
            #pragma unroll
            for (int m = 0; m < 2; m++) {
                uint32_t addr = sbase + swz(qw + m * 16 + (lane & 15),
                                            kh * 2 + (lane >> 4));
                ldsm_x4(ah[m][0], ah[m][1], ah[m][2], ah[m][3], addr);
            }
            const int nrow = (lane & 7) + ((lane >> 4) << 3);
            const int nc4  = kh * 2 + ((lane >> 3) & 1);
            #pragma unroll
            for (int jj = 0; jj < 4; jj++) {
                uint32_t addr = sbase + O_APL + swz(ew + jj * 16 + nrow, nc4);
                uint32_t bh[4];
                ldsm_x4(bh[0], bh[1], bh[2], bh[3], addr);
                #pragma unroll
                for (int m = 0; m < 2; m++)
                    #pragma unroll
                    for (int jb = 0; jb < 2; jb++)
                        mma_bf16(acc[m * 8 + jj * 2 + jb], ah[m], bh + jb * 2);
            }
        }
    }
    __syncthreads();   // all tile reads done; safe to overwrite with staging
    float* sx = (float*)smem;
    #pragma unroll
    for (int m = 0; m < 2; m++)
        #pragma unroll
        for (int j = 0; j < 8; j++) {
            int qr  = qw + m * 16 + (lane >> 2);
            int col = ew + j * 8 + (lane & 3) * 2;
            float* d = acc[m * 8 + j];
            sx[qr * XS + col]           = d[0];
            sx[qr * XS + col + 1]       = d[1];
            sx[(qr + 8) * XS + col]     = d[2];
            sx[(qr + 8) * XS + col + 1] = d[3];
        }
    __syncthreads();
    float wb[8], gm[8], be[8];
    {
        float4 w0 = *(const float4*)&Wb[lane * 4];
        float4 w1 = *(const float4*)&Wb[lane * 4 + 128];
        float4 g0 = *(const float4*)&gamma[lane * 4];
        float4 g1 = *(const float4*)&gamma[lane * 4 + 128];
        float4 e0 = *(const float4*)&beta[lane * 4];
        float4 e1 = *(const float4*)&beta[lane * 4 + 128];
        wb[0]=w0.x; wb[1]=w0.y; wb[2]=w0.z; wb[3]=w0.w; wb[4]=w1.x; wb[5]=w1.y; wb[6]=w1.z; wb[7]=w1.w;
        gm[0]=g0.x; gm[1]=g0.y; gm[2]=g0.z; gm[3]=g0.w; gm[4]=g1.x; gm[5]=g1.y; gm[6]=g1.z; gm[7]=g1.w;
        be[0]=e0.x; be[1]=e0.y; be[2]=e0.z; be[3]=e0.w; be[4]=e1.x; be[5]=e1.y; be[6]=e1.z; be[7]=e1.w;
    }
    const __nv_bfloat16* tH = g_tgtH + (size_t)b * Q_ * D_;
    const __nv_bfloat16* tL = g_tgtL + (size_t)b * Q_ * D_;
    #pragma unroll
    for (int i = 0; i < 8; i++) {
        const int r = wid * 8 + i;          // local q row (16 warps x 8 = 128)
        const int q = q0 + r;
        float4 a0 = *(const float4*)&sx[r * XS + lane * 4];
        float4 a1 = *(const float4*)&sx[r * XS + lane * 4 + 128];
        float av[8] = {a0.x, a0.y, a0.z, a0.w, a1.x, a1.y, a1.z, a1.w};
        float tv[8];
        rec4(tH, tL, (size_t)q * D_ + lane * 4, tv);
        rec4(tH, tL, (size_t)q * D_ + lane * 4 + 128, tv + 4);
        float v[8], s = 0.f;
        #pragma unroll
        for (int j = 0; j < 8; j++) {
            v[j] = fmaxf(av[j] + wb[j], 0.f) + tv[j];
            s += v[j];
        }
        s = warpSum32(s);
        const float mu = s * (1.0f / 256.0f);
        float d2 = 0.f;
        #pragma unroll
        for (int j = 0; j < 8; j++) { float dd = v[j] - mu; d2 += dd * dd; }
        d2 = warpSum32(d2);
        const float rs = rsqrtf(d2 * (1.0f / 256.0f));
        float o[8];
        #pragma unroll
        for (int j = 0; j < 8; j++) o[j] = (v[j] - mu) * rs * gm[j] + be[j];
        float* orow = out + (size_t)(b * Q_ + q) * D_;
        *(float4*)&orow[lane * 4]       = make_float4(o[0], o[1], o[2], o[3]);
        *(float4*)&orow[lane * 4 + 128] = make_float4(o[4], o[5], o[6], o[7]);
    }
}

// ---------------------------------------------------------------------------
extern "C" void kernel_launch(void* const* d_in, const int* in_sizes, int n_in,
                              void* d_out, int out_size) {
    const float* input    = (const float*)d_in[0];  // [B, D, 32, 32]
    const float* contexts = (const float*)d_in[1];  // [N, B, C, L]
    const float* Wc       = (const float*)d_in[2];  // [D, C]
    const float* Wcat     = (const float*)d_in[3];  // [D, N*D]
    const float* Wb       = (const float*)d_in[4];  // [D]
    const float* gamma    = (const float*)d_in[5];  // [D]
    const float* beta     = (const float*)d_in[6];  // [D]
    float* out = (float*)d_out;                     // [B, Q, D]

    cudaFuncSetAttribute(k_source_mma, cudaFuncAttributeMaxDynamicSharedMemorySize, MMA_SMEM);
    cudaFuncSetAttribute(k_attn_mma,   cudaFuncAttributeMaxDynamicSharedMemorySize, MMA_SMEM);
    cudaFuncSetAttribute(k_s2_mma,     cudaFuncAttributeMaxDynamicSharedMemorySize, MMA_SMEM);
    cudaFuncSetAttribute(k_out_mma,    cudaFuncAttributeMaxDynamicSharedMemorySize, O_SMEM);

    k_transpose <<<dim3(Q_ / 32, D_ / 32, B_), dim3(32, 8)>>>(input);
    k_splitW    <<<D_ * ND_ / 1024, 256>>>(Wcat);
    k_splitWc   <<<D_ * C_ / 1024, 256>>>(Wc);
    k_ctxT      <<<dim3(L_ / 32, C_ / 32, N_ * B_), dim3(32, 8)>>>(contexts);
    k_source_mma<<<dim3(2,        N_ * B_),    256, MMA_SMEM>>>();
    k_attn_mma  <<<dim3(Q_ / 128, N_ * B_),    256, MMA_SMEM>>>();
    k_s2_mma    <<<dim3(2,        N_ * B_),    256, MMA_SMEM>>>();
    k_out_mma   <<<dim3(Q_ / 128, B_),         512, O_SMEM>>>(Wb, gamma, beta, out);
}

// round 16
// speedup vs baseline: 4.0880x; 1.0069x over previous
#include <cuda_runtime.h>
#include <cuda_bf16.h>
#include <cstdint>

// Problem dims (fixed by the reference)
constexpr int B_  = 32;
constexpr int D_  = 256;   // idf
constexpr int Q_  = 1024;  // ih*iw
constexpr int C_  = 512;   // cdf
constexpr int L_  = 128;
constexpr int N_  = 10;    // contexts
constexpr int K2_ = N_ * L_;  // 1280
constexpr int ND_ = N_ * D_;  // 2560

// Scratch (static device globals — no allocation in kernel_launch)
// bf16 split pairs (tensor-core operands); w and s2 are single-bf16.
__device__ __align__(16) __nv_bfloat16 g_tgtH[(size_t)B_ * Q_ * D_];
__device__ __align__(16) __nv_bfloat16 g_tgtL[(size_t)B_ * Q_ * D_];
__device__ __align__(16) __nv_bfloat16 g_srcH[(size_t)N_ * B_ * L_ * D_];
__device__ __align__(16) __nv_bfloat16 g_srcL[(size_t)N_ * B_ * L_ * D_];
__device__ __align__(16) __nv_bfloat16 g_wH [(size_t)B_ * Q_ * N_ * L_];
__device__ __align__(16) __nv_bfloat16 g_s2H[(size_t)B_ * D_ * N_ * L_];
__device__ __align__(16) __nv_bfloat16 g_WcatH[(size_t)D_ * ND_];
__device__ __align__(16) __nv_bfloat16 g_WcatL[(size_t)D_ * ND_];
__device__ __align__(16) __nv_bfloat16 g_WcH[(size_t)D_ * C_];
__device__ __align__(16) __nv_bfloat16 g_WcL[(size_t)D_ * C_];
__device__ __align__(16) __nv_bfloat16 g_ctxTH[(size_t)N_ * B_ * L_ * C_];
__device__ __align__(16) __nv_bfloat16 g_ctxTL[(size_t)N_ * B_ * L_ * C_];

typedef unsigned long long u64;

__device__ __forceinline__ float warpSum32(float v) {
    #pragma unroll
    for (int o = 16; o; o >>= 1) v += __shfl_xor_sync(0xffffffffu, v, o);
    return v;
}

// ---- bf16 split helpers ----
__device__ __forceinline__ void split1(float x, __nv_bfloat16& h, __nv_bfloat16& l) {
    h = __float2bfloat16(x);
    l = __float2bfloat16(x - __bfloat162float(h));
}
__device__ __forceinline__ void st_pair(__nv_bfloat16* H, __nv_bfloat16* L,
                                        size_t off, float x0, float x1) {
    __nv_bfloat16 h0, l0, h1, l1;
    split1(x0, h0, l0); split1(x1, h1, l1);
    uint32_t hu = (uint32_t)__bfloat16_as_ushort(h0) |
                  ((uint32_t)__bfloat16_as_ushort(h1) << 16);
    uint32_t lu = (uint32_t)__bfloat16_as_ushort(l0) |
                  ((uint32_t)__bfloat16_as_ushort(l1) << 16);
    *(uint32_t*)&H[off] = hu;
    *(uint32_t*)&L[off] = lu;
}
// single-bf16 pair store
__device__ __forceinline__ void st_one(__nv_bfloat16* H, size_t off,
                                       float x0, float x1) {
    *(__nv_bfloat162*)&H[off] = __floats2bfloat162_rn(x0, x1);
}
// reconstruct 4 fp32 from bf16 hi/lo pairs at off
__device__ __forceinline__ void rec4(const __nv_bfloat16* __restrict__ H,
                                     const __nv_bfloat16* __restrict__ L,
                                     size_t off, float* o) {
    #pragma unroll
    for (int k = 0; k < 2; k++) {
        float2 h = __bfloat1622float2(*(const __nv_bfloat162*)&H[off + 2 * k]);
        float2 l = __bfloat1622float2(*(const __nv_bfloat162*)&L[off + 2 * k]);
        o[2 * k]     = h.x + l.x;
        o[2 * k + 1] = h.y + l.y;
    }
}

// ---- warp-level tensor core helpers (sm_80 baseline; no 'a' features) ----
__device__ __forceinline__ uint32_t smem_u32(const void* p) {
    uint32_t a;
    asm("{ .reg .u64 t; cvta.to.shared.u64 t, %1; cvt.u32.u64 %0, t; }" : "=r"(a) : "l"(p));
    return a;
}
__device__ __forceinline__ void ldsm_x4(uint32_t& r0, uint32_t& r1, uint32_t& r2,
                                        uint32_t& r3, uint32_t a) {
    asm volatile("ldmatrix.sync.aligned.m8n8.x4.shared.b16 {%0,%1,%2,%3}, [%4];"
                 : "=r"(r0), "=r"(r1), "=r"(r2), "=r"(r3) : "r"(a));
}
__device__ __forceinline__ void mma_bf16(float* d, const uint32_t* a, const uint32_t* b) {
    asm volatile("mma.sync.aligned.m16n8k16.row.col.f32.bf16.bf16.f32 "
        "{%0,%1,%2,%3}, {%4,%5,%6,%7}, {%8,%9}, {%0,%1,%2,%3};"
        : "+f"(d[0]), "+f"(d[1]), "+f"(d[2]), "+f"(d[3])
        : "r"(a[0]), "r"(a[1]), "r"(a[2]), "r"(a[3]), "r"(b[0]), "r"(b[1]));
}
__device__ __forceinline__ void cp16(uint32_t saddr, const void* gaddr) {
    asm volatile("cp.async.cg.shared.global [%0], [%1], 16;"
                 :: "r"(saddr), "l"(gaddr) : "memory");
}
#define CP_COMMIT() asm volatile("cp.async.commit_group;" ::: "memory")
#define CP_WAIT(n)  asm volatile("cp.async.wait_group %0;" :: "n"(n) : "memory")

// XOR-swizzled 64B-row tile offset
__device__ __forceinline__ uint32_t swz(int row, int c4) {
    return (uint32_t)(row * 64 + ((c4 ^ ((row >> 1) & 3)) << 4));
}

// 3-term split MMA for one jj-group, term-outer ordering
__device__ __forceinline__ void mma_group(float (*acc)[4], int jj,
                                          uint32_t (&ah)[2][4], uint32_t (&al)[2][4],
                                          const uint32_t* bh, const uint32_t* bl) {
    #pragma unroll
    for (int m = 0; m < 2; m++)
        #pragma unroll
        for (int jb = 0; jb < 2; jb++)
            mma_bf16(acc[m * 8 + jj * 2 + jb], ah[m], bh + jb * 2);
    #pragma unroll
    for (int m = 0; m < 2; m++)
        #pragma unroll
        for (int jb = 0; jb < 2; jb++)
            mma_bf16(acc[m * 8 + jj * 2 + jb], ah[m], bl + jb * 2);
    #pragma unroll
    for (int m = 0; m < 2; m++)
        #pragma unroll
        for (int jb = 0; jb < 2; jb++)
            mma_bf16(acc[m * 8 + jj * 2 + jb], al[m], bh + jb * 2);
}

// ---------------------------------------------------------------------------
// K1: transpose input [B][D][Q] -> g_tgtH/L bf16 split, [B][Q][D]
// ---------------------------------------------------------------------------
__global__ void __launch_bounds__(256) k_transpose(const float* __restrict__ in) {
    __shared__ float tile[32][33];
    const int b  = blockIdx.z;
    const int q0 = blockIdx.x * 32;
    const int d0 = blockIdx.y * 32;
    const int tx = threadIdx.x, ty = threadIdx.y;  // 32 x 8
    #pragma unroll
    for (int j = 0; j < 4; j++)
        tile[ty + j * 8][tx] = in[((size_t)b * D_ + d0 + ty + j * 8) * Q_ + q0 + tx];
    __syncthreads();
    #pragma unroll
    for (int j = 0; j < 4; j++) {
        float x = tile[tx][ty + j * 8];
        size_t idx = ((size_t)b * Q_ + q0 + ty + j * 8) * D_ + d0 + tx;
        __nv_bfloat16 h, l; split1(x, h, l);
        g_tgtH[idx] = h; g_tgtL[idx] = l;
    }
}

// K1b: split Wcat and Wc fp32 -> bf16 hi/lo (merged single launch)
constexpr int WCAT_BLOCKS = D_ * ND_ / 1024;  // 640
constexpr int WC_BLOCKS   = D_ * C_ / 1024;   // 128
__global__ void __launch_bounds__(256) k_splitAll(const float* __restrict__ Wcat,
                                                  const float* __restrict__ Wc) {
    const int blk = blockIdx.x;
    const float* src;
    __nv_bfloat16 *H, *L;
    int base;
    if (blk < WCAT_BLOCKS) { src = Wcat; H = g_WcatH; L = g_WcatL; base = blk * 1024; }
    else { src = Wc; H = g_WcH; L = g_WcL; base = (blk - WCAT_BLOCKS) * 1024; }
    int idx = base + threadIdx.x * 4;
    #pragma unroll
    for (int i = 0; i < 4; i++) {
        float x = src[idx + i];
        __nv_bfloat16 h, l; split1(x, h, l);
        H[idx + i] = h; L[idx + i] = l;
    }
}

// K1d: transpose+split contexts [nb][c][l] fp32 -> g_ctxTH/L [nb][l][c] bf16
__global__ void __launch_bounds__(256) k_ctxT(const float* __restrict__ ctx) {
    __shared__ float tile[32][33];
    const int nb = blockIdx.z;
    const int l0 = blockIdx.x * 32;
    const int c0 = blockIdx.y * 32;
    const int tx = threadIdx.x, ty = threadIdx.y;  // 32 x 8
    const float* cp = ctx + (size_t)nb * C_ * L_;
    #pragma unroll
    for (int j = 0; j < 4; j++)
        tile[ty + j * 8][tx] = cp[(size_t)(c0 + ty + j * 8) * L_ + l0 + tx];
    __syncthreads();
    #pragma unroll
    for (int j = 0; j < 4; j++) {
        float x = tile[tx][ty + j * 8];
        size_t idx = ((size_t)nb * L_ + l0 + ty + j * 8) * C_ + c0 + tx;
        __nv_bfloat16 h, l; split1(x, h, l);
        g_ctxTH[idx] = h; g_ctxTL[idx] = l;
    }
}

// ---------------------------------------------------------------------------
// Shared tile constants for the 128x128 mma kernels (swizzled 64B rows, 3 bufs)
// ---------------------------------------------------------------------------
constexpr int PLANE64 = 128 * 64;        // 8192
constexpr int BUF64   = 4 * PLANE64;     // 32768
constexpr int MMA_SMEM = 3 * BUF64;      // 98304 (staging/logits reuse it)
constexpr int LSTRIDE = 129;
constexpr int NCH = 8;                   // K=256 in chunks of 32

// ---------------------------------------------------------------------------
// K2 (mma.sync): src[l,d] = sum_c ctxT[l,c] * Wc[d,c]  (3-term bf16 split)
// tile 128 l (M) x 128 d (N), K = 512 in 16 chunks; 3-buffer single-sync.
// ---------------------------------------------------------------------------
constexpr int SRC_NCH = C_ / 32;  // 16

__global__ void __launch_bounds__(256, 2) k_source_mma() {
    extern __shared__ __align__(16) char smem[];
    const uint32_t sb = smem_u32(smem);
    const int t = threadIdx.x;
    const int lane = t & 31, wid = t >> 5;
    const int qw = (wid & 3) * 32;   // l dir (M)
    const int lw = (wid >> 2) * 64;  // d dir (N)
    const int nb = blockIdx.y;
    const int d0 = blockIdx.x * 128;

    const __nv_bfloat16* aH = g_ctxTH + (size_t)nb * L_ * C_;
    const __nv_bfloat16* aL = g_ctxTL + (size_t)nb * L_ * C_;
    const __nv_bfloat16* bH = g_WcH + (size_t)d0 * C_;
    const __nv_bfloat16* bL = g_WcL + (size_t)d0 * C_;

    auto prefetch = [&](int c) {
        const int kd = c * 32;
        const uint32_t sbase = sb + (c % 3) * BUF64;
        #pragma unroll
        for (int i = 0; i < 8; i++) {
            int idx = t + i * 256;
            int pl = idx >> 9;
            int p2 = idx & 511;
            int row = p2 >> 2, c4 = p2 & 3;
            const __nv_bfloat16* sp =
                (pl == 0) ? aH : (pl == 1) ? aL : (pl == 2) ? bH : bL;
            cp16(sbase + pl * PLANE64 + swz(row, c4),
                 sp + (size_t)row * C_ + kd + c4 * 8);
        }
        CP_COMMIT();
    };

    float acc[16][4] = {};

    prefetch(0); prefetch(1);
    for (int c = 0; c < SRC_NCH; c++) {
        if (c + 1 < SRC_NCH) CP_WAIT(1); else CP_WAIT(0);
        __syncthreads();
        if (c + 2 < SRC_NCH) prefetch(c + 2);
        const uint32_t sbase = sb + (c % 3) * BUF64;
        #pragma unroll
        for (int kh = 0; kh < 2; kh++) {
            uint32_t ah[2][4], al[2][4];
            #pragma unroll
            for (int m = 0; m < 2; m++) {
                uint32_t addr = sbase + swz(qw + m * 16 + (lane & 15),
                                            kh * 2 + (lane >> 4));
                ldsm_x4(ah[m][0], ah[m][1], ah[m][2], ah[m][3], addr);
                ldsm_x4(al[m][0], al[m][1], al[m][2], al[m][3], addr + PLANE64);
            }
            const int nrow = (lane & 7) + ((lane >> 4) << 3);
            const int nc4  = kh * 2 + ((lane >> 3) & 1);
            #pragma unroll
            for (int jj = 0; jj < 4; jj++) {
                uint32_t addr = sbase + 2 * PLANE64 + swz(lw + jj * 16 + nrow, nc4);
                uint32_t bh[4], bl[4];
                ldsm_x4(bh[0], bh[1], bh[2], bh[3], addr);
                ldsm_x4(bl[0], bl[1], bl[2], bl[3], addr + PLANE64);
                mma_group(acc, jj, ah, al, bh, bl);
            }
        }
    }
    // stage to smem, then coalesced store (src keeps hi/lo — feeds 3-term GEMMs)
    __syncthreads();
    float* sx = (float*)smem;
    #pragma unroll
    for (int m = 0; m < 2; m++)
        #pragma unroll
        for (int j = 0; j < 8; j++) {
            int lr  = qw + m * 16 + (lane >> 2);
            int col = lw + j * 8 + (lane & 3) * 2;
            float* d = acc[m * 8 + j];
            sx[lr * 128 + col]           = d[0];
            sx[lr * 128 + col + 1]       = d[1];
            sx[(lr + 8) * 128 + col]     = d[2];
            sx[(lr + 8) * 128 + col + 1] = d[3];
        }
    __syncthreads();
    #pragma unroll
    for (int i = 0; i < 32; i++) {
        int p = t + i * 256;           // 8192 pairs
        int row = p >> 6;
        int col = (p & 63) * 2;
        st_pair(g_srcH, g_srcL, ((size_t)nb * L_ + row) * D_ + d0 + col,
                sx[row * 128 + col], sx[row * 128 + col + 1]);
    }
}

// ---------------------------------------------------------------------------
// K3 (mma.sync): logits[128q,128l] = tgt·src^T, softmax, w as single bf16.
// 3-buffer single-sync pipeline; 256-thread softmax; coalesced w store.
// ---------------------------------------------------------------------------
__global__ void __launch_bounds__(256, 2) k_attn_mma() {
    extern __shared__ __align__(16) char smem[];
    float* logits = (float*)smem;
    float* sinv   = logits + 128 * LSTRIDE;   // 128 floats
    const uint32_t sb = smem_u32(smem);
    const int t = threadIdx.x;
    const int lane = t & 31, wid = t >> 5;
    const int qw = (wid & 3) * 32;
    const int lw = (wid >> 2) * 64;
    const int nb = blockIdx.y;
    const int n = nb >> 5, b = nb & 31;
    const int q0 = blockIdx.x * 128;

    const __nv_bfloat16* aH = g_tgtH + ((size_t)b * Q_ + q0) * D_;
    const __nv_bfloat16* aL = g_tgtL + ((size_t)b * Q_ + q0) * D_;
    const __nv_bfloat16* bH = g_srcH + (size_t)nb * L_ * D_;
    const __nv_bfloat16* bL = g_srcL + (size_t)nb * L_ * D_;

    auto prefetch = [&](int c) {
        const int kd = c * 32;
        const uint32_t sbase = sb + (c % 3) * BUF64;
        #pragma unroll
        for (int i = 0; i < 8; i++) {
            int idx = t + i * 256;
            int pl = idx >> 9;
            int p2 = idx & 511;
            int row = p2 >> 2, c4 = p2 & 3;
            const __nv_bfloat16* sp =
                (pl == 0) ? aH : (pl == 1) ? aL : (pl == 2) ? bH : bL;
            cp16(sbase + pl * PLANE64 + swz(row, c4),
                 sp + (size_t)row * D_ + kd + c4 * 8);
        }
        CP_COMMIT();
    };

    float acc[16][4] = {};

    prefetch(0); prefetch(1);
    for (int c = 0; c < NCH; c++) {
        if (c + 1 < NCH) CP_WAIT(1); else CP_WAIT(0);
        __syncthreads();
        if (c + 2 < NCH) prefetch(c + 2);
        const uint32_t sbase = sb + (c % 3) * BUF64;
        #pragma unroll
        for (int kh = 0; kh < 2; kh++) {
            uint32_t ah[2][4], al[2][4];
            #pragma unroll
            for (int m = 0; m < 2; m++) {
                uint32_t addr = sbase + swz(qw + m * 16 + (lane & 15),
                                            kh * 2 + (lane >> 4));
                ldsm_x4(ah[m][0], ah[m][1], ah[m][2], ah[m][3], addr);
                ldsm_x4(al[m][0], al[m][1], al[m][2], al[m][3], addr + PLANE64);
            }
            const int nrow = (lane & 7) + ((lane >> 4) << 3);
            const int nc4  = kh * 2 + ((lane >> 3) & 1);
            #pragma unroll
            for (int jj = 0; jj < 4; jj++) {
                uint32_t addr = sbase + 2 * PLANE64 + swz(lw + jj * 16 + nrow, nc4);
                uint32_t bh[4], bl[4];
                ldsm_x4(bh[0], bh[1], bh[2], bh[3], addr);
                ldsm_x4(bl[0], bl[1], bl[2], bl[3], addr + PLANE64);
                mma_group(acc, jj, ah, al, bh, bl);
            }
        }
    }
    __syncthreads();
    #pragma unroll
    for (int m = 0; m < 2; m++)
        #pragma unroll
        for (int j = 0; j < 8; j++) {
            int qr  = qw + m * 16 + (lane >> 2);
            int col = lw + j * 8 + (lane & 3) * 2;
            float* d = acc[m * 8 + j];
            logits[qr * LSTRIDE + col]           = d[0];
            logits[qr * LSTRIDE + col + 1]       = d[1];
            logits[(qr + 8) * LSTRIDE + col]     = d[2];
            logits[(qr + 8) * LSTRIDE + col + 1] = d[3];
        }
    __syncthreads();
    {
        // softmax: 2 lanes per row; exp kept in smem; per-row inv stored
        const int row = t >> 1, half = t & 1;
        float* rp = logits + row * LSTRIDE + half * 64;
        float m = rp[0];
        #pragma unroll 8
        for (int j = 1; j < 64; j++) m = fmaxf(m, rp[j]);
        m = fmaxf(m, __shfl_xor_sync(0xffffffffu, m, 1));
        float s = 0.f;
        #pragma unroll 8
        for (int j = 0; j < 64; j++) {
            float ev = __expf(rp[j] - m);
            rp[j] = ev;
            s += ev;
        }
        s += __shfl_xor_sync(0xffffffffu, s, 1);
        if (half == 0) sinv[row] = 1.0f / s;
    }
    __syncthreads();
    // coalesced single-bf16 w store
    #pragma unroll
    for (int i = 0; i < 32; i++) {
        int p = t + i * 256;
        int row = p >> 6;
        int col = (p & 63) * 2;
        float iv = sinv[row];
        st_one(g_wH, (((size_t)b * Q_ + q0 + row) * N_ + n) * L_ + col,
               logits[row * LSTRIDE + col] * iv,
               logits[row * LSTRIDE + col + 1] * iv);
    }
}

// ---------------------------------------------------------------------------
// K4 (mma.sync): S2[e,l] = sum_d Wcat[e, n*D+d] * src[l,d] -> single bf16
// 3-buffer single-sync pipeline; staged coalesced store.
// ---------------------------------------------------------------------------
__global__ void __launch_bounds__(256, 2) k_s2_mma() {
    extern __shared__ __align__(16) char smem[];
    const uint32_t sb = smem_u32(smem);
    const int t = threadIdx.x;
    const int lane = t & 31, wid = t >> 5;
    const int qw = (wid & 3) * 32;   // e dir
    const int lw = (wid >> 2) * 64;  // l dir
    const int nb = blockIdx.y;
    const int n = nb >> 5, b = nb & 31;
    const int e0 = blockIdx.x * 128;

    const __nv_bfloat16* aH = g_WcatH + (size_t)e0 * ND_ + n * D_;
    const __nv_bfloat16* aL = g_WcatL + (size_t)e0 * ND_ + n * D_;
    const __nv_bfloat16* bH = g_srcH + (size_t)nb * L_ * D_;
    const __nv_bfloat16* bL = g_srcL + (size_t)nb * L_ * D_;

    auto prefetch = [&](int c) {
        const int kd = c * 32;
        const uint32_t sbase = sb + (c % 3) * BUF64;
        #pragma unroll
        for (int i = 0; i < 8; i++) {
            int idx = t + i * 256;
            int pl = idx >> 9;
            int p2 = idx & 511;
            int row = p2 >> 2, c4 = p2 & 3;
            const __nv_bfloat16* sp;
            size_t stride;
            if (pl < 2) { sp = pl ? aL : aH; stride = ND_; }
            else        { sp = (pl == 3) ? bL : bH; stride = D_; }
            cp16(sbase + pl * PLANE64 + swz(row, c4),
                 sp + (size_t)row * stride + kd + c4 * 8);
        }
        CP_COMMIT();
    };

    float acc[16][4] = {};

    prefetch(0); prefetch(1);
    for (int c = 0; c < NCH; c++) {
        if (c + 1 < NCH) CP_WAIT(1); else CP_WAIT(0);
        __syncthreads();
        if (c + 2 < NCH) prefetch(c + 2);
        const uint32_t sbase = sb + (c % 3) * BUF64;
        #pragma unroll
        for (int kh = 0; kh < 2; kh++) {
            uint32_t ah[2][4], al[2][4];
            #pragma unroll
            for (int m = 0; m < 2; m++) {
                uint32_t addr = sbase + swz(qw + m * 16 + (lane & 15),
                                            kh * 2 + (lane >> 4));
                ldsm_x4(ah[m][0], ah[m][1], ah[m][2], ah[m][3], addr);
                ldsm_x4(al[m][0], al[m][1], al[m][2], al[m][3], addr + PLANE64);
            }
            const int nrow = (lane & 7) + ((lane >> 4) << 3);
            const int nc4  = kh * 2 + ((lane >> 3) & 1);
            #pragma unroll
            for (int jj = 0; jj < 4; jj++) {
                uint32_t addr = sbase + 2 * PLANE64 + swz(lw + jj * 16 + nrow, nc4);
                uint32_t bh[4], bl[4];
                ldsm_x4(bh[0], bh[1], bh[2], bh[3], addr);
                ldsm_x4(bl[0], bl[1], bl[2], bl[3], addr + PLANE64);
                mma_group(acc, jj, ah, al, bh, bl);
            }
        }
    }
    // stage to smem, then coalesced single-bf16 store (rows=e, cols=l)
    __syncthreads();
    float* sx = (float*)smem;
    #pragma unroll
    for (int m = 0; m < 2; m++)
        #pragma unroll
        for (int j = 0; j < 8; j++) {
            int er  = qw + m * 16 + (lane >> 2);
            int col = lw + j * 8 + (lane & 3) * 2;
            float* d = acc[m * 8 + j];
            sx[er * 128 + col]           = d[0];
            sx[er * 128 + col + 1]       = d[1];
            sx[(er + 8) * 128 + col]     = d[2];
            sx[(er + 8) * 128 + col + 1] = d[3];
        }
    __syncthreads();
    #pragma unroll
    for (int i = 0; i < 32; i++) {
        int p = t + i * 256;
        int row = p >> 6;
        int col = (p & 63) * 2;
        st_one(g_s2H, (((size_t)b * D_ + e0 + row) * N_ + n) * L_ + col,
               sx[row * 128 + col], sx[row * 128 + col + 1]);
    }
}

// ---------------------------------------------------------------------------
// K5 (mma.sync): x[q,e] = sum_k w[q,k]*s2[e,k], K=1280, tile 64q x 256e.
// SINGLE-term bf16 GEMM. 256 threads (8 warps: 2 q x 4 e), 2-buffer
// single-sync pipeline, 2 CTAs/SM (O_SMEM=66560 -> 133120/SM).
// Epilogue: stage x to smem, then bias+relu+residual+LayerNorm -> out.
// ---------------------------------------------------------------------------
constexpr int O_APL  = 64 * 64;        // 4096  (w plane: 64 q rows x 64B)
constexpr int O_BPL  = 256 * 64;       // 16384 (s2 plane: 256 e rows x 64B)
constexpr int O_BUF  = O_APL + O_BPL;  // 20480
constexpr int O_NCH  = K2_ / 32;       // 40
constexpr int XS     = 260;            // x staging row stride (floats)
constexpr int O_SMEM = 64 * XS * 4;    // 66560 (> 2*O_BUF = 40960)

__global__ void __launch_bounds__(256, 2) k_out_mma(const float* __restrict__ Wb,
                                                    const float* __restrict__ gamma,
                                                    const float* __restrict__ beta,
                                                    float* __restrict__ out) {
    extern __shared__ __align__(16) char smem[];
    const uint32_t sb = smem_u32(smem);
    const int t = threadIdx.x;
    const int lane = t & 31, wid = t >> 5;
    const int qw = (wid & 1) * 32;   // q dir (2 warps)
    const int ew = (wid >> 1) * 64;  // e dir (4 warps)
    const int b  = blockIdx.y;
    const int q0 = blockIdx.x * 64;

    const __nv_bfloat16* wHp = g_wH + ((size_t)b * Q_ + q0) * K2_;
    const __nv_bfloat16* sHp = g_s2H + (size_t)b * D_ * K2_;

    auto prefetch = [&](int c) {
        const int k0 = c * 32;
        const uint32_t sbase = sb + (c & 1) * O_BUF;
        #pragma unroll
        for (int i = 0; i < 5; i++) {
            int idx = t + i * 256;           // 1280 pieces total
            if (idx < 256) {                 // A plane: 64 rows x 4 c4
                int row = idx >> 2, c4 = idx & 3;
                cp16(sbase + swz(row, c4),
                     wHp + (size_t)row * K2_ + k0 + c4 * 8);
            } else {                         // B plane: 256 rows x 4 c4
                int idx2 = idx - 256;
                int row = idx2 >> 2, c4 = idx2 & 3;
                cp16(sbase + O_APL + swz(row, c4),
                     sHp + (size_t)row * K2_ + k0 + c4 * 8);
            }
        }
        CP_COMMIT();
    };

    float acc[16][4] = {};

    prefetch(0);
    for (int c = 0; c < O_NCH; c++) {
        CP_WAIT(0);          // chunk c data arrived
        __syncthreads();     // compute(c-1) done everywhere -> its buffer free
        if (c + 1 < O_NCH) prefetch(c + 1);
        const uint32_t sbase = sb + (c & 1) * O_BUF;
        #pragma unroll
        for (int kh = 0; kh < 2; kh++) {
            uint32_t ah[2][4];
            #pragma unroll
            for (int m = 0; m < 2; m++) {
                uint32_t addr = sbase + swz(qw + m * 16 + (lane & 15),
                                            kh * 2 + (lane >> 4));
                ldsm_x4(ah[m][0], ah[m][1], ah[m][2], ah[m][3], addr);
            }
            const int nrow = (lane & 7) + ((lane >> 4) << 3);
            const int nc4  = kh * 2 + ((lane >> 3) & 1);
            #pragma unroll
            for (int jj = 0; jj < 4; jj++) {
                uint32_t addr = sbase + O_APL + swz(ew + jj * 16 + nrow, nc4);
                uint32_t bh[4];
                ldsm_x4(bh[0], bh[1], bh[2], bh[3], addr);
                #pragma unroll
                for (int m = 0; m < 2; m++)
                    #pragma unroll
                    for (int jb = 0; jb < 2; jb++)
                        mma_bf16(acc[m * 8 + jj * 2 + jb], ah[m], bh + jb * 2);
            }
        }
    }
    __syncthreads();   // all tile reads done; safe to overwrite with staging
    float* sx = (float*)smem;
    #pragma unroll
    for (int m = 0; m < 2; m++)
        #pragma unroll
        for (int j = 0; j < 8; j++) {
            int qr  = qw + m * 16 + (lane >> 2);
            int col = ew + j * 8 + (lane & 3) * 2;
            float* d = acc[m * 8 + j];
            sx[qr * XS + col]           = d[0];
            sx[qr * XS + col + 1]       = d[1];
            sx[(qr + 8) * XS + col]     = d[2];
            sx[(qr + 8) * XS + col + 1] = d[3];
        }
    __syncthreads();
    float wb[8], gm[8], be[8];
    {
        float4 w0 = *(const float4*)&Wb[lane * 4];
        float4 w1 = *(const float4*)&Wb[lane * 4 + 128];
        float4 g0 = *(const float4*)&gamma[lane * 4];
        float4 g1 = *(const float4*)&gamma[lane * 4 + 128];
        float4 e0 = *(const float4*)&beta[lane * 4];
        float4 e1 = *(const float4*)&beta[lane * 4 + 128];
        wb[0]=w0.x; wb[1]=w0.y; wb[2]=w0.z; wb[3]=w0.w; wb[4]=w1.x; wb[5]=w1.y; wb[6]=w1.z; wb[7]=w1.w;
        gm[0]=g0.x; gm[1]=g0.y; gm[2]=g0.z; gm[3]=g0.w; gm[4]=g1.x; gm[5]=g1.y; gm[6]=g1.z; gm[7]=g1.w;
        be[0]=e0.x; be[1]=e0.y; be[2]=e0.z; be[3]=e0.w; be[4]=e1.x; be[5]=e1.y; be[6]=e1.z; be[7]=e1.w;
    }
    const __nv_bfloat16* tH = g_tgtH + (size_t)b * Q_ * D_;
    const __nv_bfloat16* tL = g_tgtL + (size_t)b * Q_ * D_;
    #pragma unroll
    for (int i = 0; i < 8; i++) {
        const int r = wid * 8 + i;          // local q row (8 warps x 8 = 64)
        const int q = q0 + r;
        float4 a0 = *(const float4*)&sx[r * XS + lane * 4];
        float4 a1 = *(const float4*)&sx[r * XS + lane * 4 + 128];
        float av[8] = {a0.x, a0.y, a0.z, a0.w, a1.x, a1.y, a1.z, a1.w};
        float tv[8];
        rec4(tH, tL, (size_t)q * D_ + lane * 4, tv);
        rec4(tH, tL, (size_t)q * D_ + lane * 4 + 128, tv + 4);
        float v[8], s = 0.f;
        #pragma unroll
        for (int j = 0; j < 8; j++) {
            v[j] = fmaxf(av[j] + wb[j], 0.f) + tv[j];
            s += v[j];
        }
        s = warpSum32(s);
        const float mu = s * (1.0f / 256.0f);
        float d2 = 0.f;
        #pragma unroll
        for (int j = 0; j < 8; j++) { float dd = v[j] - mu; d2 += dd * dd; }
        d2 = warpSum32(d2);
        const float rs = rsqrtf(d2 * (1.0f / 256.0f));
        float o[8];
        #pragma unroll
        for (int j = 0; j < 8; j++) o[j] = (v[j] - mu) * rs * gm[j] + be[j];
        float* orow = out + (size_t)(b * Q_ + q) * D_;
        *(float4*)&orow[lane * 4]       = make_float4(o[0], o[1], o[2], o[3]);
        *(float4*)&orow[lane * 4 + 128] = make_float4(o[4], o[5], o[6], o[7]);
    }
}

// ---------------------------------------------------------------------------
extern "C" void kernel_launch(void* const* d_in, const int* in_sizes, int n_in,
                              void* d_out, int out_size) {
    const float* input    = (const float*)d_in[0];  // [B, D, 32, 32]
    const float* contexts = (const float*)d_in[1];  // [N, B, C, L]
    const float* Wc       = (const float*)d_in[2];  // [D, C]
    const float* Wcat     = (const float*)d_in[3];  // [D, N*D]
    const float* Wb       = (const float*)d_in[4];  // [D]
    const float* gamma    = (const float*)d_in[5];  // [D]
    const float* beta     = (const float*)d_in[6];  // [D]
    float* out = (float*)d_out;                     // [B, Q, D]

    cudaFuncSetAttribute(k_source_mma, cudaFuncAttributeMaxDynamicSharedMemorySize, MMA_SMEM);
    cudaFuncSetAttribute(k_attn_mma,   cudaFuncAttributeMaxDynamicSharedMemorySize, MMA_SMEM);
    cudaFuncSetAttribute(k_s2_mma,     cudaFuncAttributeMaxDynamicSharedMemorySize, MMA_SMEM);
    cudaFuncSetAttribute(k_out_mma,    cudaFuncAttributeMaxDynamicSharedMemorySize, O_SMEM);

    k_transpose <<<dim3(Q_ / 32, D_ / 32, B_), dim3(32, 8)>>>(input);
    k_splitAll  <<<WCAT_BLOCKS + WC_BLOCKS, 256>>>(Wcat, Wc);
    k_ctxT      <<<dim3(L_ / 32, C_ / 32, N_ * B_), dim3(32, 8)>>>(contexts);
    k_source_mma<<<dim3(2,        N_ * B_),    256, MMA_SMEM>>>();
    k_attn_mma  <<<dim3(Q_ / 128, N_ * B_),    256, MMA_SMEM>>>();
    k_s2_mma    <<<dim3(2,        N_ * B_),    256, MMA_SMEM>>>();
    k_out_mma   <<<dim3(Q_ / 64,  B_),         256, O_SMEM>>>(Wb, gamma, beta, out);
}

// round 17
// speedup vs baseline: 4.2024x; 1.0280x over previous
#include <cuda_runtime.h>
#include <cuda_bf16.h>
#include <cstdint>

// Problem dims (fixed by the reference)
constexpr int B_  = 32;
constexpr int D_  = 256;   // idf
constexpr int Q_  = 1024;  // ih*iw
constexpr int C_  = 512;   // cdf
constexpr int L_  = 128;
constexpr int N_  = 10;    // contexts
constexpr int K2_ = N_ * L_;  // 1280
constexpr int ND_ = N_ * D_;  // 2560

// Scratch (static device globals — no allocation in kernel_launch)
__device__ __align__(16) __nv_bfloat16 g_tgtH[(size_t)B_ * Q_ * D_];
__device__ __align__(16) __nv_bfloat16 g_tgtL[(size_t)B_ * Q_ * D_];
__device__ __align__(16) __nv_bfloat16 g_srcH[(size_t)N_ * B_ * L_ * D_];
__device__ __align__(16) __nv_bfloat16 g_srcL[(size_t)N_ * B_ * L_ * D_];
__device__ __align__(16) __nv_bfloat16 g_wH [(size_t)B_ * Q_ * N_ * L_];
__device__ __align__(16) __nv_bfloat16 g_s2H[(size_t)B_ * D_ * N_ * L_];
__device__ __align__(16) __nv_bfloat16 g_WcatH[(size_t)D_ * ND_];
__device__ __align__(16) __nv_bfloat16 g_WcatL[(size_t)D_ * ND_];
__device__ __align__(16) __nv_bfloat16 g_WcH[(size_t)D_ * C_];
__device__ __align__(16) __nv_bfloat16 g_WcL[(size_t)D_ * C_];
__device__ __align__(16) __nv_bfloat16 g_ctxTH[(size_t)N_ * B_ * L_ * C_];
__device__ __align__(16) __nv_bfloat16 g_ctxTL[(size_t)N_ * B_ * L_ * C_];

typedef unsigned long long u64;

__device__ __forceinline__ float warpSum32(float v) {
    #pragma unroll
    for (int o = 16; o; o >>= 1) v += __shfl_xor_sync(0xffffffffu, v, o);
    return v;
}

// ---- bf16 split helpers ----
__device__ __forceinline__ void split1(float x, __nv_bfloat16& h, __nv_bfloat16& l) {
    h = __float2bfloat16(x);
    l = __float2bfloat16(x - __bfloat162float(h));
}
__device__ __forceinline__ void st_pair(__nv_bfloat16* H, __nv_bfloat16* L,
                                        size_t off, float x0, float x1) {
    __nv_bfloat16 h0, l0, h1, l1;
    split1(x0, h0, l0); split1(x1, h1, l1);
    uint32_t hu = (uint32_t)__bfloat16_as_ushort(h0) |
                  ((uint32_t)__bfloat16_as_ushort(h1) << 16);
    uint32_t lu = (uint32_t)__bfloat16_as_ushort(l0) |
                  ((uint32_t)__bfloat16_as_ushort(l1) << 16);
    *(uint32_t*)&H[off] = hu;
    *(uint32_t*)&L[off] = lu;
}
__device__ __forceinline__ void st_one(__nv_bfloat16* H, size_t off,
                                       float x0, float x1) {
    *(__nv_bfloat162*)&H[off] = __floats2bfloat162_rn(x0, x1);
}
__device__ __forceinline__ void rec4(const __nv_bfloat16* __restrict__ H,
                                     const __nv_bfloat16* __restrict__ L,
                                     size_t off, float* o) {
    #pragma unroll
    for (int k = 0; k < 2; k++) {
        float2 h = __bfloat1622float2(*(const __nv_bfloat162*)&H[off + 2 * k]);
        float2 l = __bfloat1622float2(*(const __nv_bfloat162*)&L[off + 2 * k]);
        o[2 * k]     = h.x + l.x;
        o[2 * k + 1] = h.y + l.y;
    }
}

// ---- warp-level tensor core helpers ----
__device__ __forceinline__ uint32_t smem_u32(const void* p) {
    uint32_t a;
    asm("{ .reg .u64 t; cvta.to.shared.u64 t, %1; cvt.u32.u64 %0, t; }" : "=r"(a) : "l"(p));
    return a;
}
__device__ __forceinline__ void ldsm_x4(uint32_t& r0, uint32_t& r1, uint32_t& r2,
                                        uint32_t& r3, uint32_t a) {
    asm volatile("ldmatrix.sync.aligned.m8n8.x4.shared.b16 {%0,%1,%2,%3}, [%4];"
                 : "=r"(r0), "=r"(r1), "=r"(r2), "=r"(r3) : "r"(a));
}
__device__ __forceinline__ void mma_bf16(float* d, const uint32_t* a, const uint32_t* b) {
    asm volatile("mma.sync.aligned.m16n8k16.row.col.f32.bf16.bf16.f32 "
        "{%0,%1,%2,%3}, {%4,%5,%6,%7}, {%8,%9}, {%0,%1,%2,%3};"
        : "+f"(d[0]), "+f"(d[1]), "+f"(d[2]), "+f"(d[3])
        : "r"(a[0]), "r"(a[1]), "r"(a[2]), "r"(a[3]), "r"(b[0]), "r"(b[1]));
}
__device__ __forceinline__ void cp16(uint32_t saddr, const void* gaddr) {
    asm volatile("cp.async.cg.shared.global [%0], [%1], 16;"
                 :: "r"(saddr), "l"(gaddr) : "memory");
}
#define CP_COMMIT() asm volatile("cp.async.commit_group;" ::: "memory")
#define CP_WAIT(n)  asm volatile("cp.async.wait_group %0;" :: "n"(n) : "memory")

// XOR-swizzled 64B-row tile offset
__device__ __forceinline__ uint32_t swz(int row, int c4) {
    return (uint32_t)(row * 64 + ((c4 ^ ((row >> 1) & 3)) << 4));
}

// 3-term split MMA for one jj-group, term-outer ordering
__device__ __forceinline__ void mma_group(float (*acc)[4], int jj,
                                          uint32_t (&ah)[2][4], uint32_t (&al)[2][4],
                                          const uint32_t* bh, const uint32_t* bl) {
    #pragma unroll
    for (int m = 0; m < 2; m++)
        #pragma unroll
        for (int jb = 0; jb < 2; jb++)
            mma_bf16(acc[m * 8 + jj * 2 + jb], ah[m], bh + jb * 2);
    #pragma unroll
    for (int m = 0; m < 2; m++)
        #pragma unroll
        for (int jb = 0; jb < 2; jb++)
            mma_bf16(acc[m * 8 + jj * 2 + jb], ah[m], bl + jb * 2);
    #pragma unroll
    for (int m = 0; m < 2; m++)
        #pragma unroll
        for (int jb = 0; jb < 2; jb++)
            mma_bf16(acc[m * 8 + jj * 2 + jb], al[m], bh + jb * 2);
}

// ---------------------------------------------------------------------------
// K1 (merged prep): transpose(input) | ctxT(contexts) | split(Wcat, Wc)
// flat 1D grid, 256 threads; dispatch by block-id range.
// ---------------------------------------------------------------------------
constexpr int TP_BLOCKS   = (Q_ / 32) * (D_ / 32) * B_;      // 8192
constexpr int CTXT_BLOCKS = (L_ / 32) * (C_ / 32) * N_ * B_; // 20480
constexpr int WCAT_BLOCKS = D_ * ND_ / 1024;                 // 640
constexpr int WC_BLOCKS   = D_ * C_ / 1024;                  // 128
constexpr int PREP_BLOCKS = TP_BLOCKS + CTXT_BLOCKS + WCAT_BLOCKS + WC_BLOCKS;

__global__ void __launch_bounds__(256) k_prep(const float* __restrict__ in,
                                              const float* __restrict__ ctx,
                                              const float* __restrict__ Wcat,
                                              const float* __restrict__ Wc) {
    __shared__ float tile[32][33];
    const int id = blockIdx.x;
    const int t  = threadIdx.x;
    const int tx = t & 31, ty = t >> 5;   // 32 x 8

    if (id < TP_BLOCKS) {
        // transpose input [B][D][Q] -> tgtH/L [B][Q][D]
        const int b   = id >> 8;
        const int rem = id & 255;
        const int d0  = (rem >> 5) * 32;
        const int q0  = (rem & 31) * 32;
        #pragma unroll
        for (int j = 0; j < 4; j++)
            tile[ty + j * 8][tx] = in[((size_t)b * D_ + d0 + ty + j * 8) * Q_ + q0 + tx];
        __syncthreads();
        #pragma unroll
        for (int j = 0; j < 4; j++) {
            float x = tile[tx][ty + j * 8];
            size_t idx = ((size_t)b * Q_ + q0 + ty + j * 8) * D_ + d0 + tx;
            __nv_bfloat16 h, l; split1(x, h, l);
            g_tgtH[idx] = h; g_tgtL[idx] = l;
        }
    } else if (id < TP_BLOCKS + CTXT_BLOCKS) {
        // transpose+split contexts [nb][c][l] -> ctxTH/L [nb][l][c]
        const int id2 = id - TP_BLOCKS;
        const int nb  = id2 >> 6;
        const int rem = id2 & 63;
        const int c0  = (rem >> 2) * 32;
        const int l0  = (rem & 3) * 32;
        const float* cp = ctx + (size_t)nb * C_ * L_;
        #pragma unroll
        for (int j = 0; j < 4; j++)
            tile[ty + j * 8][tx] = cp[(size_t)(c0 + ty + j * 8) * L_ + l0 + tx];
        __syncthreads();
        #pragma unroll
        for (int j = 0; j < 4; j++) {
            float x = tile[tx][ty + j * 8];
            size_t idx = ((size_t)nb * L_ + l0 + ty + j * 8) * C_ + c0 + tx;
            __nv_bfloat16 h, l; split1(x, h, l);
            g_ctxTH[idx] = h; g_ctxTL[idx] = l;
        }
    } else {
        // split Wcat / Wc fp32 -> bf16 hi/lo
        const int blk = id - TP_BLOCKS - CTXT_BLOCKS;
        const float* src;
        __nv_bfloat16 *H, *L;
        int base;
        if (blk < WCAT_BLOCKS) { src = Wcat; H = g_WcatH; L = g_WcatL; base = blk * 1024; }
        else { src = Wc; H = g_WcH; L = g_WcL; base = (blk - WCAT_BLOCKS) * 1024; }
        int idx = base + t * 4;
        #pragma unroll
        for (int i = 0; i < 4; i++) {
            float x = src[idx + i];
            __nv_bfloat16 h, l; split1(x, h, l);
            H[idx + i] = h; L[idx + i] = l;
        }
    }
}

// ---------------------------------------------------------------------------
// Shared tile constants for the 128x128 mma kernels (swizzled 64B rows, 3 bufs)
// ---------------------------------------------------------------------------
constexpr int PLANE64 = 128 * 64;        // 8192
constexpr int BUF64   = 4 * PLANE64;     // 32768
constexpr int MMA_SMEM = 3 * BUF64;      // 98304 (staging/logits reuse it)
constexpr int LSTRIDE = 129;
constexpr int NCH = 8;                   // K=256 in chunks of 32

// ---------------------------------------------------------------------------
// K2 (mma.sync): src[l,d] = sum_c ctxT[l,c] * Wc[d,c]  (3-term bf16 split)
// tile 128 l (M) x 128 d (N), K = 512 in 16 chunks; 3-buffer single-sync.
// ---------------------------------------------------------------------------
constexpr int SRC_NCH = C_ / 32;  // 16

__global__ void __launch_bounds__(256, 2) k_source_mma() {
    extern __shared__ __align__(16) char smem[];
    const uint32_t sb = smem_u32(smem);
    const int t = threadIdx.x;
    const int lane = t & 31, wid = t >> 5;
    const int qw = (wid & 3) * 32;   // l dir (M)
    const int lw = (wid >> 2) * 64;  // d dir (N)
    const int nb = blockIdx.y;
    const int d0 = blockIdx.x * 128;

    const __nv_bfloat16* aH = g_ctxTH + (size_t)nb * L_ * C_;
    const __nv_bfloat16* aL = g_ctxTL + (size_t)nb * L_ * C_;
    const __nv_bfloat16* bH = g_WcH + (size_t)d0 * C_;
    const __nv_bfloat16* bL = g_WcL + (size_t)d0 * C_;

    auto prefetch = [&](int c) {
        const int kd = c * 32;
        const uint32_t sbase = sb + (c % 3) * BUF64;
        #pragma unroll
        for (int i = 0; i < 8; i++) {
            int idx = t + i * 256;
            int pl = idx >> 9;
            int p2 = idx & 511;
            int row = p2 >> 2, c4 = p2 & 3;
            const __nv_bfloat16* sp =
                (pl == 0) ? aH : (pl == 1) ? aL : (pl == 2) ? bH : bL;
            cp16(sbase + pl * PLANE64 + swz(row, c4),
                 sp + (size_t)row * C_ + kd + c4 * 8);
        }
        CP_COMMIT();
    };

    float acc[16][4] = {};

    prefetch(0); prefetch(1);
    for (int c = 0; c < SRC_NCH; c++) {
        if (c + 1 < SRC_NCH) CP_WAIT(1); else CP_WAIT(0);
        __syncthreads();
        if (c + 2 < SRC_NCH) prefetch(c + 2);
        const uint32_t sbase = sb + (c % 3) * BUF64;
        #pragma unroll
        for (int kh = 0; kh < 2; kh++) {
            uint32_t ah[2][4], al[2][4];
            #pragma unroll
            for (int m = 0; m < 2; m++) {
                uint32_t addr = sbase + swz(qw + m * 16 + (lane & 15),
                                            kh * 2 + (lane >> 4));
                ldsm_x4(ah[m][0], ah[m][1], ah[m][2], ah[m][3], addr);
                ldsm_x4(al[m][0], al[m][1], al[m][2], al[m][3], addr + PLANE64);
            }
            const int nrow = (lane & 7) + ((lane >> 4) << 3);
            const int nc4  = kh * 2 + ((lane >> 3) & 1);
            #pragma unroll
            for (int jj = 0; jj < 4; jj++) {
                uint32_t addr = sbase + 2 * PLANE64 + swz(lw + jj * 16 + nrow, nc4);
                uint32_t bh[4], bl[4];
                ldsm_x4(bh[0], bh[1], bh[2], bh[3], addr);
                ldsm_x4(bl[0], bl[1], bl[2], bl[3], addr + PLANE64);
                mma_group(acc, jj, ah, al, bh, bl);
            }
        }
    }
    // stage to smem, then coalesced store (src keeps hi/lo — feeds 3-term GEMMs)
    __syncthreads();
    float* sx = (float*)smem;
    #pragma unroll
    for (int m = 0; m < 2; m++)
        #pragma unroll
        for (int j = 0; j < 8; j++) {
            int lr  = qw + m * 16 + (lane >> 2);
            int col = lw + j * 8 + (lane & 3) * 2;
            float* d = acc[m * 8 + j];
            sx[lr * 128 + col]           = d[0];
            sx[lr * 128 + col + 1]       = d[1];
            sx[(lr + 8) * 128 + col]     = d[2];
            sx[(lr + 8) * 128 + col + 1] = d[3];
        }
    __syncthreads();
    #pragma unroll
    for (int i = 0; i < 32; i++) {
        int p = t + i * 256;           // 8192 pairs
        int row = p >> 6;
        int col = (p & 63) * 2;
        st_pair(g_srcH, g_srcL, ((size_t)nb * L_ + row) * D_ + d0 + col,
                sx[row * 128 + col], sx[row * 128 + col + 1]);
    }
}

// ---------------------------------------------------------------------------
// K3 (merged): attn (blocks 0..2559) | s2 (blocks 2560..3199)
// Both 3-term bf16 split, 3-buffer single-sync pipelines, identical smem.
// ---------------------------------------------------------------------------
constexpr int ATTN_BLOCKS = (Q_ / 128) * N_ * B_;   // 2560
constexpr int S2_BLOCKS   = 2 * N_ * B_;            // 640

__device__ void attn_body(char* smem, uint32_t sb, int q0, int nb) {
    float* logits = (float*)smem;
    float* sinv   = logits + 128 * LSTRIDE;   // 128 floats
    const int t = threadIdx.x;
    const int lane = t & 31, wid = t >> 5;
    const int qw = (wid & 3) * 32;
    const int lw = (wid >> 2) * 64;
    const int n = nb >> 5, b = nb & 31;

    const __nv_bfloat16* aH = g_tgtH + ((size_t)b * Q_ + q0) * D_;
    const __nv_bfloat16* aL = g_tgtL + ((size_t)b * Q_ + q0) * D_;
    const __nv_bfloat16* bH = g_srcH + (size_t)nb * L_ * D_;
    const __nv_bfloat16* bL = g_srcL + (size_t)nb * L_ * D_;

    auto prefetch = [&](int c) {
        const int kd = c * 32;
        const uint32_t sbase = sb + (c % 3) * BUF64;
        #pragma unroll
        for (int i = 0; i < 8; i++) {
            int idx = t + i * 256;
            int pl = idx >> 9;
            int p2 = idx & 511;
            int row = p2 >> 2, c4 = p2 & 3;
            const __nv_bfloat16* sp =
                (pl == 0) ? aH : (pl == 1) ? aL : (pl == 2) ? bH : bL;
            cp16(sbase + pl * PLANE64 + swz(row, c4),
                 sp + (size_t)row * D_ + kd + c4 * 8);
        }
        CP_COMMIT();
    };

    float acc[16][4] = {};

    prefetch(0); prefetch(1);
    for (int c = 0; c < NCH; c++) {
        if (c + 1 < NCH) CP_WAIT(1); else CP_WAIT(0);
        __syncthreads();
        if (c + 2 < NCH) prefetch(c + 2);
        const uint32_t sbase = sb + (c % 3) * BUF64;
        #pragma unroll
        for (int kh = 0; kh < 2; kh++) {
            uint32_t ah[2][4], al[2][4];
            #pragma unroll
            for (int m = 0; m < 2; m++) {
                uint32_t addr = sbase + swz(qw + m * 16 + (lane & 15),
                                            kh * 2 + (lane >> 4));
                ldsm_x4(ah[m][0], ah[m][1], ah[m][2], ah[m][3], addr);
                ldsm_x4(al[m][0], al[m][1], al[m][2], al[m][3], addr + PLANE64);
            }
            const int nrow = (lane & 7) + ((lane >> 4) << 3);
            const int nc4  = kh * 2 + ((lane >> 3) & 1);
            #pragma unroll
            for (int jj = 0; jj < 4; jj++) {
                uint32_t addr = sbase + 2 * PLANE64 + swz(lw + jj * 16 + nrow, nc4);
                uint32_t bh[4], bl[4];
                ldsm_x4(bh[0], bh[1], bh[2], bh[3], addr);
                ldsm_x4(bl[0], bl[1], bl[2], bl[3], addr + PLANE64);
                mma_group(acc, jj, ah, al, bh, bl);
            }
        }
    }
    __syncthreads();
    #pragma unroll
    for (int m = 0; m < 2; m++)
        #pragma unroll
        for (int j = 0; j < 8; j++) {
            int qr  = qw + m * 16 + (lane >> 2);
            int col = lw + j * 8 + (lane & 3) * 2;
            float* d = acc[m * 8 + j];
            logits[qr * LSTRIDE + col]           = d[0];
            logits[qr * LSTRIDE + col + 1]       = d[1];
            logits[(qr + 8) * LSTRIDE + col]     = d[2];
            logits[(qr + 8) * LSTRIDE + col + 1] = d[3];
        }
    __syncthreads();
    {
        const int row = t >> 1, half = t & 1;
        float* rp = logits + row * LSTRIDE + half * 64;
        float m = rp[0];
        #pragma unroll 8
        for (int j = 1; j < 64; j++) m = fmaxf(m, rp[j]);
        m = fmaxf(m, __shfl_xor_sync(0xffffffffu, m, 1));
        float s = 0.f;
        #pragma unroll 8
        for (int j = 0; j < 64; j++) {
            float ev = __expf(rp[j] - m);
            rp[j] = ev;
            s += ev;
        }
        s += __shfl_xor_sync(0xffffffffu, s, 1);
        if (half == 0) sinv[row] = 1.0f / s;
    }
    __syncthreads();
    #pragma unroll
    for (int i = 0; i < 32; i++) {
        int p = t + i * 256;
        int row = p >> 6;
        int col = (p & 63) * 2;
        float iv = sinv[row];
        st_one(g_wH, (((size_t)b * Q_ + q0 + row) * N_ + n) * L_ + col,
               logits[row * LSTRIDE + col] * iv,
               logits[row * LSTRIDE + col + 1] * iv);
    }
}

__device__ void s2_body(char* smem, uint32_t sb, int e0, int nb) {
    const int t = threadIdx.x;
    const int lane = t & 31, wid = t >> 5;
    const int qw = (wid & 3) * 32;   // e dir
    const int lw = (wid >> 2) * 64;  // l dir
    const int n = nb >> 5, b = nb & 31;

    const __nv_bfloat16* aH = g_WcatH + (size_t)e0 * ND_ + n * D_;
    const __nv_bfloat16* aL = g_WcatL + (size_t)e0 * ND_ + n * D_;
    const __nv_bfloat16* bH = g_srcH + (size_t)nb * L_ * D_;
    const __nv_bfloat16* bL = g_srcL + (size_t)nb * L_ * D_;

    auto prefetch = [&](int c) {
        const int kd = c * 32;
        const uint32_t sbase = sb + (c % 3) * BUF64;
        #pragma unroll
        for (int i = 0; i < 8; i++) {
            int idx = t + i * 256;
            int pl = idx >> 9;
            int p2 = idx & 511;
            int row = p2 >> 2, c4 = p2 & 3;
            const __nv_bfloat16* sp;
            size_t stride;
            if (pl < 2) { sp = pl ? aL : aH; stride = ND_; }
            else        { sp = (pl == 3) ? bL : bH; stride = D_; }
            cp16(sbase + pl * PLANE64 + swz(row, c4),
                 sp + (size_t)row * stride + kd + c4 * 8);
        }
        CP_COMMIT();
    };

    float acc[16][4] = {};

    prefetch(0); prefetch(1);
    for (int c = 0; c < NCH; c++) {
        if (c + 1 < NCH) CP_WAIT(1); else CP_WAIT(0);
        __syncthreads();
        if (c + 2 < NCH) prefetch(c + 2);
        const uint32_t sbase = sb + (c % 3) * BUF64;
        #pragma unroll
        for (int kh = 0; kh < 2; kh++) {
            uint32_t ah[2][4], al[2][4];
            #pragma unroll
            for (int m = 0; m < 2; m++) {
                uint32_t addr = sbase + swz(qw + m * 16 + (lane & 15),
                                            kh * 2 + (lane >> 4));
                ldsm_x4(ah[m][0], ah[m][1], ah[m][2], ah[m][3], addr);
                ldsm_x4(al[m][0], al[m][1], al[m][2], al[m][3], addr + PLANE64);
            }
            const int nrow = (lane & 7) + ((lane >> 4) << 3);
            const int nc4  = kh * 2 + ((lane >> 3) & 1);
            #pragma unroll
            for (int jj = 0; jj < 4; jj++) {
                uint32_t addr = sbase + 2 * PLANE64 + swz(lw + jj * 16 + nrow, nc4);
                uint32_t bh[4], bl[4];
                ldsm_x4(bh[0], bh[1], bh[2], bh[3], addr);
                ldsm_x4(bl[0], bl[1], bl[2], bl[3], addr + PLANE64);
                mma_group(acc, jj, ah, al, bh, bl);
            }
        }
    }
    __syncthreads();
    float* sx = (float*)smem;
    #pragma unroll
    for (int m = 0; m < 2; m++)
        #pragma unroll
        for (int j = 0; j < 8; j++) {
            int er  = qw + m * 16 + (lane >> 2);
            int col = lw + j * 8 + (lane & 3) * 2;
            float* d = acc[m * 8 + j];
            sx[er * 128 + col]           = d[0];
            sx[er * 128 + col + 1]       = d[1];
            sx[(er + 8) * 128 + col]     = d[2];
            sx[(er + 8) * 128 + col + 1] = d[3];
        }
    __syncthreads();
    #pragma unroll
    for (int i = 0; i < 32; i++) {
        int p = t + i * 256;
        int row = p >> 6;
        int col = (p & 63) * 2;
        st_one(g_s2H, (((size_t)b * D_ + e0 + row) * N_ + n) * L_ + col,
               sx[row * 128 + col], sx[row * 128 + col + 1]);
    }
}

__global__ void __launch_bounds__(256, 2) k_attn_s2() {
    extern __shared__ __align__(16) char smem[];
    const uint32_t sb = smem_u32(smem);
    const int id = blockIdx.x;
    if (id < ATTN_BLOCKS) {
        attn_body(smem, sb, (id & 7) * 128, id >> 3);
    } else {
        const int id2 = id - ATTN_BLOCKS;
        s2_body(smem, sb, (id2 & 1) * 128, id2 >> 1);
    }
}

// ---------------------------------------------------------------------------
// K4 (mma.sync): x[q,e] = sum_k w[q,k]*s2[e,k], K=1280, tile 64q x 256e.
// SINGLE-term bf16 GEMM. 256 threads (8 warps: 2 q x 4 e), 2-buffer
// single-sync pipeline, 2 CTAs/SM.
// Epilogue: stage x to smem, then bias+relu+residual+LayerNorm -> out.
// ---------------------------------------------------------------------------
constexpr int O_APL  = 64 * 64;        // 4096
constexpr int O_BPL  = 256 * 64;       // 16384
constexpr int O_BUF  = O_APL + O_BPL;  // 20480
constexpr int O_NCH  = K2_ / 32;       // 40
constexpr int XS     = 260;            // x staging row stride (floats)
constexpr int O_SMEM = 64 * XS * 4;    // 66560 (> 2*O_BUF = 40960)

__global__ void __launch_bounds__(256, 2) k_out_mma(const float* __restrict__ Wb,
                                                    const float* __restrict__ gamma,
                                                    const float* __restrict__ beta,
                                                    float* __restrict__ out) {
    extern __shared__ __align__(16) char smem[];
    const uint32_t sb = smem_u32(smem);
    const int t = threadIdx.x;
    const int lane = t & 31, wid = t >> 5;
    const int qw = (wid & 1) * 32;   // q dir (2 warps)
    const int ew = (wid >> 1) * 64;  // e dir (4 warps)
    const int b  = blockIdx.y;
    const int q0 = blockIdx.x * 64;

    const __nv_bfloat16* wHp = g_wH + ((size_t)b * Q_ + q0) * K2_;
    const __nv_bfloat16* sHp = g_s2H + (size_t)b * D_ * K2_;

    auto prefetch = [&](int c) {
        const int k0 = c * 32;
        const uint32_t sbase = sb + (c & 1) * O_BUF;
        #pragma unroll
        for (int i = 0; i < 5; i++) {
            int idx = t + i * 256;           // 1280 pieces total
            if (idx < 256) {                 // A plane: 64 rows x 4 c4
                int row = idx >> 2, c4 = idx & 3;
                cp16(sbase + swz(row, c4),
                     wHp + (size_t)row * K2_ + k0 + c4 * 8);
            } else {                         // B plane: 256 rows x 4 c4
                int idx2 = idx - 256;
                int row = idx2 >> 2, c4 = idx2 & 3;
                cp16(sbase + O_APL + swz(row, c4),
                     sHp + (size_t)row * K2_ + k0 + c4 * 8);
            }
        }
        CP_COMMIT();
    };

    float acc[16][4] = {};

    prefetch(0);
    for (int c = 0; c < O_NCH; c++) {
        CP_WAIT(0);
        __syncthreads();
        if (c + 1 < O_NCH) prefetch(c + 1);
        const uint32_t sbase = sb + (c & 1) * O_BUF;
        #pragma unroll
        for (int kh = 0; kh < 2; kh++) {
            uint32_t ah[2][4];
            #pragma unroll
            for (int m = 0; m < 2; m++) {
                uint32_t addr = sbase + swz(qw + m * 16 + (lane & 15),
                                            kh * 2 + (lane >> 4));
                ldsm_x4(ah[m][0], ah[m][1], ah[m][2], ah[m][3], addr);
            }
            const int nrow = (lane & 7) + ((lane >> 4) << 3);
            const int nc4  = kh * 2 + ((lane >> 3) & 1);
            #pragma unroll
            for (int jj = 0; jj < 4; jj++) {
                uint32_t addr = sbase + O_APL + swz(ew + jj * 16 + nrow, nc4);
                uint32_t bh[4];
                ldsm_x4(bh[0], bh[1], bh[2], bh[3], addr);
                #pragma unroll
                for (int m = 0; m < 2; m++)
                    #pragma unroll
                    for (int jb = 0; jb < 2; jb++)
                        mma_bf16(acc[m * 8 + jj * 2 + jb], ah[m], bh + jb * 2);
            }
        }
    }
    __syncthreads();
    float* sx = (float*)smem;
    #pragma unroll
    for (int m = 0; m < 2; m++)
        #pragma unroll
        for (int j = 0; j < 8; j++) {
            int qr  = qw + m * 16 + (lane >> 2);
            int col = ew + j * 8 + (lane & 3) * 2;
            float* d = acc[m * 8 + j];
            sx[qr * XS + col]           = d[0];
            sx[qr * XS + col + 1]       = d[1];
            sx[(qr + 8) * XS + col]     = d[2];
            sx[(qr + 8) * XS + col + 1] = d[3];
        }
    __syncthreads();
    float wb[8], gm[8], be[8];
    {
        float4 w0 = *(const float4*)&Wb[lane * 4];
        float4 w1 = *(const float4*)&Wb[lane * 4 + 128];
        float4 g0 = *(const float4*)&gamma[lane * 4];
        float4 g1 = *(const float4*)&gamma[lane * 4 + 128];
        float4 e0 = *(const float4*)&beta[lane * 4];
        float4 e1 = *(const float4*)&beta[lane * 4 + 128];
        wb[0]=w0.x; wb[1]=w0.y; wb[2]=w0.z; wb[3]=w0.w; wb[4]=w1.x; wb[5]=w1.y; wb[6]=w1.z; wb[7]=w1.w;
        gm[0]=g0.x; gm[1]=g0.y; gm[2]=g0.z; gm[3]=g0.w; gm[4]=g1.x; gm[5]=g1.y; gm[6]=g1.z; gm[7]=g1.w;
        be[0]=e0.x; be[1]=e0.y; be[2]=e0.z; be[3]=e0.w; be[4]=e1.x; be[5]=e1.y; be[6]=e1.z; be[7]=e1.w;
    }
    const __nv_bfloat16* tH = g_tgtH + (size_t)b * Q_ * D_;
    const __nv_bfloat16* tL = g_tgtL + (size_t)b * Q_ * D_;
    #pragma unroll
    for (int i = 0; i < 8; i++) {
        const int r = wid * 8 + i;          // local q row (8 warps x 8 = 64)
        const int q = q0 + r;
        float4 a0 = *(const float4*)&sx[r * XS + lane * 4];
        float4 a1 = *(const float4*)&sx[r * XS + lane * 4 + 128];
        float av[8] = {a0.x, a0.y, a0.z, a0.w, a1.x, a1.y, a1.z, a1.w};
        float tv[8];
        rec4(tH, tL, (size_t)q * D_ + lane * 4, tv);
        rec4(tH, tL, (size_t)q * D_ + lane * 4 + 128, tv + 4);
        float v[8], s = 0.f;
        #pragma unroll
        for (int j = 0; j < 8; j++) {
            v[j] = fmaxf(av[j] + wb[j], 0.f) + tv[j];
            s += v[j];
        }
        s = warpSum32(s);
        const float mu = s * (1.0f / 256.0f);
        float d2 = 0.f;
        #pragma unroll
        for (int j = 0; j < 8; j++) { float dd = v[j] - mu; d2 += dd * dd; }
        d2 = warpSum32(d2);
        const float rs = rsqrtf(d2 * (1.0f / 256.0f));
        float o[8];
        #pragma unroll
        for (int j = 0; j < 8; j++) o[j] = (v[j] - mu) * rs * gm[j] + be[j];
        float* orow = out + (size_t)(b * Q_ + q) * D_;
        *(float4*)&orow[lane * 4]       = make_float4(o[0], o[1], o[2], o[3]);
        *(float4*)&orow[lane * 4 + 128] = make_float4(o[4], o[5], o[6], o[7]);
    }
}

// ---------------------------------------------------------------------------
extern "C" void kernel_launch(void* const* d_in, const int* in_sizes, int n_in,
                              void* d_out, int out_size) {
    const float* input    = (const float*)d_in[0];  // [B, D, 32, 32]
    const float* contexts = (const float*)d_in[1];  // [N, B, C, L]
    const float* Wc       = (const float*)d_in[2];  // [D, C]
    const float* Wcat     = (const float*)d_in[3];  // [D, N*D]
    const float* Wb       = (const float*)d_in[4];  // [D]
    const float* gamma    = (const float*)d_in[5];  // [D]
    const float* beta     = (const float*)d_in[6];  // [D]
    float* out = (float*)d_out;                     // [B, Q, D]

    cudaFuncSetAttribute(k_source_mma, cudaFuncAttributeMaxDynamicSharedMemorySize, MMA_SMEM);
    cudaFuncSetAttribute(k_attn_s2,    cudaFuncAttributeMaxDynamicSharedMemorySize, MMA_SMEM);
    cudaFuncSetAttribute(k_out_mma,    cudaFuncAttributeMaxDynamicSharedMemorySize, O_SMEM);

    k_prep      <<<PREP_BLOCKS, 256>>>(input, contexts, Wcat, Wc);
    k_source_mma<<<dim3(2, N_ * B_), 256, MMA_SMEM>>>();
    k_attn_s2   <<<ATTN_BLOCKS + S2_BLOCKS, 256, MMA_SMEM>>>();
    k_out_mma   <<<dim3(Q_ / 64, B_), 256, O_SMEM>>>(Wb, gamma, beta, out);
}